// round 1
// baseline (speedup 1.0000x reference)
#include <cuda_runtime.h>
#include <math.h>

#define BZ   64
#define CINC 96
#define COUTC 96
#define HH   56
#define WW   56
#define MIDC 192
#define HWP  3136
#define EPSBN 1e-5f

// Scratch (device globals: allowed; no cudaMalloc anywhere)
__device__ float g_mid[(size_t)BZ * MIDC * HWP];     // expand output (pre-shuffle)
__device__ float g_merged[(size_t)BZ * MIDC * HWP];  // post dw/id/merge/SiLU
__device__ float g_sums[BZ * MIDC];
__device__ float g_se[BZ * MIDC];
__device__ float g_Wexp[MIDC * CINC];
__device__ float g_bexp[MIDC];
__device__ float g_W9[MIDC * 9];
__device__ float g_T[MIDC];
__device__ float g_Wproj[COUTC * MIDC];
__device__ float g_bproj[COUTC];

__device__ __forceinline__ float silu_f(float v) {
    return v / (1.f + __expf(-v));
}

// ---------------------------------------------------------------------------
// Fold all BN params into weights/biases.
// ---------------------------------------------------------------------------
__global__ void prep_kernel(const float* __restrict__ expand_w,
                            const float* __restrict__ expand_bn,
                            const float* __restrict__ dw_w,
                            const float* __restrict__ dw_bn,
                            const float* __restrict__ id_w,
                            const float* __restrict__ id_bn,
                            const float* __restrict__ merge_bn,
                            const float* __restrict__ proj_w,
                            const float* __restrict__ proj_bn) {
    int tid = blockIdx.x * blockDim.x + threadIdx.x;
    int nth = gridDim.x * blockDim.x;

    for (int i = tid; i < MIDC * CINC; i += nth) {
        int o = i / CINC;
        float sc = expand_bn[o] * rsqrtf(expand_bn[3 * MIDC + o] + EPSBN);
        g_Wexp[i] = expand_w[i] * sc;
    }
    for (int o = tid; o < MIDC; o += nth) {
        float sc = expand_bn[o] * rsqrtf(expand_bn[3 * MIDC + o] + EPSBN);
        g_bexp[o] = expand_bn[MIDC + o] - expand_bn[2 * MIDC + o] * sc;
    }
    for (int c = tid; c < MIDC; c += nth) {
        float dsc = dw_bn[c] * rsqrtf(dw_bn[3 * MIDC + c] + EPSBN);
        float dsh = dw_bn[MIDC + c] - dw_bn[2 * MIDC + c] * dsc;
        float isc = id_bn[c] * rsqrtf(id_bn[3 * MIDC + c] + EPSBN);
        float ish = id_bn[MIDC + c] - id_bn[2 * MIDC + c] * isc;
        float msc = merge_bn[c] * rsqrtf(merge_bn[3 * MIDC + c] + EPSBN);
        float msh = merge_bn[MIDC + c] - merge_bn[2 * MIDC + c] * msc;
        #pragma unroll
        for (int k = 0; k < 9; k++) g_W9[c * 9 + k] = msc * dsc * dw_w[c * 9 + k];
        g_W9[c * 9 + 4] += msc * isc * id_w[c];
        g_T[c] = msc * (dsh + ish) + msh;
    }
    for (int i = tid; i < COUTC * MIDC; i += nth) {
        int o = i / MIDC;
        float sc = proj_bn[o] * rsqrtf(proj_bn[3 * COUTC + o] + EPSBN);
        g_Wproj[i] = proj_w[i] * sc;
    }
    for (int o = tid; o < COUTC; o += nth) {
        float sc = proj_bn[o] * rsqrtf(proj_bn[3 * COUTC + o] + EPSBN);
        g_bproj[o] = proj_bn[COUTC + o] - proj_bn[2 * COUTC + o] * sc;
    }
}

// ---------------------------------------------------------------------------
// Expand 1x1 GEMM + folded BN + SiLU.   out[192,3136] = Wf[192,96] x x_b[96,3136]
// BM=64, BN=64, BK=48, 256 threads, 4x4 per thread
// ---------------------------------------------------------------------------
__global__ void __launch_bounds__(256) expand_gemm(const float* __restrict__ x) {
    __shared__ float As[64][49];   // [m][k], padded
    __shared__ float Bs[48][64];   // [k][n]
    int b  = blockIdx.z;
    int m0 = blockIdx.y * 64;
    int p0 = blockIdx.x * 64;
    int tid = threadIdx.x;
    int tx = tid & 15, ty = tid >> 4;
    int ty4 = ty * 4, tx4 = tx * 4;
    float acc[4][4] = {};
    const float* xb = x + (size_t)b * CINC * HWP;

    for (int k0 = 0; k0 < CINC; k0 += 48) {
        for (int i = tid; i < 64 * 48; i += 256) {
            int m = i / 48, k = i - m * 48;
            As[m][k] = g_Wexp[(m0 + m) * CINC + k0 + k];
        }
        for (int i = tid; i < 48 * 64; i += 256) {
            int k = i >> 6, n = i & 63;
            Bs[k][n] = xb[(size_t)(k0 + k) * HWP + p0 + n];
        }
        __syncthreads();
        #pragma unroll 8
        for (int k = 0; k < 48; k++) {
            float4 bv = *(const float4*)&Bs[k][tx4];
            float a0 = As[ty4 + 0][k], a1 = As[ty4 + 1][k];
            float a2 = As[ty4 + 2][k], a3 = As[ty4 + 3][k];
            acc[0][0] += a0 * bv.x; acc[0][1] += a0 * bv.y; acc[0][2] += a0 * bv.z; acc[0][3] += a0 * bv.w;
            acc[1][0] += a1 * bv.x; acc[1][1] += a1 * bv.y; acc[1][2] += a1 * bv.z; acc[1][3] += a1 * bv.w;
            acc[2][0] += a2 * bv.x; acc[2][1] += a2 * bv.y; acc[2][2] += a2 * bv.z; acc[2][3] += a2 * bv.w;
            acc[3][0] += a3 * bv.x; acc[3][1] += a3 * bv.y; acc[3][2] += a3 * bv.z; acc[3][3] += a3 * bv.w;
        }
        __syncthreads();
    }

    float* ob = g_mid + (size_t)b * MIDC * HWP;
    #pragma unroll
    for (int i = 0; i < 4; i++) {
        int o = m0 + ty4 + i;
        float bias = g_bexp[o];
        float4 r;
        r.x = silu_f(acc[i][0] + bias);
        r.y = silu_f(acc[i][1] + bias);
        r.z = silu_f(acc[i][2] + bias);
        r.w = silu_f(acc[i][3] + bias);
        *(float4*)&ob[(size_t)o * HWP + p0 + tx4] = r;
    }
}

// ---------------------------------------------------------------------------
// Fused shift + shuffle + dw3x3 + identity + BNs + SiLU + spatial-sum.
// One block per (b, c_out) plane. Shuffle/shift folded into addressing.
// ---------------------------------------------------------------------------
__global__ void __launch_bounds__(256) dwmerge_kernel() {
    __shared__ float sp[56 * 57];
    __shared__ float sred[8];
    int bc = blockIdx.x;
    int b = bc / MIDC, c = bc - b * MIDC;
    int cpre = (c & 3) * 48 + (c >> 2);
    int g = c & 3;
    int oy = (g == 0) ? -1 : (g == 2) ? 1 : 0;
    int ox = (g == 1) ? -1 : (g == 3) ? 1 : 0;
    const float* plane = g_mid + ((size_t)b * MIDC + cpre) * HWP;
    int tid = threadIdx.x;

    for (int p = tid; p < HWP; p += 256) {
        int h = p / 56;
        sp[h * 57 + (p - h * 56)] = plane[p];
    }
    float w9[9];
    #pragma unroll
    for (int k = 0; k < 9; k++) w9[k] = g_W9[c * 9 + k];
    float T = g_T[c];
    __syncthreads();

    float* outp = g_merged + ((size_t)b * MIDC + c) * HWP;
    float lsum = 0.f;
    for (int p = tid; p < HWP; p += 256) {
        int h = p / 56, w = p - h * 56;
        float acc = 0.f;
        if (h >= 2 && h < 54 && w >= 2 && w < 54) {
            const float* base = &sp[(h + oy) * 57 + (w + ox)];
            #pragma unroll
            for (int dy = -1; dy <= 1; dy++)
                #pragma unroll
                for (int dx = -1; dx <= 1; dx++)
                    acc += w9[(dy + 1) * 3 + dx + 1] * base[dy * 57 + dx];
        } else {
            #pragma unroll
            for (int dy = -1; dy <= 1; dy++) {
                int hh = h + dy;
                #pragma unroll
                for (int dx = -1; dx <= 1; dx++) {
                    int ww = w + dx;
                    bool ok = (unsigned)hh < 56u && (unsigned)ww < 56u &&
                              (unsigned)(hh + oy) < 56u && (unsigned)(ww + ox) < 56u;
                    float v = ok ? sp[(hh + oy) * 57 + ww + ox] : 0.f;
                    acc += w9[(dy + 1) * 3 + dx + 1] * v;
                }
            }
        }
        float s = silu_f(acc + T);
        outp[p] = s;
        lsum += s;
    }
    // block reduce
    #pragma unroll
    for (int o = 16; o > 0; o >>= 1) lsum += __shfl_down_sync(0xffffffffu, lsum, o);
    if ((tid & 31) == 0) sred[tid >> 5] = lsum;
    __syncthreads();
    if (tid < 8) {
        float v = sred[tid];
        #pragma unroll
        for (int o = 4; o > 0; o >>= 1) v += __shfl_down_sync(0xffu, v, o);
        if (tid == 0) g_sums[bc] = v;
    }
}

// ---------------------------------------------------------------------------
// SE gating: mean -> grouped 192->24 (12 groups) ReLU -> grouped 24->192 sigmoid
// ---------------------------------------------------------------------------
__global__ void se_kernel(const float* __restrict__ red_w,
                          const float* __restrict__ red_b,
                          const float* __restrict__ exp_w,
                          const float* __restrict__ exp_b) {
    __shared__ float smean[192];
    __shared__ float sred[24];
    int b = blockIdx.x, t = threadIdx.x;
    smean[t] = g_sums[b * 192 + t] * (1.f / 3136.f);
    __syncthreads();
    if (t < 24) {
        int gq = t >> 1;
        float a = red_b[t];
        #pragma unroll
        for (int i = 0; i < 16; i++) a += red_w[t * 16 + i] * smean[gq * 16 + i];
        sred[t] = fmaxf(a, 0.f);
    }
    __syncthreads();
    int gq = t >> 4;
    float v = exp_w[t * 2] * sred[gq * 2] + exp_w[t * 2 + 1] * sred[gq * 2 + 1] + exp_b[t];
    g_se[b * 192 + t] = 1.f / (1.f + __expf(-v));
}

// ---------------------------------------------------------------------------
// Project 1x1 GEMM (SE scale folded into B load) + BN + residual + SiLU.
// ---------------------------------------------------------------------------
__global__ void __launch_bounds__(256) proj_gemm(const float* __restrict__ x,
                                                 float* __restrict__ out) {
    __shared__ float As[64][49];
    __shared__ float Bs[48][64];
    __shared__ float s_se[192];
    int b  = blockIdx.z;
    int m0 = blockIdx.y * 64;
    int p0 = blockIdx.x * 64;
    int tid = threadIdx.x;
    int tx = tid & 15, ty = tid >> 4;
    int ty4 = ty * 4, tx4 = tx * 4;
    if (tid < 192) s_se[tid] = g_se[b * 192 + tid];
    __syncthreads();
    float acc[4][4] = {};
    const float* mb = g_merged + (size_t)b * MIDC * HWP;

    for (int k0 = 0; k0 < MIDC; k0 += 48) {
        for (int i = tid; i < 64 * 48; i += 256) {
            int m = i / 48, k = i - m * 48;
            int o = m0 + m;
            As[m][k] = (o < COUTC) ? g_Wproj[o * MIDC + k0 + k] : 0.f;
        }
        for (int i = tid; i < 48 * 64; i += 256) {
            int k = i >> 6, n = i & 63;
            Bs[k][n] = mb[(size_t)(k0 + k) * HWP + p0 + n] * s_se[k0 + k];
        }
        __syncthreads();
        #pragma unroll 8
        for (int k = 0; k < 48; k++) {
            float4 bv = *(const float4*)&Bs[k][tx4];
            float a0 = As[ty4 + 0][k], a1 = As[ty4 + 1][k];
            float a2 = As[ty4 + 2][k], a3 = As[ty4 + 3][k];
            acc[0][0] += a0 * bv.x; acc[0][1] += a0 * bv.y; acc[0][2] += a0 * bv.z; acc[0][3] += a0 * bv.w;
            acc[1][0] += a1 * bv.x; acc[1][1] += a1 * bv.y; acc[1][2] += a1 * bv.z; acc[1][3] += a1 * bv.w;
            acc[2][0] += a2 * bv.x; acc[2][1] += a2 * bv.y; acc[2][2] += a2 * bv.z; acc[2][3] += a2 * bv.w;
            acc[3][0] += a3 * bv.x; acc[3][1] += a3 * bv.y; acc[3][2] += a3 * bv.z; acc[3][3] += a3 * bv.w;
        }
        __syncthreads();
    }

    const float* xb = x + (size_t)b * COUTC * HWP;
    float* ob = out + (size_t)b * COUTC * HWP;
    #pragma unroll
    for (int i = 0; i < 4; i++) {
        int o = m0 + ty4 + i;
        if (o < COUTC) {
            float bias = g_bproj[o];
            float4 xr = *(const float4*)&xb[(size_t)o * HWP + p0 + tx4];
            float4 r;
            float v0 = acc[i][0] + bias + xr.x; r.x = silu_f(v0);
            float v1 = acc[i][1] + bias + xr.y; r.y = silu_f(v1);
            float v2 = acc[i][2] + bias + xr.z; r.z = silu_f(v2);
            float v3 = acc[i][3] + bias + xr.w; r.w = silu_f(v3);
            *(float4*)&ob[(size_t)o * HWP + p0 + tx4] = r;
        }
    }
}

// ---------------------------------------------------------------------------
extern "C" void kernel_launch(void* const* d_in, const int* in_sizes, int n_in,
                              void* d_out, int out_size) {
    const float* x         = (const float*)d_in[0];
    const float* expand_w  = (const float*)d_in[1];
    const float* expand_bn = (const float*)d_in[2];
    const float* dw_w      = (const float*)d_in[3];
    const float* dw_bn     = (const float*)d_in[4];
    const float* id_w      = (const float*)d_in[5];
    const float* id_bn     = (const float*)d_in[6];
    const float* merge_bn  = (const float*)d_in[7];
    const float* se_red_w  = (const float*)d_in[8];
    const float* se_red_b  = (const float*)d_in[9];
    const float* se_exp_w  = (const float*)d_in[10];
    const float* se_exp_b  = (const float*)d_in[11];
    const float* proj_w    = (const float*)d_in[12];
    const float* proj_bn   = (const float*)d_in[13];
    float* out = (float*)d_out;

    prep_kernel<<<80, 256>>>(expand_w, expand_bn, dw_w, dw_bn, id_w, id_bn,
                             merge_bn, proj_w, proj_bn);
    expand_gemm<<<dim3(49, 3, BZ), 256>>>(x);
    dwmerge_kernel<<<BZ * MIDC, 256>>>();
    se_kernel<<<BZ, 192>>>(se_red_w, se_red_b, se_exp_w, se_exp_b);
    proj_gemm<<<dim3(49, 2, BZ), 256>>>(x, out);
}

// round 2
// speedup vs baseline: 1.1351x; 1.1351x over previous
#include <cuda_runtime.h>
#include <math.h>
#include <stdint.h>

#define BZ    64
#define CINC  96
#define COUTC 96
#define MIDC  192
#define HWP   3136
#define EPSBN 1e-5f

#define AS_STRIDE 100   // 64 x 100 floats  (banks: 4g+tg -> conflict-free)
#define BS_STRIDE 72    // 96 x 72 floats   (banks: 8tg+g -> conflict-free)
#define GEMM_SMEM ((64 * AS_STRIDE + 96 * BS_STRIDE) * 4)

// Scratch (device globals: allowed; no cudaMalloc anywhere)
__device__ float g_mid[(size_t)BZ * MIDC * HWP];     // expand output (pre-shuffle)
__device__ float g_merged[(size_t)BZ * MIDC * HWP];  // post dw/id/merge/SiLU
__device__ float g_sums[BZ * MIDC];
__device__ float g_se[BZ * MIDC];
__device__ float g_Wexp[MIDC * CINC];
__device__ float g_bexp[MIDC];
__device__ float g_W9[MIDC * 9];
__device__ float g_T[MIDC];
__device__ float g_Wproj[COUTC * MIDC];
__device__ float g_bproj[COUTC];

__device__ __forceinline__ float silu_f(float v) {
    return v / (1.f + __expf(-v));
}

__device__ __forceinline__ uint32_t f2tf32(float v) {
    uint32_t r;
    asm("cvt.rna.tf32.f32 %0, %1;" : "=r"(r) : "f"(v));
    return r;
}

__device__ __forceinline__ void mma8(float* c, const uint32_t* a, const uint32_t* b) {
    asm volatile(
        "mma.sync.aligned.m16n8k8.row.col.f32.tf32.tf32.f32 "
        "{%0,%1,%2,%3},{%4,%5,%6,%7},{%8,%9},{%0,%1,%2,%3};"
        : "+f"(c[0]), "+f"(c[1]), "+f"(c[2]), "+f"(c[3])
        : "r"(a[0]), "r"(a[1]), "r"(a[2]), "r"(a[3]), "r"(b[0]), "r"(b[1]));
}

// ---------------------------------------------------------------------------
// Fold all BN params into weights/biases.
// ---------------------------------------------------------------------------
__global__ void prep_kernel(const float* __restrict__ expand_w,
                            const float* __restrict__ expand_bn,
                            const float* __restrict__ dw_w,
                            const float* __restrict__ dw_bn,
                            const float* __restrict__ id_w,
                            const float* __restrict__ id_bn,
                            const float* __restrict__ merge_bn,
                            const float* __restrict__ proj_w,
                            const float* __restrict__ proj_bn) {
    int tid = blockIdx.x * blockDim.x + threadIdx.x;
    int nth = gridDim.x * blockDim.x;

    for (int i = tid; i < MIDC * CINC; i += nth) {
        int o = i / CINC;
        float sc = expand_bn[o] * rsqrtf(expand_bn[3 * MIDC + o] + EPSBN);
        g_Wexp[i] = expand_w[i] * sc;
    }
    for (int o = tid; o < MIDC; o += nth) {
        float sc = expand_bn[o] * rsqrtf(expand_bn[3 * MIDC + o] + EPSBN);
        g_bexp[o] = expand_bn[MIDC + o] - expand_bn[2 * MIDC + o] * sc;
    }
    for (int c = tid; c < MIDC; c += nth) {
        float dsc = dw_bn[c] * rsqrtf(dw_bn[3 * MIDC + c] + EPSBN);
        float dsh = dw_bn[MIDC + c] - dw_bn[2 * MIDC + c] * dsc;
        float isc = id_bn[c] * rsqrtf(id_bn[3 * MIDC + c] + EPSBN);
        float ish = id_bn[MIDC + c] - id_bn[2 * MIDC + c] * isc;
        float msc = merge_bn[c] * rsqrtf(merge_bn[3 * MIDC + c] + EPSBN);
        float msh = merge_bn[MIDC + c] - merge_bn[2 * MIDC + c] * msc;
        #pragma unroll
        for (int k = 0; k < 9; k++) g_W9[c * 9 + k] = msc * dsc * dw_w[c * 9 + k];
        g_W9[c * 9 + 4] += msc * isc * id_w[c];
        g_T[c] = msc * (dsh + ish) + msh;
    }
    for (int i = tid; i < COUTC * MIDC; i += nth) {
        int o = i / MIDC;
        float sc = proj_bn[o] * rsqrtf(proj_bn[3 * COUTC + o] + EPSBN);
        g_Wproj[i] = proj_w[i] * sc;
    }
    for (int o = tid; o < COUTC; o += nth) {
        float sc = proj_bn[o] * rsqrtf(proj_bn[3 * COUTC + o] + EPSBN);
        g_bproj[o] = proj_bn[COUTC + o] - proj_bn[2 * COUTC + o] * sc;
    }
}

// ---------------------------------------------------------------------------
// Expand 1x1 GEMM via tf32 mma.sync (3-pass split) + folded BN + SiLU.
// Block: N-tile of 64 pixels; loops all 3 M-tiles (64 rows) reusing Bs.
// 256 threads = 8 warps in 2(M) x 4(N); warp tile 32x16; mma m16n8k8.
// ---------------------------------------------------------------------------
__global__ void __launch_bounds__(256) expand_gemm(const float* __restrict__ x) {
    extern __shared__ float sm[];
    float* As = sm;                       // [64][AS_STRIDE]
    float* Bs = sm + 64 * AS_STRIDE;      // [96][BS_STRIDE]
    int b = blockIdx.z;
    int p0 = blockIdx.x * 64;
    int tid = threadIdx.x;
    int lane = tid & 31, w = tid >> 5;
    int wr = w >> 2, wc = w & 3;
    int g = lane >> 2, tg = lane & 3;
    const float* xb = x + (size_t)b * CINC * HWP;
    float* ob = g_mid + (size_t)b * MIDC * HWP;

    // Load Bs once: activations [96 k][64 n]
    #pragma unroll
    for (int j = 0; j < 6; j++) {
        int v = tid + j * 256;
        int k = v >> 4, n4 = (v & 15) << 2;
        float4 t = *(const float4*)&xb[(size_t)k * HWP + p0 + n4];
        float* d = &Bs[k * BS_STRIDE + n4];
        d[0] = t.x; d[1] = t.y; d[2] = t.z; d[3] = t.w;
    }

    for (int mt = 0; mt < 3; mt++) {
        int m0 = mt * 64;
        __syncthreads();  // prior compute done (reads As/Bs); first iter: nothing to wait but cheap
        #pragma unroll
        for (int j = 0; j < 6; j++) {
            int v = tid + j * 256;
            int m = v / 24, c4 = (v % 24) * 4;
            float4 t = *(const float4*)&g_Wexp[(m0 + m) * CINC + c4];
            float* d = &As[m * AS_STRIDE + c4];
            d[0] = t.x; d[1] = t.y; d[2] = t.z; d[3] = t.w;
        }
        __syncthreads();

        float acc[2][2][4] = {};
        #pragma unroll 4
        for (int k = 0; k < 96; k += 8) {
            uint32_t Ah[2][4], Al[2][4], Bh[2][2], Bl[2][2];
            #pragma unroll
            for (int mi = 0; mi < 2; mi++) {
                int mr = wr * 32 + mi * 16;
                #pragma unroll
                for (int q = 0; q < 4; q++) {
                    int r = mr + g + ((q & 1) ? 8 : 0);
                    int c = k + tg + ((q & 2) ? 4 : 0);
                    float v = As[r * AS_STRIDE + c];
                    uint32_t h = f2tf32(v);
                    Ah[mi][q] = h;
                    Al[mi][q] = f2tf32(v - __uint_as_float(h));
                }
            }
            #pragma unroll
            for (int ni = 0; ni < 2; ni++) {
                int nb = wc * 16 + ni * 8;
                #pragma unroll
                for (int q = 0; q < 2; q++) {
                    float v = Bs[(k + tg + q * 4) * BS_STRIDE + nb + g];
                    uint32_t h = f2tf32(v);
                    Bh[ni][q] = h;
                    Bl[ni][q] = f2tf32(v - __uint_as_float(h));
                }
            }
            #pragma unroll
            for (int mi = 0; mi < 2; mi++)
                #pragma unroll
                for (int ni = 0; ni < 2; ni++) {
                    mma8(acc[mi][ni], Ah[mi], Bh[ni]);
                    mma8(acc[mi][ni], Al[mi], Bh[ni]);
                    mma8(acc[mi][ni], Ah[mi], Bl[ni]);
                }
        }

        #pragma unroll
        for (int mi = 0; mi < 2; mi++)
            #pragma unroll
            for (int ni = 0; ni < 2; ni++) {
                int o = m0 + wr * 32 + mi * 16 + g;
                int p = p0 + wc * 16 + ni * 8 + tg * 2;
                float b0 = g_bexp[o];
                float2 r0 = make_float2(silu_f(acc[mi][ni][0] + b0),
                                        silu_f(acc[mi][ni][1] + b0));
                *(float2*)&ob[(size_t)o * HWP + p] = r0;
                float b1 = g_bexp[o + 8];
                float2 r1 = make_float2(silu_f(acc[mi][ni][2] + b1),
                                        silu_f(acc[mi][ni][3] + b1));
                *(float2*)&ob[(size_t)(o + 8) * HWP + p] = r1;
            }
    }
}

// ---------------------------------------------------------------------------
// Fused shift + shuffle + dw3x3 + identity + BNs + SiLU + spatial-sum.
// ---------------------------------------------------------------------------
__global__ void __launch_bounds__(256) dwmerge_kernel() {
    __shared__ float sp[56 * 57];
    __shared__ float sred[8];
    int bc = blockIdx.x;
    int b = bc / MIDC, c = bc - b * MIDC;
    int cpre = (c & 3) * 48 + (c >> 2);
    int gg = c & 3;
    int oy = (gg == 0) ? -1 : (gg == 2) ? 1 : 0;
    int ox = (gg == 1) ? -1 : (gg == 3) ? 1 : 0;
    const float* plane = g_mid + ((size_t)b * MIDC + cpre) * HWP;
    int tid = threadIdx.x;

    for (int p = tid; p < HWP; p += 256) {
        int h = p / 56;
        sp[h * 57 + (p - h * 56)] = plane[p];
    }
    float w9[9];
    #pragma unroll
    for (int k = 0; k < 9; k++) w9[k] = g_W9[c * 9 + k];
    float T = g_T[c];
    __syncthreads();

    float* outp = g_merged + ((size_t)b * MIDC + c) * HWP;
    float lsum = 0.f;
    for (int p = tid; p < HWP; p += 256) {
        int h = p / 56, w = p - h * 56;
        float acc = 0.f;
        if (h >= 2 && h < 54 && w >= 2 && w < 54) {
            const float* base = &sp[(h + oy) * 57 + (w + ox)];
            #pragma unroll
            for (int dy = -1; dy <= 1; dy++)
                #pragma unroll
                for (int dx = -1; dx <= 1; dx++)
                    acc += w9[(dy + 1) * 3 + dx + 1] * base[dy * 57 + dx];
        } else {
            #pragma unroll
            for (int dy = -1; dy <= 1; dy++) {
                int hh = h + dy;
                #pragma unroll
                for (int dx = -1; dx <= 1; dx++) {
                    int ww = w + dx;
                    bool ok = (unsigned)hh < 56u && (unsigned)ww < 56u &&
                              (unsigned)(hh + oy) < 56u && (unsigned)(ww + ox) < 56u;
                    float v = ok ? sp[(hh + oy) * 57 + ww + ox] : 0.f;
                    acc += w9[(dy + 1) * 3 + dx + 1] * v;
                }
            }
        }
        float s = silu_f(acc + T);
        outp[p] = s;
        lsum += s;
    }
    #pragma unroll
    for (int o = 16; o > 0; o >>= 1) lsum += __shfl_down_sync(0xffffffffu, lsum, o);
    if ((tid & 31) == 0) sred[tid >> 5] = lsum;
    __syncthreads();
    if (tid < 8) {
        float v = sred[tid];
        #pragma unroll
        for (int o = 4; o > 0; o >>= 1) v += __shfl_down_sync(0xffu, v, o);
        if (tid == 0) g_sums[bc] = v;
    }
}

// ---------------------------------------------------------------------------
// SE gating
// ---------------------------------------------------------------------------
__global__ void se_kernel(const float* __restrict__ red_w,
                          const float* __restrict__ red_b,
                          const float* __restrict__ exp_w,
                          const float* __restrict__ exp_b) {
    __shared__ float smean[192];
    __shared__ float sred[24];
    int b = blockIdx.x, t = threadIdx.x;
    smean[t] = g_sums[b * 192 + t] * (1.f / 3136.f);
    __syncthreads();
    if (t < 24) {
        int gq = t >> 1;
        float a = red_b[t];
        #pragma unroll
        for (int i = 0; i < 16; i++) a += red_w[t * 16 + i] * smean[gq * 16 + i];
        sred[t] = fmaxf(a, 0.f);
    }
    __syncthreads();
    int gq = t >> 4;
    float v = exp_w[t * 2] * sred[gq * 2] + exp_w[t * 2 + 1] * sred[gq * 2 + 1] + exp_b[t];
    g_se[b * 192 + t] = 1.f / (1.f + __expf(-v));
}

// ---------------------------------------------------------------------------
// Project 1x1 GEMM via tf32 mma.sync. SE scale folded into Bs load.
// K=192 done in two k-tiles; both M-tiles accumulate across the k loop so
// Bs is loaded exactly once per k-tile.
// ---------------------------------------------------------------------------
__global__ void __launch_bounds__(256) proj_gemm(const float* __restrict__ x,
                                                 float* __restrict__ out) {
    extern __shared__ float sm[];
    float* As = sm;
    float* Bs = sm + 64 * AS_STRIDE;
    __shared__ float s_se[192];
    int b = blockIdx.z;
    int p0 = blockIdx.x * 64;
    int tid = threadIdx.x;
    int lane = tid & 31, w = tid >> 5;
    int wr = w >> 2, wc = w & 3;
    int g = lane >> 2, tg = lane & 3;
    const float* mb = g_merged + (size_t)b * MIDC * HWP;

    if (tid < 192) s_se[tid] = g_se[b * 192 + tid];

    float acc[2][2][2][4] = {};  // [mt][mi][ni][4]

    for (int k0 = 0; k0 < MIDC; k0 += 96) {
        __syncthreads();  // covers s_se init on first iter; prior compute otherwise
        #pragma unroll
        for (int j = 0; j < 6; j++) {
            int v = tid + j * 256;
            int k = v >> 4, n4 = (v & 15) << 2;
            float s = s_se[k0 + k];
            float4 t = *(const float4*)&mb[(size_t)(k0 + k) * HWP + p0 + n4];
            float* d = &Bs[k * BS_STRIDE + n4];
            d[0] = t.x * s; d[1] = t.y * s; d[2] = t.z * s; d[3] = t.w * s;
        }
        for (int mt = 0; mt < 2; mt++) {
            if (mt) __syncthreads();
            #pragma unroll
            for (int j = 0; j < 6; j++) {
                int v = tid + j * 256;
                int m = v / 24, c4 = (v % 24) * 4;
                int row = mt * 64 + m;
                float4 t = make_float4(0.f, 0.f, 0.f, 0.f);
                if (row < COUTC)
                    t = *(const float4*)&g_Wproj[row * MIDC + k0 + c4];
                float* d = &As[m * AS_STRIDE + c4];
                d[0] = t.x; d[1] = t.y; d[2] = t.z; d[3] = t.w;
            }
            __syncthreads();

            #pragma unroll 4
            for (int k = 0; k < 96; k += 8) {
                uint32_t Ah[2][4], Al[2][4], Bh[2][2], Bl[2][2];
                #pragma unroll
                for (int mi = 0; mi < 2; mi++) {
                    int mr = wr * 32 + mi * 16;
                    #pragma unroll
                    for (int q = 0; q < 4; q++) {
                        int r = mr + g + ((q & 1) ? 8 : 0);
                        int c = k + tg + ((q & 2) ? 4 : 0);
                        float v = As[r * AS_STRIDE + c];
                        uint32_t h = f2tf32(v);
                        Ah[mi][q] = h;
                        Al[mi][q] = f2tf32(v - __uint_as_float(h));
                    }
                }
                #pragma unroll
                for (int ni = 0; ni < 2; ni++) {
                    int nb = wc * 16 + ni * 8;
                    #pragma unroll
                    for (int q = 0; q < 2; q++) {
                        float v = Bs[(k + tg + q * 4) * BS_STRIDE + nb + g];
                        uint32_t h = f2tf32(v);
                        Bh[ni][q] = h;
                        Bl[ni][q] = f2tf32(v - __uint_as_float(h));
                    }
                }
                #pragma unroll
                for (int mi = 0; mi < 2; mi++)
                    #pragma unroll
                    for (int ni = 0; ni < 2; ni++) {
                        mma8(acc[mt][mi][ni], Ah[mi], Bh[ni]);
                        mma8(acc[mt][mi][ni], Al[mi], Bh[ni]);
                        mma8(acc[mt][mi][ni], Ah[mi], Bl[ni]);
                    }
            }
        }
    }

    const float* xb = x + (size_t)b * COUTC * HWP;
    float* ob = out + (size_t)b * COUTC * HWP;
    #pragma unroll
    for (int mt = 0; mt < 2; mt++)
        #pragma unroll
        for (int mi = 0; mi < 2; mi++)
            #pragma unroll
            for (int ni = 0; ni < 2; ni++) {
                int o = mt * 64 + wr * 32 + mi * 16 + g;
                int p = p0 + wc * 16 + ni * 8 + tg * 2;
                if (o < COUTC) {
                    float bias = g_bproj[o];
                    float2 xr = *(const float2*)&xb[(size_t)o * HWP + p];
                    float2 r;
                    r.x = silu_f(acc[mt][mi][ni][0] + bias + xr.x);
                    r.y = silu_f(acc[mt][mi][ni][1] + bias + xr.y);
                    *(float2*)&ob[(size_t)o * HWP + p] = r;
                }
                int o2 = o + 8;
                if (o2 < COUTC) {
                    float bias = g_bproj[o2];
                    float2 xr = *(const float2*)&xb[(size_t)o2 * HWP + p];
                    float2 r;
                    r.x = silu_f(acc[mt][mi][ni][2] + bias + xr.x);
                    r.y = silu_f(acc[mt][mi][ni][3] + bias + xr.y);
                    *(float2*)&ob[(size_t)o2 * HWP + p] = r;
                }
            }
}

// ---------------------------------------------------------------------------
extern "C" void kernel_launch(void* const* d_in, const int* in_sizes, int n_in,
                              void* d_out, int out_size) {
    const float* x         = (const float*)d_in[0];
    const float* expand_w  = (const float*)d_in[1];
    const float* expand_bn = (const float*)d_in[2];
    const float* dw_w      = (const float*)d_in[3];
    const float* dw_bn     = (const float*)d_in[4];
    const float* id_w      = (const float*)d_in[5];
    const float* id_bn     = (const float*)d_in[6];
    const float* merge_bn  = (const float*)d_in[7];
    const float* se_red_w  = (const float*)d_in[8];
    const float* se_red_b  = (const float*)d_in[9];
    const float* se_exp_w  = (const float*)d_in[10];
    const float* se_exp_b  = (const float*)d_in[11];
    const float* proj_w    = (const float*)d_in[12];
    const float* proj_bn   = (const float*)d_in[13];
    float* out = (float*)d_out;

    static bool attr_done = false;
    if (!attr_done) {
        cudaFuncSetAttribute(expand_gemm, cudaFuncAttributeMaxDynamicSharedMemorySize, GEMM_SMEM);
        cudaFuncSetAttribute(proj_gemm,   cudaFuncAttributeMaxDynamicSharedMemorySize, GEMM_SMEM);
        attr_done = true;
    }

    prep_kernel<<<80, 256>>>(expand_w, expand_bn, dw_w, dw_bn, id_w, id_bn,
                             merge_bn, proj_w, proj_bn);
    expand_gemm<<<dim3(49, 1, BZ), 256, GEMM_SMEM>>>(x);
    dwmerge_kernel<<<BZ * MIDC, 256>>>();
    se_kernel<<<BZ, 192>>>(se_red_w, se_red_b, se_exp_w, se_exp_b);
    proj_gemm<<<dim3(49, 1, BZ), 256, GEMM_SMEM>>>(x, out);
}

// round 3
// speedup vs baseline: 1.2473x; 1.0988x over previous
#include <cuda_runtime.h>
#include <math.h>
#include <stdint.h>

#define BZ    64
#define CINC  96
#define COUTC 96
#define MIDC  192
#define HWP   3136
#define EPSBN 1e-5f

#define AK        52   // As row stride (48-wide k-chunk + pad): banks g*20+tg all distinct
#define BS_STRIDE 72   // Bs row stride: banks tg*8+g all distinct
#define SS_STRIDE 68   // epilogue staging stride
#define SM_FLOATS (64 * AK * 2 + 96 * BS_STRIDE)
#define GEMM_SMEM (SM_FLOATS * 4)

// Scratch (device globals: allowed; no cudaMalloc anywhere)
__device__ float    g_mid[(size_t)BZ * MIDC * HWP];
__device__ float    g_merged[(size_t)BZ * MIDC * HWP];
__device__ float    g_sums[BZ * MIDC];
__device__ float    g_se[BZ * MIDC];
__device__ uint32_t g_WexpH[MIDC * CINC];
__device__ uint32_t g_WexpL[MIDC * CINC];
__device__ float    g_bexp[MIDC];
__device__ float    g_W9[MIDC * 9];
__device__ float    g_T[MIDC];
__device__ uint32_t g_WprojH[COUTC * MIDC];
__device__ uint32_t g_WprojL[COUTC * MIDC];
__device__ float    g_bproj[COUTC];

__device__ __forceinline__ float silu_f(float v) { return v / (1.f + __expf(-v)); }

__device__ __forceinline__ uint32_t f2tf32(float v) {
    uint32_t r;
    asm("cvt.rna.tf32.f32 %0, %1;" : "=r"(r) : "f"(v));
    return r;
}

__device__ __forceinline__ void mma8(float* c, const uint32_t* a, const uint32_t* b) {
    asm volatile(
        "mma.sync.aligned.m16n8k8.row.col.f32.tf32.tf32.f32 "
        "{%0,%1,%2,%3},{%4,%5,%6,%7},{%8,%9},{%0,%1,%2,%3};"
        : "+f"(c[0]), "+f"(c[1]), "+f"(c[2]), "+f"(c[3])
        : "r"(a[0]), "r"(a[1]), "r"(a[2]), "r"(a[3]), "r"(b[0]), "r"(b[1]));
}

// ---------------------------------------------------------------------------
// Fold BN into weights/biases; pre-split weights into tf32 hi/lo.
// ---------------------------------------------------------------------------
__global__ void prep_kernel(const float* __restrict__ expand_w,
                            const float* __restrict__ expand_bn,
                            const float* __restrict__ dw_w,
                            const float* __restrict__ dw_bn,
                            const float* __restrict__ id_w,
                            const float* __restrict__ id_bn,
                            const float* __restrict__ merge_bn,
                            const float* __restrict__ proj_w,
                            const float* __restrict__ proj_bn) {
    int tid = blockIdx.x * blockDim.x + threadIdx.x;
    int nth = gridDim.x * blockDim.x;

    for (int i = tid; i < MIDC * CINC; i += nth) {
        int o = i / CINC;
        float sc = expand_bn[o] * rsqrtf(expand_bn[3 * MIDC + o] + EPSBN);
        float w = expand_w[i] * sc;
        uint32_t h = f2tf32(w);
        g_WexpH[i] = h;
        g_WexpL[i] = f2tf32(w - __uint_as_float(h));
    }
    for (int o = tid; o < MIDC; o += nth) {
        float sc = expand_bn[o] * rsqrtf(expand_bn[3 * MIDC + o] + EPSBN);
        g_bexp[o] = expand_bn[MIDC + o] - expand_bn[2 * MIDC + o] * sc;
    }
    for (int c = tid; c < MIDC; c += nth) {
        float dsc = dw_bn[c] * rsqrtf(dw_bn[3 * MIDC + c] + EPSBN);
        float dsh = dw_bn[MIDC + c] - dw_bn[2 * MIDC + c] * dsc;
        float isc = id_bn[c] * rsqrtf(id_bn[3 * MIDC + c] + EPSBN);
        float ish = id_bn[MIDC + c] - id_bn[2 * MIDC + c] * isc;
        float msc = merge_bn[c] * rsqrtf(merge_bn[3 * MIDC + c] + EPSBN);
        float msh = merge_bn[MIDC + c] - merge_bn[2 * MIDC + c] * msc;
        #pragma unroll
        for (int k = 0; k < 9; k++) g_W9[c * 9 + k] = msc * dsc * dw_w[c * 9 + k];
        g_W9[c * 9 + 4] += msc * isc * id_w[c];
        g_T[c] = msc * (dsh + ish) + msh;
    }
    for (int i = tid; i < COUTC * MIDC; i += nth) {
        int o = i / MIDC;
        float sc = proj_bn[o] * rsqrtf(proj_bn[3 * COUTC + o] + EPSBN);
        float w = proj_w[i] * sc;
        uint32_t h = f2tf32(w);
        g_WprojH[i] = h;
        g_WprojL[i] = f2tf32(w - __uint_as_float(h));
    }
    for (int o = tid; o < COUTC; o += nth) {
        float sc = proj_bn[o] * rsqrtf(proj_bn[3 * COUTC + o] + EPSBN);
        g_bproj[o] = proj_bn[COUTC + o] - proj_bn[2 * COUTC + o] * sc;
    }
}

// ---------------------------------------------------------------------------
// Expand 1x1 GEMM (tf32 3-pass, pre-split A) + BN + SiLU, staged epilogue.
// Block: 64-pixel N-tile; loops 3 M-tiles of 64 reusing Bs. 8 warps 2(M)x4(N).
// ---------------------------------------------------------------------------
__global__ void __launch_bounds__(256) expand_gemm(const float* __restrict__ x) {
    extern __shared__ float sm[];
    uint32_t* AsH = (uint32_t*)sm;            // [64][AK]
    uint32_t* AsL = AsH + 64 * AK;            // [64][AK]
    float*    Bs  = sm + (size_t)64 * AK * 2; // [96][BS_STRIDE]
    float*    ss  = sm;                       // staging (reuses As region)

    int b = blockIdx.z;
    int p0 = blockIdx.x * 64;
    int tid = threadIdx.x;
    int lane = tid & 31, w = tid >> 5;
    int wr = w >> 2, wc = w & 3;
    int g = lane >> 2, tg = lane & 3;
    const float* xb = x + (size_t)b * CINC * HWP;
    float* ob = g_mid + (size_t)b * MIDC * HWP;

    // Load Bs once: [96 k][64 n]
    #pragma unroll
    for (int j = 0; j < 6; j++) {
        int v = tid + j * 256;
        int k = v >> 4, n4 = (v & 15) << 2;
        float4 t = *(const float4*)&xb[(size_t)k * HWP + p0 + n4];
        float* d = &Bs[k * BS_STRIDE + n4];
        d[0] = t.x; d[1] = t.y; d[2] = t.z; d[3] = t.w;
    }

    for (int mt = 0; mt < 3; mt++) {
        int m0 = mt * 64;
        float acc[2][2][4] = {};
        for (int kc = 0; kc < 2; kc++) {
            int k0c = kc * 48;
            __syncthreads();   // As region free (prev compute / staging reads done); 1st: Bs visible
            #pragma unroll
            for (int j = 0; j < 3; j++) {
                int v = tid + j * 256;
                int m = v / 12, c4 = (v % 12) * 4;
                const uint32_t* srcH = &g_WexpH[(m0 + m) * CINC + k0c + c4];
                const uint32_t* srcL = &g_WexpL[(m0 + m) * CINC + k0c + c4];
                uint4 th = *(const uint4*)srcH;
                uint4 tl = *(const uint4*)srcL;
                uint32_t* dH = &AsH[m * AK + c4];
                uint32_t* dL = &AsL[m * AK + c4];
                dH[0] = th.x; dH[1] = th.y; dH[2] = th.z; dH[3] = th.w;
                dL[0] = tl.x; dL[1] = tl.y; dL[2] = tl.z; dL[3] = tl.w;
            }
            __syncthreads();

            #pragma unroll 2
            for (int k = 0; k < 48; k += 8) {
                uint32_t Ah[2][4], Al[2][4], Bh[2][2], Bl[2][2];
                #pragma unroll
                for (int mi = 0; mi < 2; mi++) {
                    int mr = wr * 32 + mi * 16;
                    #pragma unroll
                    for (int q = 0; q < 4; q++) {
                        int r = mr + g + ((q & 1) ? 8 : 0);
                        int c = k + tg + ((q & 2) ? 4 : 0);
                        Ah[mi][q] = AsH[r * AK + c];
                        Al[mi][q] = AsL[r * AK + c];
                    }
                }
                #pragma unroll
                for (int ni = 0; ni < 2; ni++) {
                    int nb = wc * 16 + ni * 8;
                    #pragma unroll
                    for (int q = 0; q < 2; q++) {
                        float v = Bs[(k0c + k + tg + q * 4) * BS_STRIDE + nb + g];
                        uint32_t h = f2tf32(v);
                        Bh[ni][q] = h;
                        Bl[ni][q] = f2tf32(v - __uint_as_float(h));
                    }
                }
                #pragma unroll
                for (int mi = 0; mi < 2; mi++)
                    #pragma unroll
                    for (int ni = 0; ni < 2; ni++) {
                        mma8(acc[mi][ni], Ah[mi], Bh[ni]);
                        mma8(acc[mi][ni], Al[mi], Bh[ni]);
                        mma8(acc[mi][ni], Ah[mi], Bl[ni]);
                    }
            }
        }
        // Staged epilogue: silu(acc+bias) -> ss -> coalesced float4 stores
        __syncthreads();
        #pragma unroll
        for (int mi = 0; mi < 2; mi++)
            #pragma unroll
            for (int ni = 0; ni < 2; ni++) {
                int ro = wr * 32 + mi * 16 + g;
                int co = wc * 16 + ni * 8 + tg * 2;
                float b0 = g_bexp[m0 + ro];
                ss[ro * SS_STRIDE + co]     = silu_f(acc[mi][ni][0] + b0);
                ss[ro * SS_STRIDE + co + 1] = silu_f(acc[mi][ni][1] + b0);
                float b1 = g_bexp[m0 + ro + 8];
                ss[(ro + 8) * SS_STRIDE + co]     = silu_f(acc[mi][ni][2] + b1);
                ss[(ro + 8) * SS_STRIDE + co + 1] = silu_f(acc[mi][ni][3] + b1);
            }
        __syncthreads();
        #pragma unroll
        for (int j = 0; j < 4; j++) {
            int q = tid + j * 256;
            int row = q >> 4, col4 = (q & 15) << 2;
            float4 t = *(const float4*)&ss[row * SS_STRIDE + col4];
            *(float4*)&ob[(size_t)(m0 + row) * HWP + p0 + col4] = t;
        }
    }
}

// ---------------------------------------------------------------------------
// Fused shift + shuffle + dw3x3 + identity + BNs + SiLU + spatial-sum.
// Shifted plane materialized with zero halo in smem -> branchless 9-tap.
// ---------------------------------------------------------------------------
#define SPS 60
__global__ void __launch_bounds__(256) dwmerge_kernel() {
    __shared__ float sps[58 * SPS];
    __shared__ float sred[8];
    int bc = blockIdx.x;
    int b = bc / MIDC, c = bc - b * MIDC;
    int cpre = (c & 3) * 48 + (c >> 2);
    int gg = c & 3;
    int oy = (gg == 0) ? -1 : (gg == 2) ? 1 : 0;
    int ox = (gg == 1) ? -1 : (gg == 3) ? 1 : 0;
    const float* plane = g_mid + ((size_t)b * MIDC + cpre) * HWP;
    int tid = threadIdx.x;

    // Load shifted plane + 1px halo, all bounds (shift + conv pad) folded in.
    for (int idx = tid; idx < 58 * 58; idx += 256) {
        int r = idx / 58, cx = idx - r * 58;
        int hp = r - 1, wp = cx - 1;       // conv-space coords
        int hs = hp + oy, ws = wp + ox;    // source coords after shift
        bool ok = (unsigned)hp < 56u && (unsigned)wp < 56u &&
                  (unsigned)hs < 56u && (unsigned)ws < 56u;
        sps[r * SPS + cx] = ok ? plane[hs * 56 + ws] : 0.f;
    }
    float w9[9];
    #pragma unroll
    for (int k = 0; k < 9; k++) w9[k] = g_W9[c * 9 + k];
    float T = g_T[c];
    __syncthreads();

    float* outp = g_merged + ((size_t)b * MIDC + c) * HWP;
    int wid = tid >> 5, lane = tid & 31;
    float lsum = 0.f;
    for (int r = wid; r < 56; r += 8) {
        const float* base = &sps[(r + 1) * SPS + 1];
        {
            int cc = lane;
            float acc = 0.f;
            #pragma unroll
            for (int dy = -1; dy <= 1; dy++)
                #pragma unroll
                for (int dx = -1; dx <= 1; dx++)
                    acc += w9[(dy + 1) * 3 + dx + 1] * base[dy * SPS + cc + dx];
            float s = silu_f(acc + T);
            outp[r * 56 + cc] = s;
            lsum += s;
        }
        if (lane < 24) {
            int cc = lane + 32;
            float acc = 0.f;
            #pragma unroll
            for (int dy = -1; dy <= 1; dy++)
                #pragma unroll
                for (int dx = -1; dx <= 1; dx++)
                    acc += w9[(dy + 1) * 3 + dx + 1] * base[dy * SPS + cc + dx];
            float s = silu_f(acc + T);
            outp[r * 56 + cc] = s;
            lsum += s;
        }
    }
    #pragma unroll
    for (int o = 16; o > 0; o >>= 1) lsum += __shfl_down_sync(0xffffffffu, lsum, o);
    if (lane == 0) sred[wid] = lsum;
    __syncthreads();
    if (tid < 8) {
        float v = sred[tid];
        #pragma unroll
        for (int o = 4; o > 0; o >>= 1) v += __shfl_down_sync(0xffu, v, o);
        if (tid == 0) g_sums[bc] = v;
    }
}

// ---------------------------------------------------------------------------
// SE gating
// ---------------------------------------------------------------------------
__global__ void se_kernel(const float* __restrict__ red_w,
                          const float* __restrict__ red_b,
                          const float* __restrict__ exp_w,
                          const float* __restrict__ exp_b) {
    __shared__ float smean[192];
    __shared__ float sred[24];
    int b = blockIdx.x, t = threadIdx.x;
    smean[t] = g_sums[b * 192 + t] * (1.f / 3136.f);
    __syncthreads();
    if (t < 24) {
        int gq = t >> 1;
        float a = red_b[t];
        #pragma unroll
        for (int i = 0; i < 16; i++) a += red_w[t * 16 + i] * smean[gq * 16 + i];
        sred[t] = fmaxf(a, 0.f);
    }
    __syncthreads();
    int gq = t >> 4;
    float v = exp_w[t * 2] * sred[gq * 2] + exp_w[t * 2 + 1] * sred[gq * 2 + 1] + exp_b[t];
    g_se[b * 192 + t] = 1.f / (1.f + __expf(-v));
}

// ---------------------------------------------------------------------------
// Project 1x1 GEMM (tf32 3-pass, pre-split A, SE folded into Bs) + BN +
// residual + SiLU, staged coalesced epilogue.
// ---------------------------------------------------------------------------
__global__ void __launch_bounds__(256) proj_gemm(const float* __restrict__ x,
                                                 float* __restrict__ out) {
    extern __shared__ float sm[];
    uint32_t* AsH = (uint32_t*)sm;
    uint32_t* AsL = AsH + 64 * AK;
    float*    Bs  = sm + (size_t)64 * AK * 2;
    float*    ss  = sm;
    __shared__ float s_se[192];

    int b = blockIdx.z;
    int p0 = blockIdx.x * 64;
    int tid = threadIdx.x;
    int lane = tid & 31, w = tid >> 5;
    int wr = w >> 2, wc = w & 3;
    int g = lane >> 2, tg = lane & 3;
    const float* mb = g_merged + (size_t)b * MIDC * HWP;

    if (tid < 192) s_se[tid] = g_se[b * 192 + tid];

    float acc[2][2][2][4] = {};  // [mt][mi][ni][4]

    for (int half = 0; half < 2; half++) {
        int k0 = half * 96;
        __syncthreads();   // Bs free + s_se visible
        #pragma unroll
        for (int j = 0; j < 6; j++) {
            int v = tid + j * 256;
            int k = v >> 4, n4 = (v & 15) << 2;
            float s = s_se[k0 + k];
            float4 t = *(const float4*)&mb[(size_t)(k0 + k) * HWP + p0 + n4];
            float* d = &Bs[k * BS_STRIDE + n4];
            d[0] = t.x * s; d[1] = t.y * s; d[2] = t.z * s; d[3] = t.w * s;
        }
        for (int mt = 0; mt < 2; mt++) {
            for (int kc = 0; kc < 2; kc++) {
                int k0c = kc * 48;
                __syncthreads();
                #pragma unroll
                for (int j = 0; j < 3; j++) {
                    int v = tid + j * 256;
                    int m = v / 12, c4 = (v % 12) * 4;
                    int row = mt * 64 + m;
                    uint4 th = make_uint4(0u, 0u, 0u, 0u);
                    uint4 tl = make_uint4(0u, 0u, 0u, 0u);
                    if (row < COUTC) {
                        th = *(const uint4*)&g_WprojH[row * MIDC + k0 + k0c + c4];
                        tl = *(const uint4*)&g_WprojL[row * MIDC + k0 + k0c + c4];
                    }
                    uint32_t* dH = &AsH[m * AK + c4];
                    uint32_t* dL = &AsL[m * AK + c4];
                    dH[0] = th.x; dH[1] = th.y; dH[2] = th.z; dH[3] = th.w;
                    dL[0] = tl.x; dL[1] = tl.y; dL[2] = tl.z; dL[3] = tl.w;
                }
                __syncthreads();

                #pragma unroll 2
                for (int k = 0; k < 48; k += 8) {
                    uint32_t Ah[2][4], Al[2][4], Bh[2][2], Bl[2][2];
                    #pragma unroll
                    for (int mi = 0; mi < 2; mi++) {
                        int mr = wr * 32 + mi * 16;
                        #pragma unroll
                        for (int q = 0; q < 4; q++) {
                            int r = mr + g + ((q & 1) ? 8 : 0);
                            int c = k + tg + ((q & 2) ? 4 : 0);
                            Ah[mi][q] = AsH[r * AK + c];
                            Al[mi][q] = AsL[r * AK + c];
                        }
                    }
                    #pragma unroll
                    for (int ni = 0; ni < 2; ni++) {
                        int nb = wc * 16 + ni * 8;
                        #pragma unroll
                        for (int q = 0; q < 2; q++) {
                            float v = Bs[(k0c + k + tg + q * 4) * BS_STRIDE + nb + g];
                            uint32_t h = f2tf32(v);
                            Bh[ni][q] = h;
                            Bl[ni][q] = f2tf32(v - __uint_as_float(h));
                        }
                    }
                    #pragma unroll
                    for (int mi = 0; mi < 2; mi++)
                        #pragma unroll
                        for (int ni = 0; ni < 2; ni++) {
                            mma8(acc[mt][mi][ni], Ah[mi], Bh[ni]);
                            mma8(acc[mt][mi][ni], Al[mi], Bh[ni]);
                            mma8(acc[mt][mi][ni], Ah[mi], Bl[ni]);
                        }
                }
            }
        }
    }

    const float* xb = x + (size_t)b * COUTC * HWP;
    float* ob = out + (size_t)b * COUTC * HWP;
    for (int mt = 0; mt < 2; mt++) {
        int m0 = mt * 64;
        __syncthreads();
        #pragma unroll
        for (int mi = 0; mi < 2; mi++)
            #pragma unroll
            for (int ni = 0; ni < 2; ni++) {
                int ro = wr * 32 + mi * 16 + g;
                int co = wc * 16 + ni * 8 + tg * 2;
                float b0 = (m0 + ro < COUTC) ? g_bproj[m0 + ro] : 0.f;
                ss[ro * SS_STRIDE + co]     = acc[mt][mi][ni][0] + b0;
                ss[ro * SS_STRIDE + co + 1] = acc[mt][mi][ni][1] + b0;
                float b1 = (m0 + ro + 8 < COUTC) ? g_bproj[m0 + ro + 8] : 0.f;
                ss[(ro + 8) * SS_STRIDE + co]     = acc[mt][mi][ni][2] + b1;
                ss[(ro + 8) * SS_STRIDE + co + 1] = acc[mt][mi][ni][3] + b1;
            }
        __syncthreads();
        #pragma unroll
        for (int j = 0; j < 4; j++) {
            int q = tid + j * 256;
            int row = q >> 4, col4 = (q & 15) << 2;
            int o = m0 + row;
            if (o < COUTC) {
                float4 t = *(const float4*)&ss[row * SS_STRIDE + col4];
                float4 xr = *(const float4*)&xb[(size_t)o * HWP + p0 + col4];
                float4 r;
                r.x = silu_f(t.x + xr.x);
                r.y = silu_f(t.y + xr.y);
                r.z = silu_f(t.z + xr.z);
                r.w = silu_f(t.w + xr.w);
                *(float4*)&ob[(size_t)o * HWP + p0 + col4] = r;
            }
        }
    }
}

// ---------------------------------------------------------------------------
extern "C" void kernel_launch(void* const* d_in, const int* in_sizes, int n_in,
                              void* d_out, int out_size) {
    const float* x         = (const float*)d_in[0];
    const float* expand_w  = (const float*)d_in[1];
    const float* expand_bn = (const float*)d_in[2];
    const float* dw_w      = (const float*)d_in[3];
    const float* dw_bn     = (const float*)d_in[4];
    const float* id_w      = (const float*)d_in[5];
    const float* id_bn     = (const float*)d_in[6];
    const float* merge_bn  = (const float*)d_in[7];
    const float* se_red_w  = (const float*)d_in[8];
    const float* se_red_b  = (const float*)d_in[9];
    const float* se_exp_w  = (const float*)d_in[10];
    const float* se_exp_b  = (const float*)d_in[11];
    const float* proj_w    = (const float*)d_in[12];
    const float* proj_bn   = (const float*)d_in[13];
    float* out = (float*)d_out;

    cudaFuncSetAttribute(expand_gemm, cudaFuncAttributeMaxDynamicSharedMemorySize, GEMM_SMEM);
    cudaFuncSetAttribute(proj_gemm,   cudaFuncAttributeMaxDynamicSharedMemorySize, GEMM_SMEM);

    prep_kernel<<<80, 256>>>(expand_w, expand_bn, dw_w, dw_bn, id_w, id_bn,
                             merge_bn, proj_w, proj_bn);
    expand_gemm<<<dim3(49, 1, BZ), 256, GEMM_SMEM>>>(x);
    dwmerge_kernel<<<BZ * MIDC, 256>>>();
    se_kernel<<<BZ, 192>>>(se_red_w, se_red_b, se_exp_w, se_exp_b);
    proj_gemm<<<dim3(49, 1, BZ), 256, GEMM_SMEM>>>(x, out);
}

// round 4
// speedup vs baseline: 1.5800x; 1.2668x over previous
#include <cuda_runtime.h>
#include <math.h>
#include <stdint.h>

#define BZ    64
#define CINC  96
#define COUTC 96
#define MIDC  192
#define HWP   3136
#define EPSBN 1e-5f

#define BSS 136   // Bs row stride (128 + 8): bank = tg*8+g -> conflict-free
#define EXP_AS_U32 6144    // 64x48x2(HL) fragment-ordered chunk
#define PROJ_AS_U32 9216   // 96x48x2(HL) fragment-ordered chunk
#define EXP_SMEM  (EXP_AS_U32 * 4 + 96 * BSS * 4)
#define PROJ_SMEM (PROJ_AS_U32 * 4 + 96 * BSS * 4)

// Scratch (device globals: allowed; no cudaMalloc anywhere)
__device__ float    g_mid[(size_t)BZ * MIDC * HWP];
__device__ float    g_merged[(size_t)BZ * MIDC * HWP];
__device__ float    g_sums[BZ * MIDC];
__device__ uint32_t g_WexpF[36864];   // [mt3][kc2][wr2][ki6][mi2][hl2][lane32][q4]
__device__ uint32_t g_WprojF[36864];  // [kc4][wr2][ki6][mi3][hl2][lane32][q4]
__device__ float    g_bexp[MIDC];
__device__ float    g_W9[MIDC * 9];
__device__ float    g_T[MIDC];
__device__ float    g_bproj[COUTC];

__device__ __forceinline__ float silu_f(float v) { return v / (1.f + __expf(-v)); }

__device__ __forceinline__ uint32_t f2tf32(float v) {
    uint32_t r;
    asm("cvt.rna.tf32.f32 %0, %1;" : "=r"(r) : "f"(v));
    return r;
}

__device__ __forceinline__ void mma8(float* c, const uint32_t* a, const uint32_t* b) {
    asm volatile(
        "mma.sync.aligned.m16n8k8.row.col.f32.tf32.tf32.f32 "
        "{%0,%1,%2,%3},{%4,%5,%6,%7},{%8,%9},{%0,%1,%2,%3};"
        : "+f"(c[0]), "+f"(c[1]), "+f"(c[2]), "+f"(c[3])
        : "r"(a[0]), "r"(a[1]), "r"(a[2]), "r"(a[3]), "r"(b[0]), "r"(b[1]));
}

// ---------------------------------------------------------------------------
// Fold BN into weights/biases; emit fragment-ordered tf32 hi/lo weights.
// ---------------------------------------------------------------------------
__global__ void prep_kernel(const float* __restrict__ expand_w,
                            const float* __restrict__ expand_bn,
                            const float* __restrict__ dw_w,
                            const float* __restrict__ dw_bn,
                            const float* __restrict__ id_w,
                            const float* __restrict__ id_bn,
                            const float* __restrict__ merge_bn,
                            const float* __restrict__ proj_w,
                            const float* __restrict__ proj_bn) {
    int tid = blockIdx.x * blockDim.x + threadIdx.x;
    int nth = gridDim.x * blockDim.x;

    // expand weights, fragment order
    for (int idx = tid; idx < 36864; idx += nth) {
        int q = idx & 3, lane = (idx >> 2) & 31, hl = (idx >> 7) & 1;
        int t = idx >> 8;
        int mi = t & 1; t >>= 1;
        int ki = t % 6; t /= 6;
        int wr = t & 1; t >>= 1;
        int kc = t & 1; int mt = t >> 1;
        int m = mt * 64 + wr * 32 + mi * 16 + (lane >> 2) + 8 * (q & 1);
        int k = kc * 48 + ki * 8 + (lane & 3) + 4 * (q >> 1);
        float sc = expand_bn[m] * rsqrtf(expand_bn[3 * MIDC + m] + EPSBN);
        float wv = expand_w[m * CINC + k] * sc;
        uint32_t h = f2tf32(wv);
        g_WexpF[idx] = hl ? f2tf32(wv - __uint_as_float(h)) : h;
    }
    // proj weights, fragment order
    for (int idx = tid; idx < 36864; idx += nth) {
        int q = idx & 3, lane = (idx >> 2) & 31, hl = (idx >> 7) & 1;
        int t = idx >> 8;
        int mi = t % 3; t /= 3;
        int ki = t % 6; t /= 6;
        int wr = t & 1; int kc = t >> 1;
        int m = wr * 48 + mi * 16 + (lane >> 2) + 8 * (q & 1);
        int k = kc * 48 + ki * 8 + (lane & 3) + 4 * (q >> 1);
        float sc = proj_bn[m] * rsqrtf(proj_bn[3 * COUTC + m] + EPSBN);
        float wv = proj_w[m * MIDC + k] * sc;
        uint32_t h = f2tf32(wv);
        g_WprojF[idx] = hl ? f2tf32(wv - __uint_as_float(h)) : h;
    }
    for (int o = tid; o < MIDC; o += nth) {
        float sc = expand_bn[o] * rsqrtf(expand_bn[3 * MIDC + o] + EPSBN);
        g_bexp[o] = expand_bn[MIDC + o] - expand_bn[2 * MIDC + o] * sc;
    }
    for (int c = tid; c < MIDC; c += nth) {
        float dsc = dw_bn[c] * rsqrtf(dw_bn[3 * MIDC + c] + EPSBN);
        float dsh = dw_bn[MIDC + c] - dw_bn[2 * MIDC + c] * dsc;
        float isc = id_bn[c] * rsqrtf(id_bn[3 * MIDC + c] + EPSBN);
        float ish = id_bn[MIDC + c] - id_bn[2 * MIDC + c] * isc;
        float msc = merge_bn[c] * rsqrtf(merge_bn[3 * MIDC + c] + EPSBN);
        float msh = merge_bn[MIDC + c] - merge_bn[2 * MIDC + c] * msc;
        #pragma unroll
        for (int k = 0; k < 9; k++) g_W9[c * 9 + k] = msc * dsc * dw_w[c * 9 + k];
        g_W9[c * 9 + 4] += msc * isc * id_w[c];
        g_T[c] = msc * (dsh + ish) + msh;
    }
    for (int o = tid; o < COUTC; o += nth) {
        float sc = proj_bn[o] * rsqrtf(proj_bn[3 * COUTC + o] + EPSBN);
        g_bproj[o] = proj_bn[COUTC + o] - proj_bn[2 * COUTC + o] * sc;
    }
}

// ---------------------------------------------------------------------------
// Expand 1x1 GEMM. Block tile 64(M-pass x3) x 128(N); warp tile 32x32.
// A: fragment-ordered presplit tf32 from gmem -> smem -> LDS.128.
// B: fp32 smem, tf32 split in-loop. 3-pass tf32 mma.
// ---------------------------------------------------------------------------
__global__ void __launch_bounds__(256) expand_gemm(const float* __restrict__ x) {
    extern __shared__ float sm[];
    uint32_t* AsU = (uint32_t*)sm;        // EXP_AS_U32
    float* Bs = sm + EXP_AS_U32;          // [96][BSS]
    int b = blockIdx.z;
    int p0 = blockIdx.x * 128;
    int tid = threadIdx.x;
    int lane = tid & 31, w = tid >> 5;
    int wr = w >> 2, wc = w & 3;
    int g = lane >> 2, tg = lane & 3;
    const float* xb = x + (size_t)b * CINC * HWP;
    float* ob = g_mid + (size_t)b * MIDC * HWP;

    // Load Bs: [96 k][128 n] (guard last tile)
    {
        float4 tmp[12];
        #pragma unroll
        for (int j = 0; j < 12; j++) {
            int v = tid + j * 256;
            int k = v >> 5, c4 = (v & 31) << 2;
            int p = p0 + c4;
            tmp[j] = (p < HWP) ? *(const float4*)&xb[(size_t)k * HWP + p]
                               : make_float4(0.f, 0.f, 0.f, 0.f);
        }
        #pragma unroll
        for (int j = 0; j < 12; j++) {
            int v = tid + j * 256;
            int k = v >> 5, c4 = (v & 31) << 2;
            float* d = &Bs[k * BSS + c4];
            d[0] = tmp[j].x; d[1] = tmp[j].y; d[2] = tmp[j].z; d[3] = tmp[j].w;
        }
    }

    for (int mt = 0; mt < 3; mt++) {
        float acc[2][4][4] = {};
        for (int kc = 0; kc < 2; kc++) {
            __syncthreads();  // As free (first iter: Bs ready too)
            {
                const uint4* src = (const uint4*)(g_WexpF + (mt * 2 + kc) * EXP_AS_U32);
                uint4 t0[6];
                #pragma unroll
                for (int j = 0; j < 6; j++) t0[j] = src[tid + j * 256];
                #pragma unroll
                for (int j = 0; j < 6; j++) ((uint4*)AsU)[tid + j * 256] = t0[j];
            }
            __syncthreads();

            #pragma unroll
            for (int ki = 0; ki < 6; ki++) {
                uint4 ah[2], al[2];
                #pragma unroll
                for (int mi = 0; mi < 2; mi++) {
                    int off = (((wr * 6 + ki) * 2 + mi) * 2) * 128 + lane * 4;
                    ah[mi] = *(const uint4*)&AsU[off];
                    al[mi] = *(const uint4*)&AsU[off + 128];
                }
                uint32_t Bh[4][2], Bl[4][2];
                int kr = kc * 48 + ki * 8;
                #pragma unroll
                for (int ni = 0; ni < 4; ni++) {
                    int nb = wc * 32 + ni * 8 + g;
                    #pragma unroll
                    for (int q = 0; q < 2; q++) {
                        float v = Bs[(kr + tg + q * 4) * BSS + nb];
                        uint32_t h = f2tf32(v);
                        Bh[ni][q] = h;
                        Bl[ni][q] = f2tf32(v - __uint_as_float(h));
                    }
                }
                #pragma unroll
                for (int mi = 0; mi < 2; mi++)
                    #pragma unroll
                    for (int ni = 0; ni < 4; ni++) {
                        mma8(acc[mi][ni], (const uint32_t*)&ah[mi], Bh[ni]);
                        mma8(acc[mi][ni], (const uint32_t*)&al[mi], Bh[ni]);
                        mma8(acc[mi][ni], (const uint32_t*)&ah[mi], Bl[ni]);
                    }
            }
        }
        // Epilogue: STG.64; each warp-row covers 32 contiguous cols (full sectors)
        int m0 = mt * 64;
        #pragma unroll
        for (int mi = 0; mi < 2; mi++) {
            int o = m0 + wr * 32 + mi * 16 + g;
            float b0 = g_bexp[o], b1 = g_bexp[o + 8];
            #pragma unroll
            for (int ni = 0; ni < 4; ni++) {
                int p = p0 + wc * 32 + ni * 8 + tg * 2;
                if (p < HWP) {
                    float2 r0 = make_float2(silu_f(acc[mi][ni][0] + b0),
                                            silu_f(acc[mi][ni][1] + b0));
                    *(float2*)&ob[(size_t)o * HWP + p] = r0;
                    float2 r1 = make_float2(silu_f(acc[mi][ni][2] + b1),
                                            silu_f(acc[mi][ni][3] + b1));
                    *(float2*)&ob[(size_t)(o + 8) * HWP + p] = r1;
                }
            }
        }
    }
}

// ---------------------------------------------------------------------------
// Fused shift + shuffle + dw3x3 + identity + BNs + SiLU + spatial-sum.
// ---------------------------------------------------------------------------
#define SPS 60
__global__ void __launch_bounds__(256) dwmerge_kernel() {
    __shared__ float sps[58 * SPS];
    __shared__ float sred[8];
    int bc = blockIdx.x;
    int b = bc / MIDC, c = bc - b * MIDC;
    int cpre = (c & 3) * 48 + (c >> 2);
    int gg = c & 3;
    int oy = (gg == 0) ? -1 : (gg == 2) ? 1 : 0;
    int ox = (gg == 1) ? -1 : (gg == 3) ? 1 : 0;
    const float* plane = g_mid + ((size_t)b * MIDC + cpre) * HWP;
    int tid = threadIdx.x;

    for (int idx = tid; idx < 58 * 58; idx += 256) {
        int r = idx / 58, cx = idx - r * 58;
        int hp = r - 1, wp = cx - 1;
        int hs = hp + oy, ws = wp + ox;
        bool ok = (unsigned)hp < 56u && (unsigned)wp < 56u &&
                  (unsigned)hs < 56u && (unsigned)ws < 56u;
        sps[r * SPS + cx] = ok ? plane[hs * 56 + ws] : 0.f;
    }
    float w9[9];
    #pragma unroll
    for (int k = 0; k < 9; k++) w9[k] = g_W9[c * 9 + k];
    float T = g_T[c];
    __syncthreads();

    float* outp = g_merged + ((size_t)b * MIDC + c) * HWP;
    int wid = tid >> 5, lane = tid & 31;
    float lsum = 0.f;
    for (int r = wid; r < 56; r += 8) {
        const float* base = &sps[(r + 1) * SPS + 1];
        {
            int cc = lane;
            float acc = 0.f;
            #pragma unroll
            for (int dy = -1; dy <= 1; dy++)
                #pragma unroll
                for (int dx = -1; dx <= 1; dx++)
                    acc += w9[(dy + 1) * 3 + dx + 1] * base[dy * SPS + cc + dx];
            float s = silu_f(acc + T);
            outp[r * 56 + cc] = s;
            lsum += s;
        }
        if (lane < 24) {
            int cc = lane + 32;
            float acc = 0.f;
            #pragma unroll
            for (int dy = -1; dy <= 1; dy++)
                #pragma unroll
                for (int dx = -1; dx <= 1; dx++)
                    acc += w9[(dy + 1) * 3 + dx + 1] * base[dy * SPS + cc + dx];
            float s = silu_f(acc + T);
            outp[r * 56 + cc] = s;
            lsum += s;
        }
    }
    #pragma unroll
    for (int o = 16; o > 0; o >>= 1) lsum += __shfl_down_sync(0xffffffffu, lsum, o);
    if (lane == 0) sred[wid] = lsum;
    __syncthreads();
    if (tid < 8) {
        float v = sred[tid];
        #pragma unroll
        for (int o = 4; o > 0; o >>= 1) v += __shfl_down_sync(0xffu, v, o);
        if (tid == 0) g_sums[bc] = v;
    }
}

// ---------------------------------------------------------------------------
// Project 1x1 GEMM. Block: M=96 (single pass, mi=3) x N=128. SE computed
// inline from g_sums; SE scale folded into Bs; BN+residual+SiLU epilogue.
// ---------------------------------------------------------------------------
__global__ void __launch_bounds__(256) proj_gemm(const float* __restrict__ x,
                                                 const float* __restrict__ red_w,
                                                 const float* __restrict__ red_b,
                                                 const float* __restrict__ exp_w,
                                                 const float* __restrict__ exp_b,
                                                 float* __restrict__ out) {
    extern __shared__ float sm[];
    uint32_t* AsU = (uint32_t*)sm;        // PROJ_AS_U32
    float* Bs = sm + PROJ_AS_U32;         // [96][BSS]
    __shared__ float s_se[192];
    __shared__ float smean[192];
    __shared__ float sredu[24];

    int b = blockIdx.z;
    int p0 = blockIdx.x * 128;
    int tid = threadIdx.x;
    int lane = tid & 31, w = tid >> 5;
    int wr = w >> 2, wc = w & 3;
    int g = lane >> 2, tg = lane & 3;
    const float* mb = g_merged + (size_t)b * MIDC * HWP;

    // Inline SE gating (cheap, per-block recompute)
    if (tid < 192) smean[tid] = g_sums[b * 192 + tid] * (1.f / 3136.f);
    __syncthreads();
    if (tid < 24) {
        int gq = tid >> 1;
        float a = red_b[tid];
        #pragma unroll
        for (int i = 0; i < 16; i++) a += red_w[tid * 16 + i] * smean[gq * 16 + i];
        sredu[tid] = fmaxf(a, 0.f);
    }
    __syncthreads();
    if (tid < 192) {
        int gq = tid >> 4;
        float v = exp_w[tid * 2] * sredu[gq * 2] + exp_w[tid * 2 + 1] * sredu[gq * 2 + 1]
                + exp_b[tid];
        s_se[tid] = 1.f / (1.f + __expf(-v));
    }

    float acc[3][4][4] = {};

    for (int half = 0; half < 2; half++) {
        __syncthreads();  // Bs free + s_se ready
        {
            float4 tmp[12];
            #pragma unroll
            for (int j = 0; j < 12; j++) {
                int v = tid + j * 256;
                int k = v >> 5, c4 = (v & 31) << 2;
                int p = p0 + c4;
                tmp[j] = (p < HWP)
                    ? *(const float4*)&mb[(size_t)(half * 96 + k) * HWP + p]
                    : make_float4(0.f, 0.f, 0.f, 0.f);
            }
            #pragma unroll
            for (int j = 0; j < 12; j++) {
                int v = tid + j * 256;
                int k = v >> 5, c4 = (v & 31) << 2;
                float s = s_se[half * 96 + k];
                float* d = &Bs[k * BSS + c4];
                d[0] = tmp[j].x * s; d[1] = tmp[j].y * s;
                d[2] = tmp[j].z * s; d[3] = tmp[j].w * s;
            }
        }
        for (int kcl = 0; kcl < 2; kcl++) {
            int kc = half * 2 + kcl;
            __syncthreads();  // As free + Bs ready
            {
                const uint4* src = (const uint4*)(g_WprojF + kc * PROJ_AS_U32);
                uint4 t0[9];
                #pragma unroll
                for (int j = 0; j < 9; j++) t0[j] = src[tid + j * 256];
                #pragma unroll
                for (int j = 0; j < 9; j++) ((uint4*)AsU)[tid + j * 256] = t0[j];
            }
            __syncthreads();

            #pragma unroll
            for (int ki = 0; ki < 6; ki++) {
                uint4 ah[3], al[3];
                #pragma unroll
                for (int mi = 0; mi < 3; mi++) {
                    int off = (((wr * 6 + ki) * 3 + mi) * 2) * 128 + lane * 4;
                    ah[mi] = *(const uint4*)&AsU[off];
                    al[mi] = *(const uint4*)&AsU[off + 128];
                }
                uint32_t Bh[4][2], Bl[4][2];
                int kr = kcl * 48 + ki * 8;
                #pragma unroll
                for (int ni = 0; ni < 4; ni++) {
                    int nb = wc * 32 + ni * 8 + g;
                    #pragma unroll
                    for (int q = 0; q < 2; q++) {
                        float v = Bs[(kr + tg + q * 4) * BSS + nb];
                        uint32_t h = f2tf32(v);
                        Bh[ni][q] = h;
                        Bl[ni][q] = f2tf32(v - __uint_as_float(h));
                    }
                }
                #pragma unroll
                for (int mi = 0; mi < 3; mi++)
                    #pragma unroll
                    for (int ni = 0; ni < 4; ni++) {
                        mma8(acc[mi][ni], (const uint32_t*)&ah[mi], Bh[ni]);
                        mma8(acc[mi][ni], (const uint32_t*)&al[mi], Bh[ni]);
                        mma8(acc[mi][ni], (const uint32_t*)&ah[mi], Bl[ni]);
                    }
            }
        }
    }

    const float* xb = x + (size_t)b * COUTC * HWP;
    float* ob = out + (size_t)b * COUTC * HWP;
    #pragma unroll
    for (int mi = 0; mi < 3; mi++) {
        int o = wr * 48 + mi * 16 + g;
        float b0 = g_bproj[o], b1 = g_bproj[o + 8];
        #pragma unroll
        for (int ni = 0; ni < 4; ni++) {
            int p = p0 + wc * 32 + ni * 8 + tg * 2;
            if (p < HWP) {
                float2 x0 = *(const float2*)&xb[(size_t)o * HWP + p];
                float2 r0;
                r0.x = silu_f(acc[mi][ni][0] + b0 + x0.x);
                r0.y = silu_f(acc[mi][ni][1] + b0 + x0.y);
                *(float2*)&ob[(size_t)o * HWP + p] = r0;
                float2 x1 = *(const float2*)&xb[(size_t)(o + 8) * HWP + p];
                float2 r1;
                r1.x = silu_f(acc[mi][ni][2] + b1 + x1.x);
                r1.y = silu_f(acc[mi][ni][3] + b1 + x1.y);
                *(float2*)&ob[(size_t)(o + 8) * HWP + p] = r1;
            }
        }
    }
}

// ---------------------------------------------------------------------------
extern "C" void kernel_launch(void* const* d_in, const int* in_sizes, int n_in,
                              void* d_out, int out_size) {
    const float* x         = (const float*)d_in[0];
    const float* expand_w  = (const float*)d_in[1];
    const float* expand_bn = (const float*)d_in[2];
    const float* dw_w      = (const float*)d_in[3];
    const float* dw_bn     = (const float*)d_in[4];
    const float* id_w      = (const float*)d_in[5];
    const float* id_bn     = (const float*)d_in[6];
    const float* merge_bn  = (const float*)d_in[7];
    const float* se_red_w  = (const float*)d_in[8];
    const float* se_red_b  = (const float*)d_in[9];
    const float* se_exp_w  = (const float*)d_in[10];
    const float* se_exp_b  = (const float*)d_in[11];
    const float* proj_w    = (const float*)d_in[12];
    const float* proj_bn   = (const float*)d_in[13];
    float* out = (float*)d_out;

    cudaFuncSetAttribute(expand_gemm, cudaFuncAttributeMaxDynamicSharedMemorySize, EXP_SMEM);
    cudaFuncSetAttribute(proj_gemm,   cudaFuncAttributeMaxDynamicSharedMemorySize, PROJ_SMEM);

    prep_kernel<<<80, 256>>>(expand_w, expand_bn, dw_w, dw_bn, id_w, id_bn,
                             merge_bn, proj_w, proj_bn);
    expand_gemm<<<dim3(25, 1, BZ), 256, EXP_SMEM>>>(x);
    dwmerge_kernel<<<BZ * MIDC, 256>>>();
    proj_gemm<<<dim3(25, 1, BZ), 256, PROJ_SMEM>>>(x, se_red_w, se_red_b,
                                                   se_exp_w, se_exp_b, out);
}

// round 5
// speedup vs baseline: 1.9377x; 1.2264x over previous
#include <cuda_runtime.h>
#include <cuda_bf16.h>
#include <math.h>
#include <stdint.h>

#define BZ    64
#define CINC  96
#define COUTC 96
#define MIDC  192
#define HWP   3136
#define EPSBN 1e-5f

#define BSS 136                  // B pair-row stride (uint32): bank = tg*8+g, conflict-free
#define EXP_AS_U32  6144         // per-mt A chunk: [wr2][ki6][mi2][hl2][lane32][q4]
#define PROJ_AS_U32 9216         // per-half A chunk: [wr2][ki6][mi3][hl2][lane32][q4]
#define B_U32 (48 * BSS)         // one hi or lo plane: 48 k-pairs x 128 n (+pad)
#define EXP_SMEM  ((EXP_AS_U32  + 2 * B_U32) * 4)
#define PROJ_SMEM ((PROJ_AS_U32 + 2 * B_U32) * 4)

// Scratch (device globals: allowed; no cudaMalloc anywhere)
__device__ float    g_mid[(size_t)BZ * MIDC * HWP];
__device__ float    g_merged[(size_t)BZ * MIDC * HWP];
__device__ float    g_sums[BZ * MIDC];
__device__ uint32_t g_WexpF[18432];   // [mt3][wr2][ki6][mi2][hl2][lane32][q4]
__device__ uint32_t g_WprojF[18432];  // [half2][wr2][ki6][mi3][hl2][lane32][q4]
__device__ float    g_bexp[MIDC];
__device__ float    g_W9[MIDC * 9];
__device__ float    g_T[MIDC];
__device__ float    g_bproj[COUTC];

__device__ __forceinline__ float silu_f(float v) { return v / (1.f + __expf(-v)); }

__device__ __forceinline__ uint32_t packbf2(float lo_elem, float hi_elem) {
    __nv_bfloat162 t = __floats2bfloat162_rn(lo_elem, hi_elem);  // .x = low 16 bits
    return *(uint32_t*)&t;
}

__device__ __forceinline__ void mma16(float* c, const uint32_t* a, const uint32_t* b) {
    asm volatile(
        "mma.sync.aligned.m16n8k16.row.col.f32.bf16.bf16.f32 "
        "{%0,%1,%2,%3},{%4,%5,%6,%7},{%8,%9},{%0,%1,%2,%3};"
        : "+f"(c[0]), "+f"(c[1]), "+f"(c[2]), "+f"(c[3])
        : "r"(a[0]), "r"(a[1]), "r"(a[2]), "r"(a[3]), "r"(b[0]), "r"(b[1]));
}

// ---------------------------------------------------------------------------
// Fold BN into weights/biases; emit fragment-ordered packed-bf16 hi/lo weights.
// ---------------------------------------------------------------------------
__global__ void prep_kernel(const float* __restrict__ expand_w,
                            const float* __restrict__ expand_bn,
                            const float* __restrict__ dw_w,
                            const float* __restrict__ dw_bn,
                            const float* __restrict__ id_w,
                            const float* __restrict__ id_bn,
                            const float* __restrict__ merge_bn,
                            const float* __restrict__ proj_w,
                            const float* __restrict__ proj_bn) {
    int tid = blockIdx.x * blockDim.x + threadIdx.x;
    int nth = gridDim.x * blockDim.x;

    // expand weights, fragment order (m16n8k16 A-frag, k-pairs packed)
    for (int idx = tid; idx < 18432; idx += nth) {
        int q = idx & 3, lane = (idx >> 2) & 31, hl = (idx >> 7) & 1;
        int t = idx >> 8;
        int mi = t & 1; t >>= 1;
        int ki = t % 6; t /= 6;
        int wr = t & 1; int mt = t >> 1;
        int m = mt * 64 + wr * 32 + mi * 16 + (lane >> 2) + 8 * (q & 1);
        int k = ki * 16 + (lane & 3) * 2 + 8 * (q >> 1);
        float sc = expand_bn[m] * rsqrtf(expand_bn[3 * MIDC + m] + EPSBN);
        float w0 = expand_w[m * CINC + k] * sc;
        float w1 = expand_w[m * CINC + k + 1] * sc;
        float h0 = __bfloat162float(__float2bfloat16_rn(w0));
        float h1 = __bfloat162float(__float2bfloat16_rn(w1));
        g_WexpF[idx] = hl ? packbf2(w0 - h0, w1 - h1) : packbf2(h0, h1);
    }
    // proj weights, fragment order
    for (int idx = tid; idx < 18432; idx += nth) {
        int q = idx & 3, lane = (idx >> 2) & 31, hl = (idx >> 7) & 1;
        int t = idx >> 8;
        int mi = t % 3; t /= 3;
        int ki = t % 6; t /= 6;
        int wr = t & 1; int half = t >> 1;
        int m = wr * 48 + mi * 16 + (lane >> 2) + 8 * (q & 1);
        int k = half * 96 + ki * 16 + (lane & 3) * 2 + 8 * (q >> 1);
        float sc = proj_bn[m] * rsqrtf(proj_bn[3 * COUTC + m] + EPSBN);
        float w0 = proj_w[m * MIDC + k] * sc;
        float w1 = proj_w[m * MIDC + k + 1] * sc;
        float h0 = __bfloat162float(__float2bfloat16_rn(w0));
        float h1 = __bfloat162float(__float2bfloat16_rn(w1));
        g_WprojF[idx] = hl ? packbf2(w0 - h0, w1 - h1) : packbf2(h0, h1);
    }
    for (int o = tid; o < MIDC; o += nth) {
        float sc = expand_bn[o] * rsqrtf(expand_bn[3 * MIDC + o] + EPSBN);
        g_bexp[o] = expand_bn[MIDC + o] - expand_bn[2 * MIDC + o] * sc;
    }
    for (int c = tid; c < MIDC; c += nth) {
        float dsc = dw_bn[c] * rsqrtf(dw_bn[3 * MIDC + c] + EPSBN);
        float dsh = dw_bn[MIDC + c] - dw_bn[2 * MIDC + c] * dsc;
        float isc = id_bn[c] * rsqrtf(id_bn[3 * MIDC + c] + EPSBN);
        float ish = id_bn[MIDC + c] - id_bn[2 * MIDC + c] * isc;
        float msc = merge_bn[c] * rsqrtf(merge_bn[3 * MIDC + c] + EPSBN);
        float msh = merge_bn[MIDC + c] - merge_bn[2 * MIDC + c] * msc;
        #pragma unroll
        for (int k = 0; k < 9; k++) g_W9[c * 9 + k] = msc * dsc * dw_w[c * 9 + k];
        g_W9[c * 9 + 4] += msc * isc * id_w[c];
        g_T[c] = msc * (dsh + ish) + msh;
    }
    for (int o = tid; o < COUTC; o += nth) {
        float sc = proj_bn[o] * rsqrtf(proj_bn[3 * COUTC + o] + EPSBN);
        g_bproj[o] = proj_bn[COUTC + o] - proj_bn[2 * COUTC + o] * sc;
    }
}

// ---------------------------------------------------------------------------
// Load 96 k-rows x 128 n of activations as packed bf16x2 k-pairs, hi/lo split.
// Optional per-k scale (SE). 6 tasks/thread.
// ---------------------------------------------------------------------------
__device__ __forceinline__ void load_B_pairs(const float* __restrict__ src,
                                             int p0, uint32_t* Bh, uint32_t* Bl,
                                             const float* __restrict__ scale,
                                             int tid) {
    #pragma unroll
    for (int j = 0; j < 6; j++) {
        int v = tid + j * 256;
        int k2 = v >> 5, c4 = (v & 31) << 2;
        int p = p0 + c4;
        float4 r0 = make_float4(0.f, 0.f, 0.f, 0.f);
        float4 r1 = r0;
        if (p < HWP) {
            r0 = *(const float4*)&src[(size_t)(2 * k2) * HWP + p];
            r1 = *(const float4*)&src[(size_t)(2 * k2 + 1) * HWP + p];
        }
        if (scale) {
            float s0 = scale[2 * k2], s1 = scale[2 * k2 + 1];
            r0.x *= s0; r0.y *= s0; r0.z *= s0; r0.w *= s0;
            r1.x *= s1; r1.y *= s1; r1.z *= s1; r1.w *= s1;
        }
        uint32_t hh[4], ll[4];
        float e0[4] = {r0.x, r0.y, r0.z, r0.w};
        float e1[4] = {r1.x, r1.y, r1.z, r1.w};
        #pragma unroll
        for (int i = 0; i < 4; i++) {
            float h0 = __bfloat162float(__float2bfloat16_rn(e0[i]));
            float h1 = __bfloat162float(__float2bfloat16_rn(e1[i]));
            hh[i] = packbf2(h0, h1);
            ll[i] = packbf2(e0[i] - h0, e1[i] - h1);
        }
        *(uint4*)&Bh[k2 * BSS + c4] = make_uint4(hh[0], hh[1], hh[2], hh[3]);
        *(uint4*)&Bl[k2 * BSS + c4] = make_uint4(ll[0], ll[1], ll[2], ll[3]);
    }
}

// ---------------------------------------------------------------------------
// Expand 1x1 GEMM. Block 64(Mx3 passes) x 128(N); warp tile 32x32; bf16 k16.
// ---------------------------------------------------------------------------
__global__ void __launch_bounds__(256) expand_gemm(const float* __restrict__ x) {
    extern __shared__ uint32_t smu[];
    uint32_t* AsU = smu;                  // EXP_AS_U32
    uint32_t* Bh  = smu + EXP_AS_U32;     // B_U32
    uint32_t* Bl  = Bh + B_U32;           // B_U32
    int b = blockIdx.z;
    int p0 = blockIdx.x * 128;
    int tid = threadIdx.x;
    int lane = tid & 31, w = tid >> 5;
    int wr = w >> 2, wc = w & 3;
    int g = lane >> 2, tg = lane & 3;
    const float* xb = x + (size_t)b * CINC * HWP;
    float* ob = g_mid + (size_t)b * MIDC * HWP;

    load_B_pairs(xb, p0, Bh, Bl, nullptr, tid);

    for (int mt = 0; mt < 3; mt++) {
        __syncthreads();  // As free (epilogue reads regs only); iter0: nothing pending
        {
            const uint4* src = (const uint4*)(g_WexpF + mt * EXP_AS_U32);
            uint4 t0[6];
            #pragma unroll
            for (int j = 0; j < 6; j++) t0[j] = src[tid + j * 256];
            #pragma unroll
            for (int j = 0; j < 6; j++) ((uint4*)AsU)[tid + j * 256] = t0[j];
        }
        __syncthreads();  // As + (iter0) B visible

        float acc[2][4][4] = {};
        #pragma unroll
        for (int ki = 0; ki < 6; ki++) {
            uint4 ah[2], al[2];
            #pragma unroll
            for (int mi = 0; mi < 2; mi++) {
                int off = (((wr * 6 + ki) * 2 + mi) * 2) * 128 + lane * 4;
                ah[mi] = *(const uint4*)&AsU[off];
                al[mi] = *(const uint4*)&AsU[off + 128];
            }
            uint32_t bh[4][2], bl[4][2];
            int kr2 = ki * 8;
            #pragma unroll
            for (int ni = 0; ni < 4; ni++) {
                int nb = wc * 32 + ni * 8 + g;
                bh[ni][0] = Bh[(kr2 + tg) * BSS + nb];
                bh[ni][1] = Bh[(kr2 + tg + 4) * BSS + nb];
                bl[ni][0] = Bl[(kr2 + tg) * BSS + nb];
                bl[ni][1] = Bl[(kr2 + tg + 4) * BSS + nb];
            }
            #pragma unroll
            for (int mi = 0; mi < 2; mi++)
                #pragma unroll
                for (int ni = 0; ni < 4; ni++) {
                    mma16(acc[mi][ni], (const uint32_t*)&ah[mi], bh[ni]);
                    mma16(acc[mi][ni], (const uint32_t*)&al[mi], bh[ni]);
                    mma16(acc[mi][ni], (const uint32_t*)&ah[mi], bl[ni]);
                }
        }

        int m0 = mt * 64;
        #pragma unroll
        for (int mi = 0; mi < 2; mi++) {
            int o = m0 + wr * 32 + mi * 16 + g;
            float b0 = g_bexp[o], b1 = g_bexp[o + 8];
            #pragma unroll
            for (int ni = 0; ni < 4; ni++) {
                int p = p0 + wc * 32 + ni * 8 + tg * 2;
                if (p < HWP) {
                    float2 r0 = make_float2(silu_f(acc[mi][ni][0] + b0),
                                            silu_f(acc[mi][ni][1] + b0));
                    *(float2*)&ob[(size_t)o * HWP + p] = r0;
                    float2 r1 = make_float2(silu_f(acc[mi][ni][2] + b1),
                                            silu_f(acc[mi][ni][3] + b1));
                    *(float2*)&ob[(size_t)(o + 8) * HWP + p] = r1;
                }
            }
        }
    }
}

// ---------------------------------------------------------------------------
// Fused shift + shuffle + dw3x3 + identity + BNs + SiLU + spatial-sum.
// ---------------------------------------------------------------------------
#define SPS 60
__global__ void __launch_bounds__(256) dwmerge_kernel() {
    __shared__ float sps[58 * SPS];
    __shared__ float sred[8];
    int bc = blockIdx.x;
    int b = bc / MIDC, c = bc - b * MIDC;
    int cpre = (c & 3) * 48 + (c >> 2);
    int gg = c & 3;
    int oy = (gg == 0) ? -1 : (gg == 2) ? 1 : 0;
    int ox = (gg == 1) ? -1 : (gg == 3) ? 1 : 0;
    const float* plane = g_mid + ((size_t)b * MIDC + cpre) * HWP;
    int tid = threadIdx.x;

    for (int idx = tid; idx < 58 * 58; idx += 256) {
        int r = idx / 58, cx = idx - r * 58;
        int hp = r - 1, wp = cx - 1;
        int hs = hp + oy, ws = wp + ox;
        bool ok = (unsigned)hp < 56u && (unsigned)wp < 56u &&
                  (unsigned)hs < 56u && (unsigned)ws < 56u;
        sps[r * SPS + cx] = ok ? plane[hs * 56 + ws] : 0.f;
    }
    float w9[9];
    #pragma unroll
    for (int k = 0; k < 9; k++) w9[k] = g_W9[c * 9 + k];
    float T = g_T[c];
    __syncthreads();

    float* outp = g_merged + ((size_t)b * MIDC + c) * HWP;
    int wid = tid >> 5, lane = tid & 31;
    float lsum = 0.f;
    for (int r = wid; r < 56; r += 8) {
        const float* base = &sps[(r + 1) * SPS + 1];
        {
            int cc = lane;
            float acc = 0.f;
            #pragma unroll
            for (int dy = -1; dy <= 1; dy++)
                #pragma unroll
                for (int dx = -1; dx <= 1; dx++)
                    acc += w9[(dy + 1) * 3 + dx + 1] * base[dy * SPS + cc + dx];
            float s = silu_f(acc + T);
            outp[r * 56 + cc] = s;
            lsum += s;
        }
        if (lane < 24) {
            int cc = lane + 32;
            float acc = 0.f;
            #pragma unroll
            for (int dy = -1; dy <= 1; dy++)
                #pragma unroll
                for (int dx = -1; dx <= 1; dx++)
                    acc += w9[(dy + 1) * 3 + dx + 1] * base[dy * SPS + cc + dx];
            float s = silu_f(acc + T);
            outp[r * 56 + cc] = s;
            lsum += s;
        }
    }
    #pragma unroll
    for (int o = 16; o > 0; o >>= 1) lsum += __shfl_down_sync(0xffffffffu, lsum, o);
    if (lane == 0) sred[wid] = lsum;
    __syncthreads();
    if (tid < 8) {
        float v = sred[tid];
        #pragma unroll
        for (int o = 4; o > 0; o >>= 1) v += __shfl_down_sync(0xffu, v, o);
        if (tid == 0) g_sums[bc] = v;
    }
}

// ---------------------------------------------------------------------------
// Project 1x1 GEMM. M=96 single pass (mi=3) x N=128; bf16 k16; inline SE.
// ---------------------------------------------------------------------------
__global__ void __launch_bounds__(256) proj_gemm(const float* __restrict__ x,
                                                 const float* __restrict__ red_w,
                                                 const float* __restrict__ red_b,
                                                 const float* __restrict__ exp_w,
                                                 const float* __restrict__ exp_b,
                                                 float* __restrict__ out) {
    extern __shared__ uint32_t smu[];
    uint32_t* AsU = smu;                   // PROJ_AS_U32
    uint32_t* Bhs = smu + PROJ_AS_U32;     // B_U32
    uint32_t* Bls = Bhs + B_U32;           // B_U32
    __shared__ float s_se[192];
    __shared__ float smean[192];
    __shared__ float sredu[24];

    int b = blockIdx.z;
    int p0 = blockIdx.x * 128;
    int tid = threadIdx.x;
    int lane = tid & 31, w = tid >> 5;
    int wr = w >> 2, wc = w & 3;
    int g = lane >> 2, tg = lane & 3;
    const float* mb = g_merged + (size_t)b * MIDC * HWP;

    if (tid < 192) smean[tid] = g_sums[b * 192 + tid] * (1.f / 3136.f);
    __syncthreads();
    if (tid < 24) {
        int gq = tid >> 1;
        float a = red_b[tid];
        #pragma unroll
        for (int i = 0; i < 16; i++) a += red_w[tid * 16 + i] * smean[gq * 16 + i];
        sredu[tid] = fmaxf(a, 0.f);
    }
    __syncthreads();
    if (tid < 192) {
        int gq = tid >> 4;
        float v = exp_w[tid * 2] * sredu[gq * 2] + exp_w[tid * 2 + 1] * sredu[gq * 2 + 1]
                + exp_b[tid];
        s_se[tid] = 1.f / (1.f + __expf(-v));
    }

    float acc[3][4][4] = {};

    for (int half = 0; half < 2; half++) {
        __syncthreads();  // B/A regions free; s_se visible
        load_B_pairs(mb + (size_t)(half * 96) * HWP, p0, Bhs, Bls,
                     s_se + half * 96, tid);
        {
            const uint4* src = (const uint4*)(g_WprojF + half * PROJ_AS_U32);
            uint4 t0[9];
            #pragma unroll
            for (int j = 0; j < 9; j++) t0[j] = src[tid + j * 256];
            #pragma unroll
            for (int j = 0; j < 9; j++) ((uint4*)AsU)[tid + j * 256] = t0[j];
        }
        __syncthreads();

        #pragma unroll
        for (int ki = 0; ki < 6; ki++) {
            uint4 ah[3], al[3];
            #pragma unroll
            for (int mi = 0; mi < 3; mi++) {
                int off = (((wr * 6 + ki) * 3 + mi) * 2) * 128 + lane * 4;
                ah[mi] = *(const uint4*)&AsU[off];
                al[mi] = *(const uint4*)&AsU[off + 128];
            }
            uint32_t bh[4][2], bl[4][2];
            int kr2 = ki * 8;
            #pragma unroll
            for (int ni = 0; ni < 4; ni++) {
                int nb = wc * 32 + ni * 8 + g;
                bh[ni][0] = Bhs[(kr2 + tg) * BSS + nb];
                bh[ni][1] = Bhs[(kr2 + tg + 4) * BSS + nb];
                bl[ni][0] = Bls[(kr2 + tg) * BSS + nb];
                bl[ni][1] = Bls[(kr2 + tg + 4) * BSS + nb];
            }
            #pragma unroll
            for (int mi = 0; mi < 3; mi++)
                #pragma unroll
                for (int ni = 0; ni < 4; ni++) {
                    mma16(acc[mi][ni], (const uint32_t*)&ah[mi], bh[ni]);
                    mma16(acc[mi][ni], (const uint32_t*)&al[mi], bh[ni]);
                    mma16(acc[mi][ni], (const uint32_t*)&ah[mi], bl[ni]);
                }
        }
    }

    const float* xb = x + (size_t)b * COUTC * HWP;
    float* ob = out + (size_t)b * COUTC * HWP;
    #pragma unroll
    for (int mi = 0; mi < 3; mi++) {
        int o = wr * 48 + mi * 16 + g;
        float b0 = g_bproj[o], b1 = g_bproj[o + 8];
        #pragma unroll
        for (int ni = 0; ni < 4; ni++) {
            int p = p0 + wc * 32 + ni * 8 + tg * 2;
            if (p < HWP) {
                float2 x0 = *(const float2*)&xb[(size_t)o * HWP + p];
                float2 r0;
                r0.x = silu_f(acc[mi][ni][0] + b0 + x0.x);
                r0.y = silu_f(acc[mi][ni][1] + b0 + x0.y);
                *(float2*)&ob[(size_t)o * HWP + p] = r0;
                float2 x1 = *(const float2*)&xb[(size_t)(o + 8) * HWP + p];
                float2 r1;
                r1.x = silu_f(acc[mi][ni][2] + b1 + x1.x);
                r1.y = silu_f(acc[mi][ni][3] + b1 + x1.y);
                *(float2*)&ob[(size_t)(o + 8) * HWP + p] = r1;
            }
        }
    }
}

// ---------------------------------------------------------------------------
extern "C" void kernel_launch(void* const* d_in, const int* in_sizes, int n_in,
                              void* d_out, int out_size) {
    const float* x         = (const float*)d_in[0];
    const float* expand_w  = (const float*)d_in[1];
    const float* expand_bn = (const float*)d_in[2];
    const float* dw_w      = (const float*)d_in[3];
    const float* dw_bn     = (const float*)d_in[4];
    const float* id_w      = (const float*)d_in[5];
    const float* id_bn     = (const float*)d_in[6];
    const float* merge_bn  = (const float*)d_in[7];
    const float* se_red_w  = (const float*)d_in[8];
    const float* se_red_b  = (const float*)d_in[9];
    const float* se_exp_w  = (const float*)d_in[10];
    const float* se_exp_b  = (const float*)d_in[11];
    const float* proj_w    = (const float*)d_in[12];
    const float* proj_bn   = (const float*)d_in[13];
    float* out = (float*)d_out;

    cudaFuncSetAttribute(expand_gemm, cudaFuncAttributeMaxDynamicSharedMemorySize, EXP_SMEM);
    cudaFuncSetAttribute(proj_gemm,   cudaFuncAttributeMaxDynamicSharedMemorySize, PROJ_SMEM);

    prep_kernel<<<80, 256>>>(expand_w, expand_bn, dw_w, dw_bn, id_w, id_bn,
                             merge_bn, proj_w, proj_bn);
    expand_gemm<<<dim3(25, 1, BZ), 256, EXP_SMEM>>>(x);
    dwmerge_kernel<<<BZ * MIDC, 256>>>();
    proj_gemm<<<dim3(25, 1, BZ), 256, PROJ_SMEM>>>(x, se_red_w, se_red_b,
                                                   se_exp_w, se_exp_b, out);
}

// round 6
// speedup vs baseline: 2.0335x; 1.0494x over previous
#include <cuda_runtime.h>
#include <cuda_bf16.h>
#include <math.h>
#include <stdint.h>

#define BZ    64
#define CINC  96
#define COUTC 96
#define MIDC  192
#define HWP   3136
#define EPSBN 1e-5f

#define BSS 136                    // pair-row stride (u32): bank = 8*tg+g, conflict-free
#define EXP_A_U32   6144           // per-mt A chunk  [wr2][ki6][mi2][hl2][lane32][q4]
#define PROJ_A_U32  4608           // per-kchunk A    [wr2][ki3][mi3][hl2][lane32][q4]
#define EXP_B_U32   (48 * BSS)     // one plane (hi or lo), 48 pair-rows
#define PROJ_B_U32  (24 * BSS)     // one plane per chunk, 24 pair-rows
#define EXP_SMEM  ((2 * EXP_A_U32 + 2 * EXP_B_U32) * 4)      // 101376 B
#define PROJ_SMEM ((2 * PROJ_A_U32 + 4 * PROJ_B_U32) * 4)    // 89088 B

// Scratch (device globals: allowed; no cudaMalloc anywhere)
__device__ __align__(16) float    g_mid[(size_t)BZ * MIDC * HWP];
__device__ __align__(16) uint32_t g_mergedH[(size_t)BZ * 96 * HWP];  // packed bf16 (c,c+1) hi
__device__ __align__(16) uint32_t g_mergedL[(size_t)BZ * 96 * HWP];  // packed bf16 lo residual
__device__ float    g_sums[BZ * MIDC];
__device__ __align__(16) uint32_t g_WexpF[18432];   // [mt3][wr2][ki6][mi2][hl2][lane32][q4]
__device__ __align__(16) uint32_t g_WprojF[18432];  // [chunk4][wr2][ki3][mi3][hl2][lane32][q4]
__device__ float    g_bexp[MIDC];
__device__ float    g_W9[MIDC * 9];
__device__ float    g_T[MIDC];
__device__ float    g_bproj[COUTC];

__device__ __forceinline__ float silu_f(float v) { return v / (1.f + __expf(-v)); }

__device__ __forceinline__ uint32_t packbf2(float lo_elem, float hi_elem) {
    __nv_bfloat162 t = __floats2bfloat162_rn(lo_elem, hi_elem);  // .x = low 16 bits
    return *(uint32_t*)&t;
}
__device__ __forceinline__ float2 unpackbf2(uint32_t u) {
    __nv_bfloat162 t = *(__nv_bfloat162*)&u;
    return __bfloat1622float2(t);
}
__device__ __forceinline__ float bf16hi(float v) {
    return __bfloat162float(__float2bfloat16_rn(v));
}

__device__ __forceinline__ void mma16(float* c, const uint32_t* a, const uint32_t* b) {
    asm volatile(
        "mma.sync.aligned.m16n8k16.row.col.f32.bf16.bf16.f32 "
        "{%0,%1,%2,%3},{%4,%5,%6,%7},{%8,%9},{%0,%1,%2,%3};"
        : "+f"(c[0]), "+f"(c[1]), "+f"(c[2]), "+f"(c[3])
        : "r"(a[0]), "r"(a[1]), "r"(a[2]), "r"(a[3]), "r"(b[0]), "r"(b[1]));
}

__device__ __forceinline__ uint32_t smaddr(const void* p) {
    return (uint32_t)__cvta_generic_to_shared(p);
}
__device__ __forceinline__ void cpa16(uint32_t dst_s, const void* src, bool valid) {
    int sz = valid ? 16 : 0;
    asm volatile("cp.async.cg.shared.global [%0], [%1], 16, %2;\n"
                 :: "r"(dst_s), "l"(src), "r"(sz));
}
__device__ __forceinline__ void cpa_commit() {
    asm volatile("cp.async.commit_group;\n");
}
template <int N>
__device__ __forceinline__ void cpa_wait() {
    asm volatile("cp.async.wait_group %0;\n" :: "n"(N));
}

// ---------------------------------------------------------------------------
// prep: fold BN; emit fragment-ordered packed-bf16 hi/lo weights.
// ---------------------------------------------------------------------------
__global__ void prep_kernel(const float* __restrict__ expand_w,
                            const float* __restrict__ expand_bn,
                            const float* __restrict__ dw_w,
                            const float* __restrict__ dw_bn,
                            const float* __restrict__ id_w,
                            const float* __restrict__ id_bn,
                            const float* __restrict__ merge_bn,
                            const float* __restrict__ proj_w,
                            const float* __restrict__ proj_bn) {
    int tid = blockIdx.x * blockDim.x + threadIdx.x;
    int nth = gridDim.x * blockDim.x;

    for (int idx = tid; idx < 18432; idx += nth) {
        int q = idx & 3, lane = (idx >> 2) & 31, hl = (idx >> 7) & 1;
        int t = idx >> 8;
        int mi = t & 1; t >>= 1;
        int ki = t % 6; t /= 6;
        int wr = t & 1; int mt = t >> 1;
        int m = mt * 64 + wr * 32 + mi * 16 + (lane >> 2) + 8 * (q & 1);
        int k = ki * 16 + (lane & 3) * 2 + 8 * (q >> 1);
        float sc = expand_bn[m] * rsqrtf(expand_bn[3 * MIDC + m] + EPSBN);
        float w0 = expand_w[m * CINC + k] * sc;
        float w1 = expand_w[m * CINC + k + 1] * sc;
        float h0 = bf16hi(w0), h1 = bf16hi(w1);
        g_WexpF[idx] = hl ? packbf2(w0 - h0, w1 - h1) : packbf2(h0, h1);
    }
    for (int idx = tid; idx < 18432; idx += nth) {
        int q = idx & 3, lane = (idx >> 2) & 31, hl = (idx >> 7) & 1;
        int t = idx >> 8;
        int mi = t % 3; t /= 3;
        int ki = t % 3; t /= 3;
        int wr = t & 1; int chunk = t >> 1;
        int m = wr * 48 + mi * 16 + (lane >> 2) + 8 * (q & 1);
        int k = chunk * 48 + ki * 16 + (lane & 3) * 2 + 8 * (q >> 1);
        float sc = proj_bn[m] * rsqrtf(proj_bn[3 * COUTC + m] + EPSBN);
        float w0 = proj_w[m * MIDC + k] * sc;
        float w1 = proj_w[m * MIDC + k + 1] * sc;
        float h0 = bf16hi(w0), h1 = bf16hi(w1);
        g_WprojF[idx] = hl ? packbf2(w0 - h0, w1 - h1) : packbf2(h0, h1);
    }
    for (int o = tid; o < MIDC; o += nth) {
        float sc = expand_bn[o] * rsqrtf(expand_bn[3 * MIDC + o] + EPSBN);
        g_bexp[o] = expand_bn[MIDC + o] - expand_bn[2 * MIDC + o] * sc;
    }
    for (int c = tid; c < MIDC; c += nth) {
        float dsc = dw_bn[c] * rsqrtf(dw_bn[3 * MIDC + c] + EPSBN);
        float dsh = dw_bn[MIDC + c] - dw_bn[2 * MIDC + c] * dsc;
        float isc = id_bn[c] * rsqrtf(id_bn[3 * MIDC + c] + EPSBN);
        float ish = id_bn[MIDC + c] - id_bn[2 * MIDC + c] * isc;
        float msc = merge_bn[c] * rsqrtf(merge_bn[3 * MIDC + c] + EPSBN);
        float msh = merge_bn[MIDC + c] - merge_bn[2 * MIDC + c] * msc;
        #pragma unroll
        for (int k = 0; k < 9; k++) g_W9[c * 9 + k] = msc * dsc * dw_w[c * 9 + k];
        g_W9[c * 9 + 4] += msc * isc * id_w[c];
        g_T[c] = msc * (dsh + ish) + msh;
    }
    for (int o = tid; o < COUTC; o += nth) {
        float sc = proj_bn[o] * rsqrtf(proj_bn[3 * COUTC + o] + EPSBN);
        g_bproj[o] = proj_bn[COUTC + o] - proj_bn[2 * COUTC + o] * sc;
    }
}

// ---------------------------------------------------------------------------
// Expand 1x1 GEMM. 192(Mx3 passes) x 128(N); warp tile 32x32; bf16 k16;
// A via cp.async double buffer; B converted once at start.
// ---------------------------------------------------------------------------
__global__ void __launch_bounds__(256, 2) expand_gemm(const float* __restrict__ x) {
    extern __shared__ uint32_t smu[];
    uint32_t* As0 = smu;                    // EXP_A_U32
    uint32_t* As1 = smu + EXP_A_U32;
    uint32_t* Bh  = smu + 2 * EXP_A_U32;    // EXP_B_U32
    uint32_t* Bl  = Bh + EXP_B_U32;
    int b = blockIdx.z;
    int p0 = blockIdx.x * 128;
    int tid = threadIdx.x;
    int lane = tid & 31, w = tid >> 5;
    int wr = w >> 2, wc = w & 3;
    int g = lane >> 2, tg = lane & 3;
    const float* xb = x + (size_t)b * CINC * HWP;
    float* ob = g_mid + (size_t)b * MIDC * HWP;

    // Prefetch A(0) while converting B
    {
        const uint4* src = (const uint4*)g_WexpF;
        #pragma unroll
        for (int j = 0; j < 6; j++)
            cpa16(smaddr(As0) + (tid + j * 256) * 16, src + tid + j * 256, true);
        cpa_commit();
    }
    // Convert B: x fp32 -> packed bf16x2 hi/lo k-pairs
    #pragma unroll
    for (int j = 0; j < 6; j++) {
        int v = tid + j * 256;
        int k2 = v >> 5, c4 = (v & 31) << 2;
        int p = p0 + c4;
        float4 r0 = make_float4(0.f, 0.f, 0.f, 0.f), r1 = r0;
        if (p < HWP) {
            r0 = *(const float4*)&xb[(size_t)(2 * k2) * HWP + p];
            r1 = *(const float4*)&xb[(size_t)(2 * k2 + 1) * HWP + p];
        }
        float e0[4] = {r0.x, r0.y, r0.z, r0.w};
        float e1[4] = {r1.x, r1.y, r1.z, r1.w};
        uint32_t hh[4], ll[4];
        #pragma unroll
        for (int i = 0; i < 4; i++) {
            float h0 = bf16hi(e0[i]), h1 = bf16hi(e1[i]);
            hh[i] = packbf2(h0, h1);
            ll[i] = packbf2(e0[i] - h0, e1[i] - h1);
        }
        *(uint4*)&Bh[k2 * BSS + c4] = make_uint4(hh[0], hh[1], hh[2], hh[3]);
        *(uint4*)&Bl[k2 * BSS + c4] = make_uint4(ll[0], ll[1], ll[2], ll[3]);
    }

    for (int mt = 0; mt < 3; mt++) {
        uint32_t* Acur = (mt & 1) ? As1 : As0;
        if (mt < 2) {
            uint32_t* Anext = (mt & 1) ? As0 : As1;
            const uint4* src = ((const uint4*)g_WexpF) + (mt + 1) * (EXP_A_U32 / 4);
            #pragma unroll
            for (int j = 0; j < 6; j++)
                cpa16(smaddr(Anext) + (tid + j * 256) * 16, src + tid + j * 256, true);
            cpa_commit();
            cpa_wait<1>();
        } else {
            cpa_wait<0>();
        }
        __syncthreads();

        float acc[2][4][4] = {};
        #pragma unroll
        for (int ki = 0; ki < 6; ki++) {
            uint4 ah[2], al[2];
            #pragma unroll
            for (int mi = 0; mi < 2; mi++) {
                int off = (((wr * 6 + ki) * 2 + mi) * 2) * 128 + lane * 4;
                ah[mi] = *(const uint4*)&Acur[off];
                al[mi] = *(const uint4*)&Acur[off + 128];
            }
            uint32_t bh[4][2], bl[4][2];
            int kr2 = ki * 8;
            #pragma unroll
            for (int ni = 0; ni < 4; ni++) {
                int nb = wc * 32 + ni * 8 + g;
                bh[ni][0] = Bh[(kr2 + tg) * BSS + nb];
                bh[ni][1] = Bh[(kr2 + tg + 4) * BSS + nb];
                bl[ni][0] = Bl[(kr2 + tg) * BSS + nb];
                bl[ni][1] = Bl[(kr2 + tg + 4) * BSS + nb];
            }
            #pragma unroll
            for (int mi = 0; mi < 2; mi++)
                #pragma unroll
                for (int ni = 0; ni < 4; ni++) {
                    mma16(acc[mi][ni], (const uint32_t*)&ah[mi], bh[ni]);
                    mma16(acc[mi][ni], (const uint32_t*)&al[mi], bh[ni]);
                    mma16(acc[mi][ni], (const uint32_t*)&ah[mi], bl[ni]);
                }
        }

        int m0 = mt * 64;
        #pragma unroll
        for (int mi = 0; mi < 2; mi++) {
            int o = m0 + wr * 32 + mi * 16 + g;
            float b0 = g_bexp[o], b1 = g_bexp[o + 8];
            #pragma unroll
            for (int ni = 0; ni < 4; ni++) {
                int p = p0 + wc * 32 + ni * 8 + tg * 2;
                if (p < HWP) {
                    float2 r0 = make_float2(silu_f(acc[mi][ni][0] + b0),
                                            silu_f(acc[mi][ni][1] + b0));
                    *(float2*)&ob[(size_t)o * HWP + p] = r0;
                    float2 r1 = make_float2(silu_f(acc[mi][ni][2] + b1),
                                            silu_f(acc[mi][ni][3] + b1));
                    *(float2*)&ob[(size_t)(o + 8) * HWP + p] = r1;
                }
            }
        }
        __syncthreads();
    }
}

// ---------------------------------------------------------------------------
// dwmerge: shift+shuffle+dw3x3+id+BNs+SiLU+sums; block = (b, channel pair).
// Emits packed bf16 hi/lo channel-pair words in proj's B layout.
// ---------------------------------------------------------------------------
#define SPS 60
__global__ void __launch_bounds__(256) dwmerge_kernel() {
    __shared__ float sps[2][58 * SPS];
    __shared__ float sred[16];
    int bc = blockIdx.x;
    int b = bc / 96, k2 = bc - b * 96;
    int tid = threadIdx.x;

    float w9[2][9], T[2];
    #pragma unroll
    for (int ch = 0; ch < 2; ch++) {
        int c = 2 * k2 + ch;
        int cpre = (c & 3) * 48 + (c >> 2);
        int gg = c & 3;
        int oy = (gg == 0) ? -1 : (gg == 2) ? 1 : 0;
        int ox = (gg == 1) ? -1 : (gg == 3) ? 1 : 0;
        const float* plane = g_mid + ((size_t)b * MIDC + cpre) * HWP;
        for (int idx = tid; idx < 58 * 58; idx += 256) {
            int r = idx / 58, cx = idx - r * 58;
            int hp = r - 1, wp = cx - 1;
            int hs = hp + oy, ws = wp + ox;
            bool ok = (unsigned)hp < 56u && (unsigned)wp < 56u &&
                      (unsigned)hs < 56u && (unsigned)ws < 56u;
            sps[ch][r * SPS + cx] = ok ? plane[hs * 56 + ws] : 0.f;
        }
        #pragma unroll
        for (int k = 0; k < 9; k++) w9[ch][k] = g_W9[c * 9 + k];
        T[ch] = g_T[c];
    }
    __syncthreads();

    uint32_t* oH = g_mergedH + ((size_t)b * 96 + k2) * HWP;
    uint32_t* oL = g_mergedL + ((size_t)b * 96 + k2) * HWP;
    int wid = tid >> 5, lane = tid & 31;
    float ls0 = 0.f, ls1 = 0.f;
    for (int r = wid; r < 56; r += 8) {
        const float* b0p = &sps[0][(r + 1) * SPS + 1];
        const float* b1p = &sps[1][(r + 1) * SPS + 1];
        #pragma unroll
        for (int seg = 0; seg < 2; seg++) {
            int cc = lane + seg * 32;
            if (seg == 0 || lane < 24) {
                float a0 = 0.f, a1 = 0.f;
                #pragma unroll
                for (int dy = -1; dy <= 1; dy++)
                    #pragma unroll
                    for (int dx = -1; dx <= 1; dx++) {
                        float wA = w9[0][(dy + 1) * 3 + dx + 1];
                        float wB = w9[1][(dy + 1) * 3 + dx + 1];
                        a0 += wA * b0p[dy * SPS + cc + dx];
                        a1 += wB * b1p[dy * SPS + cc + dx];
                    }
                float s0 = silu_f(a0 + T[0]);
                float s1 = silu_f(a1 + T[1]);
                float h0 = bf16hi(s0), h1 = bf16hi(s1);
                oH[r * 56 + cc] = packbf2(h0, h1);
                oL[r * 56 + cc] = packbf2(s0 - h0, s1 - h1);
                ls0 += s0;
                ls1 += s1;
            }
        }
    }
    #pragma unroll
    for (int o = 16; o > 0; o >>= 1) {
        ls0 += __shfl_down_sync(0xffffffffu, ls0, o);
        ls1 += __shfl_down_sync(0xffffffffu, ls1, o);
    }
    if (lane == 0) { sred[wid] = ls0; sred[8 + wid] = ls1; }
    __syncthreads();
    if (tid < 16) {
        float v = sred[tid];
        #pragma unroll
        for (int o = 4; o > 0; o >>= 1) v += __shfl_down_sync(0xffffu, v, o);
        if (tid == 0) g_sums[b * 192 + 2 * k2] = v;
        if (tid == 8) g_sums[b * 192 + 2 * k2 + 1] = v;
    }
}

// ---------------------------------------------------------------------------
// Project 1x1 GEMM. M=96 x N=128; 4 k-chunks of 48, cp.async pipelined B;
// SE folded into A with full hi/lo resplit; BN+residual+SiLU epilogue.
// ---------------------------------------------------------------------------
__global__ void __launch_bounds__(256, 2) proj_gemm(const float* __restrict__ x,
                                                    const float* __restrict__ red_w,
                                                    const float* __restrict__ red_b,
                                                    const float* __restrict__ exp_w,
                                                    const float* __restrict__ exp_b,
                                                    float* __restrict__ out) {
    extern __shared__ uint32_t smu[];
    uint32_t* As0 = smu;                        // PROJ_A_U32
    uint32_t* As1 = smu + PROJ_A_U32;
    uint32_t* Bst = smu + 2 * PROJ_A_U32;       // 2 stages x 2 planes x PROJ_B_U32
    __shared__ float s_se[192];
    __shared__ float smean[192];
    __shared__ float sredu[24];

    int b = blockIdx.z;
    int p0 = blockIdx.x * 128;
    int tid = threadIdx.x;
    int lane = tid & 31, w = tid >> 5;
    int wr = w >> 2, wc = w & 3;
    int g = lane >> 2, tg = lane & 3;
    const uint32_t* mH = g_mergedH + (size_t)b * 96 * HWP;
    const uint32_t* mL = g_mergedL + (size_t)b * 96 * HWP;

    // Prefetch B chunk 0 (overlaps SE compute)
    auto cp_chunk = [&](int c, int stage) {
        uint32_t dst = smaddr(Bst) + stage * 2 * PROJ_B_U32 * 4;
        const uint4* sH = (const uint4*)(mH + (size_t)(c * 24) * HWP);
        const uint4* sL = (const uint4*)(mL + (size_t)(c * 24) * HWP);
        #pragma unroll
        for (int j = 0; j < 3; j++) {
            int v = tid + j * 256;
            int r = v >> 5, c4 = (v & 31);
            int p = p0 + c4 * 4;
            bool ok = p < HWP;
            size_t so = (size_t)r * (HWP / 4) + (p0 >> 2) + c4;
            uint32_t d = dst + (r * BSS + c4 * 4) * 4;
            cpa16(d, sH + (ok ? so : 0), ok);
            cpa16(d + PROJ_B_U32 * 4, sL + (ok ? so : 0), ok);
        }
        cpa_commit();
    };
    cp_chunk(0, 0);

    // SE gating
    if (tid < 192) smean[tid] = g_sums[b * 192 + tid] * (1.f / 3136.f);
    __syncthreads();
    if (tid < 24) {
        int gq = tid >> 1;
        float a = red_b[tid];
        #pragma unroll
        for (int i = 0; i < 16; i++) a += red_w[tid * 16 + i] * smean[gq * 16 + i];
        sredu[tid] = fmaxf(a, 0.f);
    }
    __syncthreads();
    if (tid < 192) {
        int gq = tid >> 4;
        float v = exp_w[tid * 2] * sredu[gq * 2] + exp_w[tid * 2 + 1] * sredu[gq * 2 + 1]
                + exp_b[tid];
        s_se[tid] = 1.f / (1.f + __expf(-v));
    }
    __syncthreads();  // s_se ready for A scaling

    // A chunk load + SE scale + hi/lo resplit
    auto load_A = [&](int c, uint32_t* dst) {
        const uint4* src = ((const uint4*)g_WprojF) + c * (PROJ_A_U32 / 4);
        for (int i = tid; i < 576; i += 256) {
            int grp = i >> 5, li = i & 31;
            int ki = (grp / 3) % 3;
            uint4 H = src[grp * 64 + li];
            uint4 L = src[grp * 64 + li + 32];
            int k2a = c * 24 + ki * 8 + (li & 3);
            float se0 = s_se[2 * k2a], se1 = s_se[2 * k2a + 1];
            float se2 = s_se[2 * k2a + 8], se3 = s_se[2 * k2a + 9];
            uint32_t hu[4] = {H.x, H.y, H.z, H.w};
            uint32_t lu[4] = {L.x, L.y, L.z, L.w};
            uint32_t nh[4], nl[4];
            #pragma unroll
            for (int q = 0; q < 4; q++) {
                float sA = (q < 2) ? se0 : se2;
                float sB = (q < 2) ? se1 : se3;
                float2 hf = unpackbf2(hu[q]);
                float2 lf = unpackbf2(lu[q]);
                float v0 = (hf.x + lf.x) * sA;
                float v1 = (hf.y + lf.y) * sB;
                float h0 = bf16hi(v0), h1 = bf16hi(v1);
                nh[q] = packbf2(h0, h1);
                nl[q] = packbf2(v0 - h0, v1 - h1);
            }
            *(uint4*)&dst[(grp * 64 + li) * 4] = make_uint4(nh[0], nh[1], nh[2], nh[3]);
            *(uint4*)&dst[(grp * 64 + li + 32) * 4] = make_uint4(nl[0], nl[1], nl[2], nl[3]);
        }
    };
    load_A(0, As0);

    float acc[3][4][4] = {};

    for (int c = 0; c < 4; c++) {
        uint32_t* Acur = (c & 1) ? As1 : As0;
        uint32_t* BhS = Bst + (c & 1) * 2 * PROJ_B_U32;
        uint32_t* BlS = BhS + PROJ_B_U32;
        if (c < 3) {
            cp_chunk(c + 1, (c + 1) & 1);
            load_A(c + 1, (c & 1) ? As0 : As1);
            cpa_wait<1>();
        } else {
            cpa_wait<0>();
        }
        __syncthreads();

        #pragma unroll
        for (int ki = 0; ki < 3; ki++) {
            uint4 ah[3], al[3];
            #pragma unroll
            for (int mi = 0; mi < 3; mi++) {
                int off = ((wr * 3 + ki) * 3 + mi) * 256 + lane * 4;
                ah[mi] = *(const uint4*)&Acur[off];
                al[mi] = *(const uint4*)&Acur[off + 128];
            }
            uint32_t bh[4][2], bl[4][2];
            int kr2 = ki * 8;
            #pragma unroll
            for (int ni = 0; ni < 4; ni++) {
                int nb = wc * 32 + ni * 8 + g;
                bh[ni][0] = BhS[(kr2 + tg) * BSS + nb];
                bh[ni][1] = BhS[(kr2 + tg + 4) * BSS + nb];
                bl[ni][0] = BlS[(kr2 + tg) * BSS + nb];
                bl[ni][1] = BlS[(kr2 + tg + 4) * BSS + nb];
            }
            #pragma unroll
            for (int mi = 0; mi < 3; mi++)
                #pragma unroll
                for (int ni = 0; ni < 4; ni++) {
                    mma16(acc[mi][ni], (const uint32_t*)&ah[mi], bh[ni]);
                    mma16(acc[mi][ni], (const uint32_t*)&al[mi], bh[ni]);
                    mma16(acc[mi][ni], (const uint32_t*)&ah[mi], bl[ni]);
                }
        }
        __syncthreads();
    }

    const float* xb = x + (size_t)b * COUTC * HWP;
    float* ob = out + (size_t)b * COUTC * HWP;
    #pragma unroll
    for (int mi = 0; mi < 3; mi++) {
        int o = wr * 48 + mi * 16 + g;
        float b0 = g_bproj[o], b1 = g_bproj[o + 8];
        #pragma unroll
        for (int ni = 0; ni < 4; ni++) {
            int p = p0 + wc * 32 + ni * 8 + tg * 2;
            if (p < HWP) {
                float2 x0 = *(const float2*)&xb[(size_t)o * HWP + p];
                float2 r0;
                r0.x = silu_f(acc[mi][ni][0] + b0 + x0.x);
                r0.y = silu_f(acc[mi][ni][1] + b0 + x0.y);
                *(float2*)&ob[(size_t)o * HWP + p] = r0;
                float2 x1 = *(const float2*)&xb[(size_t)(o + 8) * HWP + p];
                float2 r1;
                r1.x = silu_f(acc[mi][ni][2] + b1 + x1.x);
                r1.y = silu_f(acc[mi][ni][3] + b1 + x1.y);
                *(float2*)&ob[(size_t)(o + 8) * HWP + p] = r1;
            }
        }
    }
}

// ---------------------------------------------------------------------------
extern "C" void kernel_launch(void* const* d_in, const int* in_sizes, int n_in,
                              void* d_out, int out_size) {
    const float* x         = (const float*)d_in[0];
    const float* expand_w  = (const float*)d_in[1];
    const float* expand_bn = (const float*)d_in[2];
    const float* dw_w      = (const float*)d_in[3];
    const float* dw_bn     = (const float*)d_in[4];
    const float* id_w      = (const float*)d_in[5];
    const float* id_bn     = (const float*)d_in[6];
    const float* merge_bn  = (const float*)d_in[7];
    const float* se_red_w  = (const float*)d_in[8];
    const float* se_red_b  = (const float*)d_in[9];
    const float* se_exp_w  = (const float*)d_in[10];
    const float* se_exp_b  = (const float*)d_in[11];
    const float* proj_w    = (const float*)d_in[12];
    const float* proj_bn   = (const float*)d_in[13];
    float* out = (float*)d_out;

    cudaFuncSetAttribute(expand_gemm, cudaFuncAttributeMaxDynamicSharedMemorySize, EXP_SMEM);
    cudaFuncSetAttribute(proj_gemm,   cudaFuncAttributeMaxDynamicSharedMemorySize, PROJ_SMEM);

    prep_kernel<<<80, 256>>>(expand_w, expand_bn, dw_w, dw_bn, id_w, id_bn,
                             merge_bn, proj_w, proj_bn);
    expand_gemm<<<dim3(25, 1, BZ), 256, EXP_SMEM>>>(x);
    dwmerge_kernel<<<BZ * 96, 256>>>();
    proj_gemm<<<dim3(25, 1, BZ), 256, PROJ_SMEM>>>(x, se_red_w, se_red_b,
                                                   se_exp_w, se_exp_b, out);
}

// round 8
// speedup vs baseline: 2.1575x; 1.0610x over previous
#include <cuda_runtime.h>
#include <cuda_bf16.h>
#include <math.h>
#include <stdint.h>

#define BZ    64
#define CINC  96
#define COUTC 96
#define MIDC  192
#define HWP   3136
#define EPSBN 1e-5f

#define BSS 136                    // pair-row stride (u32): bank = 8*tg+g, conflict-free
#define EXP_A_U32   6144           // per-mt A chunk  [wr2][ki6][mi2][hl2][lane32][q4]
#define PROJ_A_U32  4608           // per-kchunk A    [wr2][ki3][mi3][hl2][lane32][q4]
#define EXP_B_U32   (48 * BSS)     // one plane (hi or lo), 48 pair-rows
#define PROJ_B_U32  (24 * BSS)     // one plane per chunk, 24 pair-rows
#define EXP_SMEM  ((2 * EXP_A_U32 + 2 * EXP_B_U32) * 4)      // 101376 B
#define PROJ_SMEM ((2 * PROJ_A_U32 + 4 * PROJ_B_U32) * 4)    // 89088 B

// Scratch (device globals: allowed; no cudaMalloc anywhere)
__device__ __align__(16) float    g_mid[(size_t)BZ * MIDC * HWP];
__device__ __align__(16) uint32_t g_mergedH[(size_t)BZ * 96 * HWP];  // packed bf16 (c,c+1) hi
__device__ __align__(16) uint32_t g_mergedL[(size_t)BZ * 96 * HWP];  // packed bf16 lo residual
__device__ float    g_sums[BZ * MIDC];
__device__ __align__(16) uint32_t g_WexpF[18432];   // [mt3][wr2][ki6][mi2][hl2][lane32][q4]
__device__ __align__(16) uint32_t g_WprojF[18432];  // [chunk4][wr2][ki3][mi3][hl2][lane32][q4]
__device__ __align__(16) uint32_t g_WprojSE[(size_t)BZ * 18432];  // per-batch SE-scaled resplit
__device__ float    g_bexp[MIDC];
__device__ float    g_W9[MIDC * 9];
__device__ float    g_T[MIDC];
__device__ float    g_bproj[COUTC];

__device__ __forceinline__ float silu_f(float v) { return v / (1.f + __expf(-v)); }

__device__ __forceinline__ uint32_t packbf2(float lo_elem, float hi_elem) {
    __nv_bfloat162 t = __floats2bfloat162_rn(lo_elem, hi_elem);  // .x = low 16 bits
    return *(uint32_t*)&t;
}
__device__ __forceinline__ float2 unpackbf2(uint32_t u) {
    __nv_bfloat162 t = *(__nv_bfloat162*)&u;
    return __bfloat1622float2(t);
}
__device__ __forceinline__ float bf16hi(float v) {
    return __bfloat162float(__float2bfloat16_rn(v));
}

__device__ __forceinline__ void mma16(float* c, const uint32_t* a, const uint32_t* b) {
    asm volatile(
        "mma.sync.aligned.m16n8k16.row.col.f32.bf16.bf16.f32 "
        "{%0,%1,%2,%3},{%4,%5,%6,%7},{%8,%9},{%0,%1,%2,%3};"
        : "+f"(c[0]), "+f"(c[1]), "+f"(c[2]), "+f"(c[3])
        : "r"(a[0]), "r"(a[1]), "r"(a[2]), "r"(a[3]), "r"(b[0]), "r"(b[1]));
}

__device__ __forceinline__ uint32_t smaddr(const void* p) {
    return (uint32_t)__cvta_generic_to_shared(p);
}
__device__ __forceinline__ void cpa16(uint32_t dst_s, const void* src, bool valid) {
    // NOTE: valid=false still WRITES 16 zero bytes to dst (zero-fill), use only
    // where zero-padding the destination is intended.
    int sz = valid ? 16 : 0;
    asm volatile("cp.async.cg.shared.global [%0], [%1], 16, %2;\n"
                 :: "r"(dst_s), "l"(src), "r"(sz));
}
__device__ __forceinline__ void cpa_commit() {
    asm volatile("cp.async.commit_group;\n");
}
template <int N>
__device__ __forceinline__ void cpa_wait() {
    asm volatile("cp.async.wait_group %0;\n" :: "n"(N));
}

// ---------------------------------------------------------------------------
// prep: fold BN; emit fragment-ordered packed-bf16 hi/lo weights.
// ---------------------------------------------------------------------------
__global__ void prep_kernel(const float* __restrict__ expand_w,
                            const float* __restrict__ expand_bn,
                            const float* __restrict__ dw_w,
                            const float* __restrict__ dw_bn,
                            const float* __restrict__ id_w,
                            const float* __restrict__ id_bn,
                            const float* __restrict__ merge_bn,
                            const float* __restrict__ proj_w,
                            const float* __restrict__ proj_bn) {
    int tid = blockIdx.x * blockDim.x + threadIdx.x;
    int nth = gridDim.x * blockDim.x;

    for (int idx = tid; idx < 18432; idx += nth) {
        int q = idx & 3, lane = (idx >> 2) & 31, hl = (idx >> 7) & 1;
        int t = idx >> 8;
        int mi = t & 1; t >>= 1;
        int ki = t % 6; t /= 6;
        int wr = t & 1; t >>= 1;
        int mt = t;
        int m = mt * 64 + wr * 32 + mi * 16 + (lane >> 2) + 8 * (q & 1);
        int k = ki * 16 + (lane & 3) * 2 + 8 * (q >> 1);
        float sc = expand_bn[m] * rsqrtf(expand_bn[3 * MIDC + m] + EPSBN);
        float w0 = expand_w[m * CINC + k] * sc;
        float w1 = expand_w[m * CINC + k + 1] * sc;
        float h0 = bf16hi(w0), h1 = bf16hi(w1);
        g_WexpF[idx] = hl ? packbf2(w0 - h0, w1 - h1) : packbf2(h0, h1);
    }
    for (int idx = tid; idx < 18432; idx += nth) {
        int q = idx & 3, lane = (idx >> 2) & 31, hl = (idx >> 7) & 1;
        int t = idx >> 8;
        int mi = t % 3; t /= 3;
        int ki = t % 3; t /= 3;
        int wr = t & 1; int chunk = t >> 1;
        int m = wr * 48 + mi * 16 + (lane >> 2) + 8 * (q & 1);
        int k = chunk * 48 + ki * 16 + (lane & 3) * 2 + 8 * (q >> 1);
        float sc = proj_bn[m] * rsqrtf(proj_bn[3 * COUTC + m] + EPSBN);
        float w0 = proj_w[m * MIDC + k] * sc;
        float w1 = proj_w[m * MIDC + k + 1] * sc;
        float h0 = bf16hi(w0), h1 = bf16hi(w1);
        g_WprojF[idx] = hl ? packbf2(w0 - h0, w1 - h1) : packbf2(h0, h1);
    }
    for (int o = tid; o < MIDC; o += nth) {
        float sc = expand_bn[o] * rsqrtf(expand_bn[3 * MIDC + o] + EPSBN);
        g_bexp[o] = expand_bn[MIDC + o] - expand_bn[2 * MIDC + o] * sc;
    }
    for (int c = tid; c < MIDC; c += nth) {
        float dsc = dw_bn[c] * rsqrtf(dw_bn[3 * MIDC + c] + EPSBN);
        float dsh = dw_bn[MIDC + c] - dw_bn[2 * MIDC + c] * dsc;
        float isc = id_bn[c] * rsqrtf(id_bn[3 * MIDC + c] + EPSBN);
        float ish = id_bn[MIDC + c] - id_bn[2 * MIDC + c] * isc;
        float msc = merge_bn[c] * rsqrtf(merge_bn[3 * MIDC + c] + EPSBN);
        float msh = merge_bn[MIDC + c] - merge_bn[2 * MIDC + c] * msc;
        #pragma unroll
        for (int k = 0; k < 9; k++) g_W9[c * 9 + k] = msc * dsc * dw_w[c * 9 + k];
        g_W9[c * 9 + 4] += msc * isc * id_w[c];
        g_T[c] = msc * (dsh + ish) + msh;
    }
    for (int o = tid; o < COUTC; o += nth) {
        float sc = proj_bn[o] * rsqrtf(proj_bn[3 * COUTC + o] + EPSBN);
        g_bproj[o] = proj_bn[COUTC + o] - proj_bn[2 * COUTC + o] * sc;
    }
}

// ---------------------------------------------------------------------------
// Expand 1x1 GEMM. 192(Mx3 passes) x 128(N); warp tile 32x32; bf16 k16;
// A via cp.async double buffer; B converted once at start.
// ---------------------------------------------------------------------------
__global__ void __launch_bounds__(256, 2) expand_gemm(const float* __restrict__ x) {
    extern __shared__ uint32_t smu[];
    uint32_t* As0 = smu;                    // EXP_A_U32
    uint32_t* As1 = smu + EXP_A_U32;
    uint32_t* Bh  = smu + 2 * EXP_A_U32;    // EXP_B_U32
    uint32_t* Bl  = Bh + EXP_B_U32;
    int b = blockIdx.z;
    int p0 = blockIdx.x * 128;
    int tid = threadIdx.x;
    int lane = tid & 31, w = tid >> 5;
    int wr = w >> 2, wc = w & 3;
    int g = lane >> 2, tg = lane & 3;
    const float* xb = x + (size_t)b * CINC * HWP;
    float* ob = g_mid + (size_t)b * MIDC * HWP;

    {
        const uint4* src = (const uint4*)g_WexpF;
        #pragma unroll
        for (int j = 0; j < 6; j++)   // 1536 = 6*256 exact
            cpa16(smaddr(As0) + (tid + j * 256) * 16, src + tid + j * 256, true);
        cpa_commit();
    }
    #pragma unroll
    for (int j = 0; j < 6; j++) {
        int v = tid + j * 256;
        int k2 = v >> 5, c4 = (v & 31) << 2;
        int p = p0 + c4;
        float4 r0 = make_float4(0.f, 0.f, 0.f, 0.f), r1 = r0;
        if (p < HWP) {
            r0 = *(const float4*)&xb[(size_t)(2 * k2) * HWP + p];
            r1 = *(const float4*)&xb[(size_t)(2 * k2 + 1) * HWP + p];
        }
        float e0[4] = {r0.x, r0.y, r0.z, r0.w};
        float e1[4] = {r1.x, r1.y, r1.z, r1.w};
        uint32_t hh[4], ll[4];
        #pragma unroll
        for (int i = 0; i < 4; i++) {
            float h0 = bf16hi(e0[i]), h1 = bf16hi(e1[i]);
            hh[i] = packbf2(h0, h1);
            ll[i] = packbf2(e0[i] - h0, e1[i] - h1);
        }
        *(uint4*)&Bh[k2 * BSS + c4] = make_uint4(hh[0], hh[1], hh[2], hh[3]);
        *(uint4*)&Bl[k2 * BSS + c4] = make_uint4(ll[0], ll[1], ll[2], ll[3]);
    }

    for (int mt = 0; mt < 3; mt++) {
        uint32_t* Acur = (mt & 1) ? As1 : As0;
        if (mt < 2) {
            uint32_t* Anext = (mt & 1) ? As0 : As1;
            const uint4* src = ((const uint4*)g_WexpF) + (mt + 1) * (EXP_A_U32 / 4);
            #pragma unroll
            for (int j = 0; j < 6; j++)
                cpa16(smaddr(Anext) + (tid + j * 256) * 16, src + tid + j * 256, true);
            cpa_commit();
            cpa_wait<1>();
        } else {
            cpa_wait<0>();
        }
        __syncthreads();

        float acc[2][4][4] = {};
        #pragma unroll
        for (int ki = 0; ki < 6; ki++) {
            uint4 ah[2], al[2];
            #pragma unroll
            for (int mi = 0; mi < 2; mi++) {
                int off = (((wr * 6 + ki) * 2 + mi) * 2) * 128 + lane * 4;
                ah[mi] = *(const uint4*)&Acur[off];
                al[mi] = *(const uint4*)&Acur[off + 128];
            }
            uint32_t bh[4][2], bl[4][2];
            int kr2 = ki * 8;
            #pragma unroll
            for (int ni = 0; ni < 4; ni++) {
                int nb = wc * 32 + ni * 8 + g;
                bh[ni][0] = Bh[(kr2 + tg) * BSS + nb];
                bh[ni][1] = Bh[(kr2 + tg + 4) * BSS + nb];
                bl[ni][0] = Bl[(kr2 + tg) * BSS + nb];
                bl[ni][1] = Bl[(kr2 + tg + 4) * BSS + nb];
            }
            #pragma unroll
            for (int mi = 0; mi < 2; mi++)
                #pragma unroll
                for (int ni = 0; ni < 4; ni++) {
                    mma16(acc[mi][ni], (const uint32_t*)&ah[mi], bh[ni]);
                    mma16(acc[mi][ni], (const uint32_t*)&al[mi], bh[ni]);
                    mma16(acc[mi][ni], (const uint32_t*)&ah[mi], bl[ni]);
                }
        }

        int m0 = mt * 64;
        #pragma unroll
        for (int mi = 0; mi < 2; mi++) {
            int o = m0 + wr * 32 + mi * 16 + g;
            float b0 = g_bexp[o], b1 = g_bexp[o + 8];
            #pragma unroll
            for (int ni = 0; ni < 4; ni++) {
                int p = p0 + wc * 32 + ni * 8 + tg * 2;
                if (p < HWP) {
                    float2 r0 = make_float2(silu_f(acc[mi][ni][0] + b0),
                                            silu_f(acc[mi][ni][1] + b0));
                    *(float2*)&ob[(size_t)o * HWP + p] = r0;
                    float2 r1 = make_float2(silu_f(acc[mi][ni][2] + b1),
                                            silu_f(acc[mi][ni][3] + b1));
                    *(float2*)&ob[(size_t)(o + 8) * HWP + p] = r1;
                }
            }
        }
        __syncthreads();
    }
}

// ---------------------------------------------------------------------------
// dwmerge: shift+shuffle+dw3x3+id+BNs+SiLU+sums; block = (b, channel pair).
// Emits packed bf16 hi/lo channel-pair words in proj's B layout.
// ---------------------------------------------------------------------------
#define SPS 60
__global__ void __launch_bounds__(256) dwmerge_kernel() {
    __shared__ float sps[2][58 * SPS];
    __shared__ float sred[16];
    int bc = blockIdx.x;
    int b = bc / 96, k2 = bc - b * 96;
    int tid = threadIdx.x;

    float w9[2][9], T[2];
    #pragma unroll
    for (int ch = 0; ch < 2; ch++) {
        int c = 2 * k2 + ch;
        int cpre = (c & 3) * 48 + (c >> 2);
        int gg = c & 3;
        int oy = (gg == 0) ? -1 : (gg == 2) ? 1 : 0;
        int ox = (gg == 1) ? -1 : (gg == 3) ? 1 : 0;
        const float* plane = g_mid + ((size_t)b * MIDC + cpre) * HWP;
        for (int idx = tid; idx < 58 * 58; idx += 256) {
            int r = idx / 58, cx = idx - r * 58;
            int hp = r - 1, wp = cx - 1;
            int hs = hp + oy, ws = wp + ox;
            bool ok = (unsigned)hp < 56u && (unsigned)wp < 56u &&
                      (unsigned)hs < 56u && (unsigned)ws < 56u;
            sps[ch][r * SPS + cx] = ok ? plane[hs * 56 + ws] : 0.f;
        }
        #pragma unroll
        for (int k = 0; k < 9; k++) w9[ch][k] = g_W9[c * 9 + k];
        T[ch] = g_T[c];
    }
    __syncthreads();

    uint32_t* oH = g_mergedH + ((size_t)b * 96 + k2) * HWP;
    uint32_t* oL = g_mergedL + ((size_t)b * 96 + k2) * HWP;
    int wid = tid >> 5, lane = tid & 31;
    float ls0 = 0.f, ls1 = 0.f;
    for (int r = wid; r < 56; r += 8) {
        const float* b0p = &sps[0][(r + 1) * SPS + 1];
        const float* b1p = &sps[1][(r + 1) * SPS + 1];
        #pragma unroll
        for (int seg = 0; seg < 2; seg++) {
            int cc = lane + seg * 32;
            if (seg == 0 || lane < 24) {
                float a0 = 0.f, a1 = 0.f;
                #pragma unroll
                for (int dy = -1; dy <= 1; dy++)
                    #pragma unroll
                    for (int dx = -1; dx <= 1; dx++) {
                        float wA = w9[0][(dy + 1) * 3 + dx + 1];
                        float wB = w9[1][(dy + 1) * 3 + dx + 1];
                        a0 += wA * b0p[dy * SPS + cc + dx];
                        a1 += wB * b1p[dy * SPS + cc + dx];
                    }
                float s0 = silu_f(a0 + T[0]);
                float s1 = silu_f(a1 + T[1]);
                float h0 = bf16hi(s0), h1 = bf16hi(s1);
                oH[r * 56 + cc] = packbf2(h0, h1);
                oL[r * 56 + cc] = packbf2(s0 - h0, s1 - h1);
                ls0 += s0;
                ls1 += s1;
            }
        }
    }
    #pragma unroll
    for (int o = 16; o > 0; o >>= 1) {
        ls0 += __shfl_down_sync(0xffffffffu, ls0, o);
        ls1 += __shfl_down_sync(0xffffffffu, ls1, o);
    }
    if (lane == 0) { sred[wid] = ls0; sred[8 + wid] = ls1; }
    __syncthreads();
    if (tid < 16) {
        float v = sred[tid];
        #pragma unroll
        for (int o = 4; o > 0; o >>= 1) v += __shfl_down_sync(0xffffu, v, o);
        if (tid == 0) g_sums[b * 192 + 2 * k2] = v;
        if (tid == 8) g_sums[b * 192 + 2 * k2 + 1] = v;
    }
}

// ---------------------------------------------------------------------------
// SE gating + per-batch scaled/resplit proj weights (hoisted out of proj_gemm).
// One block per batch.
// ---------------------------------------------------------------------------
__global__ void __launch_bounds__(256) se_scale_kernel(const float* __restrict__ red_w,
                                                       const float* __restrict__ red_b,
                                                       const float* __restrict__ exp_w,
                                                       const float* __restrict__ exp_b) {
    __shared__ float smean[192];
    __shared__ float sredu[24];
    __shared__ float s_se[192];
    int b = blockIdx.x, tid = threadIdx.x;

    if (tid < 192) smean[tid] = g_sums[b * 192 + tid] * (1.f / 3136.f);
    __syncthreads();
    if (tid < 24) {
        int gq = tid >> 1;
        float a = red_b[tid];
        #pragma unroll
        for (int i = 0; i < 16; i++) a += red_w[tid * 16 + i] * smean[gq * 16 + i];
        sredu[tid] = fmaxf(a, 0.f);
    }
    __syncthreads();
    if (tid < 192) {
        int gq = tid >> 4;
        float v = exp_w[tid * 2] * sredu[gq * 2] + exp_w[tid * 2 + 1] * sredu[gq * 2 + 1]
                + exp_b[tid];
        s_se[tid] = 1.f / (1.f + __expf(-v));
    }
    __syncthreads();

    uint32_t* dstb = g_WprojSE + (size_t)b * 18432;
    for (int cc = 0; cc < 4; cc++) {
        const uint4* src = ((const uint4*)g_WprojF) + cc * (PROJ_A_U32 / 4);
        uint4* dst = ((uint4*)dstb) + cc * (PROJ_A_U32 / 4);
        for (int i = tid; i < 576; i += 256) {
            int grp = i >> 5, li = i & 31;
            int ki = (grp / 3) % 3;
            uint4 H = src[grp * 64 + li];
            uint4 L = src[grp * 64 + li + 32];
            int k2a = cc * 24 + ki * 8 + (li & 3);
            float se0 = s_se[2 * k2a], se1 = s_se[2 * k2a + 1];
            float se2 = s_se[2 * k2a + 8], se3 = s_se[2 * k2a + 9];
            uint32_t hu[4] = {H.x, H.y, H.z, H.w};
            uint32_t lu[4] = {L.x, L.y, L.z, L.w};
            uint32_t nh[4], nl[4];
            #pragma unroll
            for (int q = 0; q < 4; q++) {
                float sA = (q < 2) ? se0 : se2;
                float sB = (q < 2) ? se1 : se3;
                float2 hf = unpackbf2(hu[q]);
                float2 lf = unpackbf2(lu[q]);
                float v0 = (hf.x + lf.x) * sA;
                float v1 = (hf.y + lf.y) * sB;
                float h0 = bf16hi(v0), h1 = bf16hi(v1);
                nh[q] = packbf2(h0, h1);
                nl[q] = packbf2(v0 - h0, v1 - h1);
            }
            dst[grp * 64 + li]      = make_uint4(nh[0], nh[1], nh[2], nh[3]);
            dst[grp * 64 + li + 32] = make_uint4(nl[0], nl[1], nl[2], nl[3]);
        }
    }
}

// ---------------------------------------------------------------------------
// Project 1x1 GEMM. M=96 x N=128; 4 k-chunks of 48; BOTH A and B raw
// cp.async double-buffered (A pre-scaled by SE). Pure copy+MMA mainloop.
// ---------------------------------------------------------------------------
__global__ void __launch_bounds__(256, 2) proj_gemm(const float* __restrict__ x,
                                                    float* __restrict__ out) {
    extern __shared__ uint32_t smu[];
    uint32_t* As0 = smu;                        // PROJ_A_U32
    uint32_t* As1 = smu + PROJ_A_U32;
    uint32_t* Bst = smu + 2 * PROJ_A_U32;       // 2 stages x 2 planes x PROJ_B_U32

    int b = blockIdx.z;
    int p0 = blockIdx.x * 128;
    int tid = threadIdx.x;
    int lane = tid & 31, w = tid >> 5;
    int wr = w >> 2, wc = w & 3;
    int g = lane >> 2, tg = lane & 3;
    const uint32_t* mH = g_mergedH + (size_t)b * 96 * HWP;
    const uint32_t* mL = g_mergedL + (size_t)b * 96 * HWP;
    const uint4* Asrc = (const uint4*)(g_WprojSE + (size_t)b * 18432);

    auto cp_stage = [&](int c) {
        int stage = c & 1;
        // B chunk: 24 pair-rows x 32 uint4  = 768 tasks = 3*256 exact
        uint32_t dstB = smaddr(Bst) + stage * 2 * PROJ_B_U32 * 4;
        const uint4* sH = (const uint4*)(mH + (size_t)(c * 24) * HWP);
        const uint4* sL = (const uint4*)(mL + (size_t)(c * 24) * HWP);
        #pragma unroll
        for (int j = 0; j < 3; j++) {
            int v = tid + j * 256;
            int r = v >> 5, c4 = (v & 31);
            int p = p0 + c4 * 4;
            bool ok = p < HWP;                  // zero-fill pad (intended)
            size_t so = (size_t)r * (HWP / 4) + (p0 >> 2) + c4;
            uint32_t d = dstB + (r * BSS + c4 * 4) * 4;
            cpa16(d, sH + (ok ? so : 0), ok);
            cpa16(d + PROJ_B_U32 * 4, sL + (ok ? so : 0), ok);
        }
        // A chunk (raw, pre-scaled): 1152 uint4 = 4*256 + 128 (EXACT — no overrun!)
        uint32_t dstA = smaddr(stage ? As1 : As0);
        const uint4* sA = Asrc + c * (PROJ_A_U32 / 4);
        #pragma unroll
        for (int j = 0; j < 4; j++) {
            int v = tid + j * 256;
            cpa16(dstA + v * 16, sA + v, true);
        }
        if (tid < 128) {
            int v = tid + 1024;
            cpa16(dstA + v * 16, sA + v, true);
        }
        cpa_commit();
    };
    cp_stage(0);

    float acc[3][4][4] = {};

    for (int c = 0; c < 4; c++) {
        uint32_t* Acur = (c & 1) ? As1 : As0;
        uint32_t* BhS = Bst + (c & 1) * 2 * PROJ_B_U32;
        uint32_t* BlS = BhS + PROJ_B_U32;
        if (c < 3) {
            cp_stage(c + 1);
            cpa_wait<1>();
        } else {
            cpa_wait<0>();
        }
        __syncthreads();

        #pragma unroll
        for (int ki = 0; ki < 3; ki++) {
            uint4 ah[3], al[3];
            #pragma unroll
            for (int mi = 0; mi < 3; mi++) {
                int off = ((wr * 3 + ki) * 3 + mi) * 256 + lane * 4;
                ah[mi] = *(const uint4*)&Acur[off];
                al[mi] = *(const uint4*)&Acur[off + 128];
            }
            uint32_t bh[4][2], bl[4][2];
            int kr2 = ki * 8;
            #pragma unroll
            for (int ni = 0; ni < 4; ni++) {
                int nb = wc * 32 + ni * 8 + g;
                bh[ni][0] = BhS[(kr2 + tg) * BSS + nb];
                bh[ni][1] = BhS[(kr2 + tg + 4) * BSS + nb];
                bl[ni][0] = BlS[(kr2 + tg) * BSS + nb];
                bl[ni][1] = BlS[(kr2 + tg + 4) * BSS + nb];
            }
            #pragma unroll
            for (int mi = 0; mi < 3; mi++)
                #pragma unroll
                for (int ni = 0; ni < 4; ni++) {
                    mma16(acc[mi][ni], (const uint32_t*)&ah[mi], bh[ni]);
                    mma16(acc[mi][ni], (const uint32_t*)&al[mi], bh[ni]);
                    mma16(acc[mi][ni], (const uint32_t*)&ah[mi], bl[ni]);
                }
        }
        __syncthreads();
    }

    const float* xb = x + (size_t)b * COUTC * HWP;
    float* ob = out + (size_t)b * COUTC * HWP;
    #pragma unroll
    for (int mi = 0; mi < 3; mi++) {
        int o = wr * 48 + mi * 16 + g;
        float b0 = g_bproj[o], b1 = g_bproj[o + 8];
        #pragma unroll
        for (int ni = 0; ni < 4; ni++) {
            int p = p0 + wc * 32 + ni * 8 + tg * 2;
            if (p < HWP) {
                float2 x0 = *(const float2*)&xb[(size_t)o * HWP + p];
                float2 r0;
                r0.x = silu_f(acc[mi][ni][0] + b0 + x0.x);
                r0.y = silu_f(acc[mi][ni][1] + b0 + x0.y);
                *(float2*)&ob[(size_t)o * HWP + p] = r0;
                float2 x1 = *(const float2*)&xb[(size_t)(o + 8) * HWP + p];
                float2 r1;
                r1.x = silu_f(acc[mi][ni][2] + b1 + x1.x);
                r1.y = silu_f(acc[mi][ni][3] + b1 + x1.y);
                *(float2*)&ob[(size_t)(o + 8) * HWP + p] = r1;
            }
        }
    }
}

// ---------------------------------------------------------------------------
extern "C" void kernel_launch(void* const* d_in, const int* in_sizes, int n_in,
                              void* d_out, int out_size) {
    const float* x         = (const float*)d_in[0];
    const float* expand_w  = (const float*)d_in[1];
    const float* expand_bn = (const float*)d_in[2];
    const float* dw_w      = (const float*)d_in[3];
    const float* dw_bn     = (const float*)d_in[4];
    const float* id_w      = (const float*)d_in[5];
    const float* id_bn     = (const float*)d_in[6];
    const float* merge_bn  = (const float*)d_in[7];
    const float* se_red_w  = (const float*)d_in[8];
    const float* se_red_b  = (const float*)d_in[9];
    const float* se_exp_w  = (const float*)d_in[10];
    const float* se_exp_b  = (const float*)d_in[11];
    const float* proj_w    = (const float*)d_in[12];
    const float* proj_bn   = (const float*)d_in[13];
    float* out = (float*)d_out;

    cudaFuncSetAttribute(expand_gemm, cudaFuncAttributeMaxDynamicSharedMemorySize, EXP_SMEM);
    cudaFuncSetAttribute(proj_gemm,   cudaFuncAttributeMaxDynamicSharedMemorySize, PROJ_SMEM);

    prep_kernel<<<80, 256>>>(expand_w, expand_bn, dw_w, dw_bn, id_w, id_bn,
                             merge_bn, proj_w, proj_bn);
    expand_gemm<<<dim3(25, 1, BZ), 256, EXP_SMEM>>>(x);
    dwmerge_kernel<<<BZ * 96, 256>>>();
    se_scale_kernel<<<BZ, 256>>>(se_red_w, se_red_b, se_exp_w, se_exp_b);
    proj_gemm<<<dim3(25, 1, BZ), 256, PROJ_SMEM>>>(x, out);
}

// round 9
// speedup vs baseline: 2.2229x; 1.0303x over previous
#include <cuda_runtime.h>
#include <cuda_bf16.h>
#include <math.h>
#include <stdint.h>

#define BZ    64
#define CINC  96
#define COUTC 96
#define MIDC  192
#define HWP   3136
#define EPSBN 1e-5f

#define BSS 136                    // pair-row stride (u32): bank = 8*tg+g, conflict-free
#define EXP_A_U32   6144           // per-mt A chunk  [wr2][ki6][mi2][hl2][lane32][q4]
#define PROJ_A_U32  4608           // per-kchunk A    [wr2][ki3][mi3][hl2][lane32][q4]
#define EXP_B_U32   (48 * BSS)     // one plane (hi or lo), 48 pair-rows
#define PROJ_B_U32  (24 * BSS)     // one plane per chunk, 24 pair-rows
#define EXP_SMEM  ((2 * EXP_A_U32 + 2 * EXP_B_U32) * 4)      // 101376 B
#define PROJ_SMEM ((2 * PROJ_A_U32 + 4 * PROJ_B_U32) * 4)    // 89088 B

// Scratch (device globals: allowed; no cudaMalloc anywhere)
__device__ __align__(16) float    g_mid[(size_t)BZ * MIDC * HWP];
__device__ __align__(16) uint32_t g_mergedH[(size_t)BZ * 96 * HWP];  // packed bf16 (c,c+1) hi
__device__ __align__(16) uint32_t g_mergedL[(size_t)BZ * 96 * HWP];  // packed bf16 lo residual
__device__ float    g_sums[BZ * MIDC];
__device__ __align__(16) uint32_t g_WexpF[18432];   // [mt3][wr2][ki6][mi2][hl2][lane32][q4]
__device__ __align__(16) uint32_t g_WprojF[18432];  // [chunk4][wr2][ki3][mi3][hl2][lane32][q4]
__device__ __align__(16) uint32_t g_WprojSE[(size_t)BZ * 18432];  // per-batch SE-scaled resplit
__device__ float    g_bexp[MIDC];
__device__ float    g_W9[MIDC * 9];
__device__ float    g_T[MIDC];
__device__ float    g_bproj[COUTC];

__device__ __forceinline__ float silu_f(float v) { return v / (1.f + __expf(-v)); }

__device__ __forceinline__ uint32_t packbf2(float lo_elem, float hi_elem) {
    __nv_bfloat162 t = __floats2bfloat162_rn(lo_elem, hi_elem);  // .x = low 16 bits
    return *(uint32_t*)&t;
}
__device__ __forceinline__ float2 unpackbf2(uint32_t u) {
    __nv_bfloat162 t = *(__nv_bfloat162*)&u;
    return __bfloat1622float2(t);
}
__device__ __forceinline__ float bf16hi(float v) {
    return __bfloat162float(__float2bfloat16_rn(v));
}

__device__ __forceinline__ void mma16(float* c, const uint32_t* a, const uint32_t* b) {
    asm volatile(
        "mma.sync.aligned.m16n8k16.row.col.f32.bf16.bf16.f32 "
        "{%0,%1,%2,%3},{%4,%5,%6,%7},{%8,%9},{%0,%1,%2,%3};"
        : "+f"(c[0]), "+f"(c[1]), "+f"(c[2]), "+f"(c[3])
        : "r"(a[0]), "r"(a[1]), "r"(a[2]), "r"(a[3]), "r"(b[0]), "r"(b[1]));
}

__device__ __forceinline__ uint32_t smaddr(const void* p) {
    return (uint32_t)__cvta_generic_to_shared(p);
}
__device__ __forceinline__ void cpa16(uint32_t dst_s, const void* src, bool valid) {
    // NOTE: valid=false still WRITES 16 zero bytes to dst (zero-fill), use only
    // where zero-padding the destination is intended.
    int sz = valid ? 16 : 0;
    asm volatile("cp.async.cg.shared.global [%0], [%1], 16, %2;\n"
                 :: "r"(dst_s), "l"(src), "r"(sz));
}
__device__ __forceinline__ void cpa_commit() {
    asm volatile("cp.async.commit_group;\n");
}
template <int N>
__device__ __forceinline__ void cpa_wait() {
    asm volatile("cp.async.wait_group %0;\n" :: "n"(N));
}

// ---------------------------------------------------------------------------
// prep: fold BN; emit fragment-ordered packed-bf16 hi/lo weights.
// ---------------------------------------------------------------------------
__global__ void prep_kernel(const float* __restrict__ expand_w,
                            const float* __restrict__ expand_bn,
                            const float* __restrict__ dw_w,
                            const float* __restrict__ dw_bn,
                            const float* __restrict__ id_w,
                            const float* __restrict__ id_bn,
                            const float* __restrict__ merge_bn,
                            const float* __restrict__ proj_w,
                            const float* __restrict__ proj_bn) {
    int tid = blockIdx.x * blockDim.x + threadIdx.x;
    int nth = gridDim.x * blockDim.x;

    for (int idx = tid; idx < 18432; idx += nth) {
        int q = idx & 3, lane = (idx >> 2) & 31, hl = (idx >> 7) & 1;
        int t = idx >> 8;
        int mi = t & 1; t >>= 1;
        int ki = t % 6; t /= 6;
        int wr = t & 1; t >>= 1;
        int mt = t;
        int m = mt * 64 + wr * 32 + mi * 16 + (lane >> 2) + 8 * (q & 1);
        int k = ki * 16 + (lane & 3) * 2 + 8 * (q >> 1);
        float sc = expand_bn[m] * rsqrtf(expand_bn[3 * MIDC + m] + EPSBN);
        float w0 = expand_w[m * CINC + k] * sc;
        float w1 = expand_w[m * CINC + k + 1] * sc;
        float h0 = bf16hi(w0), h1 = bf16hi(w1);
        g_WexpF[idx] = hl ? packbf2(w0 - h0, w1 - h1) : packbf2(h0, h1);
    }
    for (int idx = tid; idx < 18432; idx += nth) {
        int q = idx & 3, lane = (idx >> 2) & 31, hl = (idx >> 7) & 1;
        int t = idx >> 8;
        int mi = t % 3; t /= 3;
        int ki = t % 3; t /= 3;
        int wr = t & 1; int chunk = t >> 1;
        int m = wr * 48 + mi * 16 + (lane >> 2) + 8 * (q & 1);
        int k = chunk * 48 + ki * 16 + (lane & 3) * 2 + 8 * (q >> 1);
        float sc = proj_bn[m] * rsqrtf(proj_bn[3 * COUTC + m] + EPSBN);
        float w0 = proj_w[m * MIDC + k] * sc;
        float w1 = proj_w[m * MIDC + k + 1] * sc;
        float h0 = bf16hi(w0), h1 = bf16hi(w1);
        g_WprojF[idx] = hl ? packbf2(w0 - h0, w1 - h1) : packbf2(h0, h1);
    }
    for (int o = tid; o < MIDC; o += nth) {
        float sc = expand_bn[o] * rsqrtf(expand_bn[3 * MIDC + o] + EPSBN);
        g_bexp[o] = expand_bn[MIDC + o] - expand_bn[2 * MIDC + o] * sc;
    }
    for (int c = tid; c < MIDC; c += nth) {
        float dsc = dw_bn[c] * rsqrtf(dw_bn[3 * MIDC + c] + EPSBN);
        float dsh = dw_bn[MIDC + c] - dw_bn[2 * MIDC + c] * dsc;
        float isc = id_bn[c] * rsqrtf(id_bn[3 * MIDC + c] + EPSBN);
        float ish = id_bn[MIDC + c] - id_bn[2 * MIDC + c] * isc;
        float msc = merge_bn[c] * rsqrtf(merge_bn[3 * MIDC + c] + EPSBN);
        float msh = merge_bn[MIDC + c] - merge_bn[2 * MIDC + c] * msc;
        #pragma unroll
        for (int k = 0; k < 9; k++) g_W9[c * 9 + k] = msc * dsc * dw_w[c * 9 + k];
        g_W9[c * 9 + 4] += msc * isc * id_w[c];
        g_T[c] = msc * (dsh + ish) + msh;
    }
    for (int o = tid; o < COUTC; o += nth) {
        float sc = proj_bn[o] * rsqrtf(proj_bn[3 * COUTC + o] + EPSBN);
        g_bproj[o] = proj_bn[COUTC + o] - proj_bn[2 * COUTC + o] * sc;
    }
}

// ---------------------------------------------------------------------------
// Expand 1x1 GEMM. 192(Mx3 passes) x 128(N); warp tile 32x32; bf16 k16;
// A via cp.async double buffer; B converted once at start.
// ---------------------------------------------------------------------------
__global__ void __launch_bounds__(256, 2) expand_gemm(const float* __restrict__ x) {
    extern __shared__ uint32_t smu[];
    uint32_t* As0 = smu;                    // EXP_A_U32
    uint32_t* As1 = smu + EXP_A_U32;
    uint32_t* Bh  = smu + 2 * EXP_A_U32;    // EXP_B_U32
    uint32_t* Bl  = Bh + EXP_B_U32;
    int b = blockIdx.z;
    int p0 = blockIdx.x * 128;
    int tid = threadIdx.x;
    int lane = tid & 31, w = tid >> 5;
    int wr = w >> 2, wc = w & 3;
    int g = lane >> 2, tg = lane & 3;
    const float* xb = x + (size_t)b * CINC * HWP;
    float* ob = g_mid + (size_t)b * MIDC * HWP;

    {
        const uint4* src = (const uint4*)g_WexpF;
        #pragma unroll
        for (int j = 0; j < 6; j++)   // 1536 = 6*256 exact
            cpa16(smaddr(As0) + (tid + j * 256) * 16, src + tid + j * 256, true);
        cpa_commit();
    }
    #pragma unroll
    for (int j = 0; j < 6; j++) {
        int v = tid + j * 256;
        int k2 = v >> 5, c4 = (v & 31) << 2;
        int p = p0 + c4;
        float4 r0 = make_float4(0.f, 0.f, 0.f, 0.f), r1 = r0;
        if (p < HWP) {
            r0 = *(const float4*)&xb[(size_t)(2 * k2) * HWP + p];
            r1 = *(const float4*)&xb[(size_t)(2 * k2 + 1) * HWP + p];
        }
        float e0[4] = {r0.x, r0.y, r0.z, r0.w};
        float e1[4] = {r1.x, r1.y, r1.z, r1.w};
        uint32_t hh[4], ll[4];
        #pragma unroll
        for (int i = 0; i < 4; i++) {
            float h0 = bf16hi(e0[i]), h1 = bf16hi(e1[i]);
            hh[i] = packbf2(h0, h1);
            ll[i] = packbf2(e0[i] - h0, e1[i] - h1);
        }
        *(uint4*)&Bh[k2 * BSS + c4] = make_uint4(hh[0], hh[1], hh[2], hh[3]);
        *(uint4*)&Bl[k2 * BSS + c4] = make_uint4(ll[0], ll[1], ll[2], ll[3]);
    }

    for (int mt = 0; mt < 3; mt++) {
        uint32_t* Acur = (mt & 1) ? As1 : As0;
        if (mt < 2) {
            uint32_t* Anext = (mt & 1) ? As0 : As1;
            const uint4* src = ((const uint4*)g_WexpF) + (mt + 1) * (EXP_A_U32 / 4);
            #pragma unroll
            for (int j = 0; j < 6; j++)
                cpa16(smaddr(Anext) + (tid + j * 256) * 16, src + tid + j * 256, true);
            cpa_commit();
            cpa_wait<1>();
        } else {
            cpa_wait<0>();
        }
        __syncthreads();

        float acc[2][4][4] = {};
        #pragma unroll
        for (int ki = 0; ki < 6; ki++) {
            uint4 ah[2], al[2];
            #pragma unroll
            for (int mi = 0; mi < 2; mi++) {
                int off = (((wr * 6 + ki) * 2 + mi) * 2) * 128 + lane * 4;
                ah[mi] = *(const uint4*)&Acur[off];
                al[mi] = *(const uint4*)&Acur[off + 128];
            }
            uint32_t bh[4][2], bl[4][2];
            int kr2 = ki * 8;
            #pragma unroll
            for (int ni = 0; ni < 4; ni++) {
                int nb = wc * 32 + ni * 8 + g;
                bh[ni][0] = Bh[(kr2 + tg) * BSS + nb];
                bh[ni][1] = Bh[(kr2 + tg + 4) * BSS + nb];
                bl[ni][0] = Bl[(kr2 + tg) * BSS + nb];
                bl[ni][1] = Bl[(kr2 + tg + 4) * BSS + nb];
            }
            #pragma unroll
            for (int mi = 0; mi < 2; mi++)
                #pragma unroll
                for (int ni = 0; ni < 4; ni++) {
                    mma16(acc[mi][ni], (const uint32_t*)&ah[mi], bh[ni]);
                    mma16(acc[mi][ni], (const uint32_t*)&al[mi], bh[ni]);
                    mma16(acc[mi][ni], (const uint32_t*)&ah[mi], bl[ni]);
                }
        }

        int m0 = mt * 64;
        #pragma unroll
        for (int mi = 0; mi < 2; mi++) {
            int o = m0 + wr * 32 + mi * 16 + g;
            float b0 = g_bexp[o], b1 = g_bexp[o + 8];
            #pragma unroll
            for (int ni = 0; ni < 4; ni++) {
                int p = p0 + wc * 32 + ni * 8 + tg * 2;
                if (p < HWP) {
                    float2 r0 = make_float2(silu_f(acc[mi][ni][0] + b0),
                                            silu_f(acc[mi][ni][1] + b0));
                    *(float2*)&ob[(size_t)o * HWP + p] = r0;
                    float2 r1 = make_float2(silu_f(acc[mi][ni][2] + b1),
                                            silu_f(acc[mi][ni][3] + b1));
                    *(float2*)&ob[(size_t)(o + 8) * HWP + p] = r1;
                }
            }
        }
        __syncthreads();
    }
}

// ---------------------------------------------------------------------------
// dwmerge v2: vectorized. Shifted planes stored at col offset OFF=5-ox so
// OFF+ox=5 for all groups -> all compute reads start at col 4q+4 (aligned).
// Quad-pixel compute, 2 channels, uint4 stores of packed bf16 hi/lo.
// ---------------------------------------------------------------------------
#define SROW 64
__global__ void __launch_bounds__(256) dwmerge_kernel() {
    __shared__ float sps[2][58 * SROW];
    __shared__ float sred[16];
    int bc = blockIdx.x;
    int b = bc / 96, k2 = bc - b * 96;
    int tid = threadIdx.x;

    int oyA[2], oxA[2];
    const float* planes[2];
    float w9[2][9], T[2];
    #pragma unroll
    for (int ch = 0; ch < 2; ch++) {
        int c = 2 * k2 + ch;
        int cpre = (c & 3) * 48 + (c >> 2);
        int gg = c & 3;
        oyA[ch] = (gg == 0) ? -1 : (gg == 2) ? 1 : 0;
        oxA[ch] = (gg == 1) ? -1 : (gg == 3) ? 1 : 0;
        planes[ch] = g_mid + ((size_t)b * MIDC + cpre) * HWP;
        #pragma unroll
        for (int k = 0; k < 9; k++) w9[ch][k] = g_W9[c * 9 + k];
        T[ch] = g_T[c];
    }

    // Pass 1: zero both planes (float4)
    {
        float4* z = (float4*)&sps[0][0];
        for (int i = tid; i < 2 * 58 * SROW / 4; i += 256)
            z[i] = make_float4(0.f, 0.f, 0.f, 0.f);
    }
    __syncthreads();

    // Pass 2: fill valid rows with LDG.128 row segments at col offset OFF=5-ox
    for (int t = tid; t < 1624; t += 256) {
        int ch = t >= 812;
        int u = t - ch * 812;
        int r = u / 14, qq = u - r * 14;
        int hp = r - 1, hs = hp + oyA[ch];
        if ((unsigned)hp < 56u && (unsigned)hs < 56u) {
            float4 v = *(const float4*)&planes[ch][hs * 56 + qq * 4];
            float* d = &sps[ch][r * SROW + qq * 4 + (5 - oxA[ch])];
            d[0] = v.x; d[1] = v.y; d[2] = v.z; d[3] = v.w;
        }
    }
    __syncthreads();

    // Pass 3: zero the conv-pad cell that the shifted copy filled (wp out of range)
    if (tid < 116) {
        int ch = tid >= 58;
        int r = tid - ch * 58;
        int ox = oxA[ch];
        if (ox == 1)  sps[ch][r * SROW + 4] = 0.f;   // wp=-1 cell
        if (ox == -1) sps[ch][r * SROW + 61] = 0.f;  // wp=56 cell
    }
    __syncthreads();

    uint32_t* oH = g_mergedH + ((size_t)b * 96 + k2) * HWP;
    uint32_t* oL = g_mergedL + ((size_t)b * 96 + k2) * HWP;
    float ls0 = 0.f, ls1 = 0.f;

    for (int t = tid; t < 784; t += 256) {
        int h = t / 14, q = t - h * 14;
        float a0[4] = {T[0], T[0], T[0], T[0]};
        float a1[4] = {T[1], T[1], T[1], T[1]};
        #pragma unroll
        for (int ch = 0; ch < 2; ch++) {
            float* accp = ch ? a1 : a0;
            #pragma unroll
            for (int dy = 0; dy < 3; dy++) {
                const float* row = &sps[ch][(h + dy) * SROW + q * 4 + 4];
                float4 A = *(const float4*)row;
                float2 Bv = *(const float2*)(row + 4);
                float wA = w9[ch][dy * 3], wB = w9[ch][dy * 3 + 1], wC = w9[ch][dy * 3 + 2];
                accp[0] += wA * A.x + wB * A.y + wC * A.z;
                accp[1] += wA * A.y + wB * A.z + wC * A.w;
                accp[2] += wA * A.z + wB * A.w + wC * Bv.x;
                accp[3] += wA * A.w + wB * Bv.x + wC * Bv.y;
            }
        }
        uint32_t Hw[4], Lw[4];
        #pragma unroll
        for (int i = 0; i < 4; i++) {
            float s0 = silu_f(a0[i]);
            float s1 = silu_f(a1[i]);
            float h0 = bf16hi(s0), h1 = bf16hi(s1);
            Hw[i] = packbf2(h0, h1);
            Lw[i] = packbf2(s0 - h0, s1 - h1);
            ls0 += s0;
            ls1 += s1;
        }
        int o = h * 56 + q * 4;
        *(uint4*)&oH[o] = make_uint4(Hw[0], Hw[1], Hw[2], Hw[3]);
        *(uint4*)&oL[o] = make_uint4(Lw[0], Lw[1], Lw[2], Lw[3]);
    }

    int wid = tid >> 5, lane = tid & 31;
    #pragma unroll
    for (int o = 16; o > 0; o >>= 1) {
        ls0 += __shfl_down_sync(0xffffffffu, ls0, o);
        ls1 += __shfl_down_sync(0xffffffffu, ls1, o);
    }
    if (lane == 0) { sred[wid] = ls0; sred[8 + wid] = ls1; }
    __syncthreads();
    if (tid < 16) {
        float v = sred[tid];
        #pragma unroll
        for (int o = 4; o > 0; o >>= 1) v += __shfl_down_sync(0xffffu, v, o);
        if (tid == 0) g_sums[b * 192 + 2 * k2] = v;
        if (tid == 8) g_sums[b * 192 + 2 * k2 + 1] = v;
    }
}

// ---------------------------------------------------------------------------
// SE gating + per-batch scaled/resplit proj weights. Block = (batch, chunk).
// ---------------------------------------------------------------------------
__global__ void __launch_bounds__(256) se_scale_kernel(const float* __restrict__ red_w,
                                                       const float* __restrict__ red_b,
                                                       const float* __restrict__ exp_w,
                                                       const float* __restrict__ exp_b) {
    __shared__ float smean[192];
    __shared__ float sredu[24];
    __shared__ float s_se[192];
    int b = blockIdx.x, cc = blockIdx.y;
    int tid = threadIdx.x;

    if (tid < 192) smean[tid] = g_sums[b * 192 + tid] * (1.f / 3136.f);
    __syncthreads();
    if (tid < 24) {
        int gq = tid >> 1;
        float a = red_b[tid];
        #pragma unroll
        for (int i = 0; i < 16; i++) a += red_w[tid * 16 + i] * smean[gq * 16 + i];
        sredu[tid] = fmaxf(a, 0.f);
    }
    __syncthreads();
    if (tid < 192) {
        int gq = tid >> 4;
        float v = exp_w[tid * 2] * sredu[gq * 2] + exp_w[tid * 2 + 1] * sredu[gq * 2 + 1]
                + exp_b[tid];
        s_se[tid] = 1.f / (1.f + __expf(-v));
    }
    __syncthreads();

    uint32_t* dstb = g_WprojSE + (size_t)b * 18432;
    const uint4* src = ((const uint4*)g_WprojF) + cc * (PROJ_A_U32 / 4);
    uint4* dst = ((uint4*)dstb) + cc * (PROJ_A_U32 / 4);
    for (int i = tid; i < 576; i += 256) {
        int grp = i >> 5, li = i & 31;
        int ki = (grp / 3) % 3;
        uint4 H = src[grp * 64 + li];
        uint4 L = src[grp * 64 + li + 32];
        int k2a = cc * 24 + ki * 8 + (li & 3);
        float se0 = s_se[2 * k2a], se1 = s_se[2 * k2a + 1];
        float se2 = s_se[2 * k2a + 8], se3 = s_se[2 * k2a + 9];
        uint32_t hu[4] = {H.x, H.y, H.z, H.w};
        uint32_t lu[4] = {L.x, L.y, L.z, L.w};
        uint32_t nh[4], nl[4];
        #pragma unroll
        for (int q = 0; q < 4; q++) {
            float sA = (q < 2) ? se0 : se2;
            float sB = (q < 2) ? se1 : se3;
            float2 hf = unpackbf2(hu[q]);
            float2 lf = unpackbf2(lu[q]);
            float v0 = (hf.x + lf.x) * sA;
            float v1 = (hf.y + lf.y) * sB;
            float h0 = bf16hi(v0), h1 = bf16hi(v1);
            nh[q] = packbf2(h0, h1);
            nl[q] = packbf2(v0 - h0, v1 - h1);
        }
        dst[grp * 64 + li]      = make_uint4(nh[0], nh[1], nh[2], nh[3]);
        dst[grp * 64 + li + 32] = make_uint4(nl[0], nl[1], nl[2], nl[3]);
    }
}

// ---------------------------------------------------------------------------
// Project 1x1 GEMM. M=96 x N=128; 4 k-chunks of 48; BOTH A and B raw
// cp.async double-buffered (A pre-scaled by SE). Pure copy+MMA mainloop.
// ---------------------------------------------------------------------------
__global__ void __launch_bounds__(256, 2) proj_gemm(const float* __restrict__ x,
                                                    float* __restrict__ out) {
    extern __shared__ uint32_t smu[];
    uint32_t* As0 = smu;                        // PROJ_A_U32
    uint32_t* As1 = smu + PROJ_A_U32;
    uint32_t* Bst = smu + 2 * PROJ_A_U32;       // 2 stages x 2 planes x PROJ_B_U32

    int b = blockIdx.z;
    int p0 = blockIdx.x * 128;
    int tid = threadIdx.x;
    int lane = tid & 31, w = tid >> 5;
    int wr = w >> 2, wc = w & 3;
    int g = lane >> 2, tg = lane & 3;
    const uint32_t* mH = g_mergedH + (size_t)b * 96 * HWP;
    const uint32_t* mL = g_mergedL + (size_t)b * 96 * HWP;
    const uint4* Asrc = (const uint4*)(g_WprojSE + (size_t)b * 18432);

    auto cp_stage = [&](int c) {
        int stage = c & 1;
        uint32_t dstB = smaddr(Bst) + stage * 2 * PROJ_B_U32 * 4;
        const uint4* sH = (const uint4*)(mH + (size_t)(c * 24) * HWP);
        const uint4* sL = (const uint4*)(mL + (size_t)(c * 24) * HWP);
        #pragma unroll
        for (int j = 0; j < 3; j++) {
            int v = tid + j * 256;
            int r = v >> 5, c4 = (v & 31);
            int p = p0 + c4 * 4;
            bool ok = p < HWP;                  // zero-fill pad (intended)
            size_t so = (size_t)r * (HWP / 4) + (p0 >> 2) + c4;
            uint32_t d = dstB + (r * BSS + c4 * 4) * 4;
            cpa16(d, sH + (ok ? so : 0), ok);
            cpa16(d + PROJ_B_U32 * 4, sL + (ok ? so : 0), ok);
        }
        // A chunk: 1152 uint4 = 4*256 + 128 exact
        uint32_t dstA = smaddr(stage ? As1 : As0);
        const uint4* sA = Asrc + c * (PROJ_A_U32 / 4);
        #pragma unroll
        for (int j = 0; j < 4; j++) {
            int v = tid + j * 256;
            cpa16(dstA + v * 16, sA + v, true);
        }
        if (tid < 128) {
            int v = tid + 1024;
            cpa16(dstA + v * 16, sA + v, true);
        }
        cpa_commit();
    };
    cp_stage(0);

    float acc[3][4][4] = {};

    for (int c = 0; c < 4; c++) {
        uint32_t* Acur = (c & 1) ? As1 : As0;
        uint32_t* BhS = Bst + (c & 1) * 2 * PROJ_B_U32;
        uint32_t* BlS = BhS + PROJ_B_U32;
        if (c < 3) {
            cp_stage(c + 1);
            cpa_wait<1>();
        } else {
            cpa_wait<0>();
        }
        __syncthreads();

        #pragma unroll
        for (int ki = 0; ki < 3; ki++) {
            uint4 ah[3], al[3];
            #pragma unroll
            for (int mi = 0; mi < 3; mi++) {
                int off = ((wr * 3 + ki) * 3 + mi) * 256 + lane * 4;
                ah[mi] = *(const uint4*)&Acur[off];
                al[mi] = *(const uint4*)&Acur[off + 128];
            }
            uint32_t bh[4][2], bl[4][2];
            int kr2 = ki * 8;
            #pragma unroll
            for (int ni = 0; ni < 4; ni++) {
                int nb = wc * 32 + ni * 8 + g;
                bh[ni][0] = BhS[(kr2 + tg) * BSS + nb];
                bh[ni][1] = BhS[(kr2 + tg + 4) * BSS + nb];
                bl[ni][0] = BlS[(kr2 + tg) * BSS + nb];
                bl[ni][1] = BlS[(kr2 + tg + 4) * BSS + nb];
            }
            #pragma unroll
            for (int mi = 0; mi < 3; mi++)
                #pragma unroll
                for (int ni = 0; ni < 4; ni++) {
                    mma16(acc[mi][ni], (const uint32_t*)&ah[mi], bh[ni]);
                    mma16(acc[mi][ni], (const uint32_t*)&al[mi], bh[ni]);
                    mma16(acc[mi][ni], (const uint32_t*)&ah[mi], bl[ni]);
                }
        }
        __syncthreads();
    }

    const float* xb = x + (size_t)b * COUTC * HWP;
    float* ob = out + (size_t)b * COUTC * HWP;
    #pragma unroll
    for (int mi = 0; mi < 3; mi++) {
        int o = wr * 48 + mi * 16 + g;
        float b0 = g_bproj[o], b1 = g_bproj[o + 8];
        #pragma unroll
        for (int ni = 0; ni < 4; ni++) {
            int p = p0 + wc * 32 + ni * 8 + tg * 2;
            if (p < HWP) {
                float2 x0 = *(const float2*)&xb[(size_t)o * HWP + p];
                float2 r0;
                r0.x = silu_f(acc[mi][ni][0] + b0 + x0.x);
                r0.y = silu_f(acc[mi][ni][1] + b0 + x0.y);
                *(float2*)&ob[(size_t)o * HWP + p] = r0;
                float2 x1 = *(const float2*)&xb[(size_t)(o + 8) * HWP + p];
                float2 r1;
                r1.x = silu_f(acc[mi][ni][2] + b1 + x1.x);
                r1.y = silu_f(acc[mi][ni][3] + b1 + x1.y);
                *(float2*)&ob[(size_t)(o + 8) * HWP + p] = r1;
            }
        }
    }
}

// ---------------------------------------------------------------------------
extern "C" void kernel_launch(void* const* d_in, const int* in_sizes, int n_in,
                              void* d_out, int out_size) {
    const float* x         = (const float*)d_in[0];
    const float* expand_w  = (const float*)d_in[1];
    const float* expand_bn = (const float*)d_in[2];
    const float* dw_w      = (const float*)d_in[3];
    const float* dw_bn     = (const float*)d_in[4];
    const float* id_w      = (const float*)d_in[5];
    const float* id_bn     = (const float*)d_in[6];
    const float* merge_bn  = (const float*)d_in[7];
    const float* se_red_w  = (const float*)d_in[8];
    const float* se_red_b  = (const float*)d_in[9];
    const float* se_exp_w  = (const float*)d_in[10];
    const float* se_exp_b  = (const float*)d_in[11];
    const float* proj_w    = (const float*)d_in[12];
    const float* proj_bn   = (const float*)d_in[13];
    float* out = (float*)d_out;

    cudaFuncSetAttribute(expand_gemm, cudaFuncAttributeMaxDynamicSharedMemorySize, EXP_SMEM);
    cudaFuncSetAttribute(proj_gemm,   cudaFuncAttributeMaxDynamicSharedMemorySize, PROJ_SMEM);

    prep_kernel<<<80, 256>>>(expand_w, expand_bn, dw_w, dw_bn, id_w, id_bn,
                             merge_bn, proj_w, proj_bn);
    expand_gemm<<<dim3(25, 1, BZ), 256, EXP_SMEM>>>(x);
    dwmerge_kernel<<<BZ * 96, 256>>>();
    se_scale_kernel<<<dim3(BZ, 4), 256>>>(se_red_w, se_red_b, se_exp_w, se_exp_b);
    proj_gemm<<<dim3(25, 1, BZ), 256, PROJ_SMEM>>>(x, out);
}

// round 10
// speedup vs baseline: 2.3798x; 1.0706x over previous
#include <cuda_runtime.h>
#include <cuda_bf16.h>
#include <math.h>
#include <stdint.h>

#define BZ    64
#define CINC  96
#define COUTC 96
#define MIDC  192
#define HWP   3136
#define EPSBN 1e-5f

#define BSS 136                    // pair-row stride (u32): bank = 8*tg+g, conflict-free
#define EXP_A_U32   6144           // per-mt A chunk  [wr2][ki6][mi2][hl2][lane32][q4]
#define PROJ_A_U32  4608           // per-kchunk A    [wr2][ki3][mi3][hl2][lane32][q4]
#define EXP_B_U32   (48 * BSS)     // one plane (hi or lo), 48 pair-rows
#define PROJ_B_U32  (24 * BSS)     // one plane per chunk, 24 pair-rows
#define EXP_SMEM  ((2 * EXP_A_U32 + 2 * EXP_B_U32) * 4)      // 101376 B
#define PROJ_SMEM ((2 * PROJ_A_U32 + 4 * PROJ_B_U32) * 4)    // 89088 B

// Scratch (device globals: allowed; no cudaMalloc anywhere)
__device__ __align__(16) float    g_mid[(size_t)BZ * MIDC * HWP];
__device__ __align__(16) uint32_t g_mergedH[(size_t)BZ * 96 * HWP];  // packed bf16 (c,c+1) hi
__device__ __align__(16) uint32_t g_mergedL[(size_t)BZ * 96 * HWP];  // packed bf16 lo residual
__device__ float    g_sums[BZ * MIDC];
__device__ __align__(16) uint32_t g_WexpF[18432];   // [mt3][wr2][ki6][mi2][hl2][lane32][q4]
__device__ __align__(16) uint32_t g_WprojF[18432];  // [chunk4][wr2][ki3][mi3][hl2][lane32][q4]
__device__ __align__(16) uint32_t g_WprojSE[(size_t)BZ * 18432];  // per-batch SE-scaled resplit
__device__ float    g_bexp[MIDC];
__device__ float    g_W9[MIDC * 9];
__device__ float    g_T[MIDC];
__device__ float    g_bproj[COUTC];

__device__ __forceinline__ float silu_f(float v) { return v / (1.f + __expf(-v)); }

__device__ __forceinline__ uint32_t packbf2(float lo_elem, float hi_elem) {
    __nv_bfloat162 t = __floats2bfloat162_rn(lo_elem, hi_elem);  // .x = low 16 bits
    return *(uint32_t*)&t;
}
__device__ __forceinline__ float2 unpackbf2(uint32_t u) {
    __nv_bfloat162 t = *(__nv_bfloat162*)&u;
    return __bfloat1622float2(t);
}
__device__ __forceinline__ float bf16hi(float v) {
    return __bfloat162float(__float2bfloat16_rn(v));
}

__device__ __forceinline__ void mma16(float* c, const uint32_t* a, const uint32_t* b) {
    asm volatile(
        "mma.sync.aligned.m16n8k16.row.col.f32.bf16.bf16.f32 "
        "{%0,%1,%2,%3},{%4,%5,%6,%7},{%8,%9},{%0,%1,%2,%3};"
        : "+f"(c[0]), "+f"(c[1]), "+f"(c[2]), "+f"(c[3])
        : "r"(a[0]), "r"(a[1]), "r"(a[2]), "r"(a[3]), "r"(b[0]), "r"(b[1]));
}

__device__ __forceinline__ uint32_t smaddr(const void* p) {
    return (uint32_t)__cvta_generic_to_shared(p);
}
__device__ __forceinline__ void cpa16(uint32_t dst_s, const void* src, bool valid) {
    // NOTE: valid=false still WRITES 16 zero bytes to dst (zero-fill), use only
    // where zero-padding the destination is intended.
    int sz = valid ? 16 : 0;
    asm volatile("cp.async.cg.shared.global [%0], [%1], 16, %2;\n"
                 :: "r"(dst_s), "l"(src), "r"(sz));
}
__device__ __forceinline__ void cpa_commit() {
    asm volatile("cp.async.commit_group;\n");
}
template <int N>
__device__ __forceinline__ void cpa_wait() {
    asm volatile("cp.async.wait_group %0;\n" :: "n"(N));
}

// ---------------------------------------------------------------------------
// prep: fold BN; emit fragment-ordered packed-bf16 hi/lo weights.
// ---------------------------------------------------------------------------
__global__ void prep_kernel(const float* __restrict__ expand_w,
                            const float* __restrict__ expand_bn,
                            const float* __restrict__ dw_w,
                            const float* __restrict__ dw_bn,
                            const float* __restrict__ id_w,
                            const float* __restrict__ id_bn,
                            const float* __restrict__ merge_bn,
                            const float* __restrict__ proj_w,
                            const float* __restrict__ proj_bn) {
    int tid = blockIdx.x * blockDim.x + threadIdx.x;
    int nth = gridDim.x * blockDim.x;

    for (int idx = tid; idx < 18432; idx += nth) {
        int q = idx & 3, lane = (idx >> 2) & 31, hl = (idx >> 7) & 1;
        int t = idx >> 8;
        int mi = t & 1; t >>= 1;
        int ki = t % 6; t /= 6;
        int wr = t & 1; t >>= 1;
        int mt = t;
        int m = mt * 64 + wr * 32 + mi * 16 + (lane >> 2) + 8 * (q & 1);
        int k = ki * 16 + (lane & 3) * 2 + 8 * (q >> 1);
        float sc = expand_bn[m] * rsqrtf(expand_bn[3 * MIDC + m] + EPSBN);
        float w0 = expand_w[m * CINC + k] * sc;
        float w1 = expand_w[m * CINC + k + 1] * sc;
        float h0 = bf16hi(w0), h1 = bf16hi(w1);
        g_WexpF[idx] = hl ? packbf2(w0 - h0, w1 - h1) : packbf2(h0, h1);
    }
    for (int idx = tid; idx < 18432; idx += nth) {
        int q = idx & 3, lane = (idx >> 2) & 31, hl = (idx >> 7) & 1;
        int t = idx >> 8;
        int mi = t % 3; t /= 3;
        int ki = t % 3; t /= 3;
        int wr = t & 1; int chunk = t >> 1;
        int m = wr * 48 + mi * 16 + (lane >> 2) + 8 * (q & 1);
        int k = chunk * 48 + ki * 16 + (lane & 3) * 2 + 8 * (q >> 1);
        float sc = proj_bn[m] * rsqrtf(proj_bn[3 * COUTC + m] + EPSBN);
        float w0 = proj_w[m * MIDC + k] * sc;
        float w1 = proj_w[m * MIDC + k + 1] * sc;
        float h0 = bf16hi(w0), h1 = bf16hi(w1);
        g_WprojF[idx] = hl ? packbf2(w0 - h0, w1 - h1) : packbf2(h0, h1);
    }
    for (int o = tid; o < MIDC; o += nth) {
        float sc = expand_bn[o] * rsqrtf(expand_bn[3 * MIDC + o] + EPSBN);
        g_bexp[o] = expand_bn[MIDC + o] - expand_bn[2 * MIDC + o] * sc;
    }
    for (int c = tid; c < MIDC; c += nth) {
        float dsc = dw_bn[c] * rsqrtf(dw_bn[3 * MIDC + c] + EPSBN);
        float dsh = dw_bn[MIDC + c] - dw_bn[2 * MIDC + c] * dsc;
        float isc = id_bn[c] * rsqrtf(id_bn[3 * MIDC + c] + EPSBN);
        float ish = id_bn[MIDC + c] - id_bn[2 * MIDC + c] * isc;
        float msc = merge_bn[c] * rsqrtf(merge_bn[3 * MIDC + c] + EPSBN);
        float msh = merge_bn[MIDC + c] - merge_bn[2 * MIDC + c] * msc;
        #pragma unroll
        for (int k = 0; k < 9; k++) g_W9[c * 9 + k] = msc * dsc * dw_w[c * 9 + k];
        g_W9[c * 9 + 4] += msc * isc * id_w[c];
        g_T[c] = msc * (dsh + ish) + msh;
    }
    for (int o = tid; o < COUTC; o += nth) {
        float sc = proj_bn[o] * rsqrtf(proj_bn[3 * COUTC + o] + EPSBN);
        g_bproj[o] = proj_bn[COUTC + o] - proj_bn[2 * COUTC + o] * sc;
    }
}

// ---------------------------------------------------------------------------
// Expand 1x1 GEMM. 192(Mx3 passes) x 128(N); warp tile 32x32; bf16 k16.
// A depth-2 cp.async pipeline (A0+A1 upfront, A2 issued after pass 0);
// B converted once at start (overlapped with A fetches).
// ---------------------------------------------------------------------------
__global__ void __launch_bounds__(256, 2) expand_gemm(const float* __restrict__ x) {
    extern __shared__ uint32_t smu[];
    uint32_t* As0 = smu;                    // EXP_A_U32
    uint32_t* As1 = smu + EXP_A_U32;
    uint32_t* Bh  = smu + 2 * EXP_A_U32;    // EXP_B_U32
    uint32_t* Bl  = Bh + EXP_B_U32;
    int b = blockIdx.z;
    int p0 = blockIdx.x * 128;
    int tid = threadIdx.x;
    int lane = tid & 31, w = tid >> 5;
    int wr = w >> 2, wc = w & 3;
    int g = lane >> 2, tg = lane & 3;
    const float* xb = x + (size_t)b * CINC * HWP;
    float* ob = g_mid + (size_t)b * MIDC * HWP;

    // Prefetch A(0) and A(1) upfront (two commit groups)
    {
        const uint4* src = (const uint4*)g_WexpF;
        #pragma unroll
        for (int j = 0; j < 6; j++)
            cpa16(smaddr(As0) + (tid + j * 256) * 16, src + tid + j * 256, true);
        cpa_commit();
        src += EXP_A_U32 / 4;
        #pragma unroll
        for (int j = 0; j < 6; j++)
            cpa16(smaddr(As1) + (tid + j * 256) * 16, src + tid + j * 256, true);
        cpa_commit();
    }
    // Convert B (overlaps both A fetches)
    #pragma unroll
    for (int j = 0; j < 6; j++) {
        int v = tid + j * 256;
        int k2 = v >> 5, c4 = (v & 31) << 2;
        int p = p0 + c4;
        float4 r0 = make_float4(0.f, 0.f, 0.f, 0.f), r1 = r0;
        if (p < HWP) {
            r0 = *(const float4*)&xb[(size_t)(2 * k2) * HWP + p];
            r1 = *(const float4*)&xb[(size_t)(2 * k2 + 1) * HWP + p];
        }
        float e0[4] = {r0.x, r0.y, r0.z, r0.w};
        float e1[4] = {r1.x, r1.y, r1.z, r1.w};
        uint32_t hh[4], ll[4];
        #pragma unroll
        for (int i = 0; i < 4; i++) {
            float h0 = bf16hi(e0[i]), h1 = bf16hi(e1[i]);
            hh[i] = packbf2(h0, h1);
            ll[i] = packbf2(e0[i] - h0, e1[i] - h1);
        }
        *(uint4*)&Bh[k2 * BSS + c4] = make_uint4(hh[0], hh[1], hh[2], hh[3]);
        *(uint4*)&Bl[k2 * BSS + c4] = make_uint4(ll[0], ll[1], ll[2], ll[3]);
    }

    for (int mt = 0; mt < 3; mt++) {
        uint32_t* Acur = (mt & 1) ? As1 : As0;
        if (mt == 2) { cpa_wait<0>(); } else { cpa_wait<1>(); }
        __syncthreads();   // A(mt) visible; B visible (mt=0); prev buffer free

        float acc[2][4][4] = {};
        #pragma unroll
        for (int ki = 0; ki < 6; ki++) {
            uint4 ah[2], al[2];
            #pragma unroll
            for (int mi = 0; mi < 2; mi++) {
                int off = (((wr * 6 + ki) * 2 + mi) * 2) * 128 + lane * 4;
                ah[mi] = *(const uint4*)&Acur[off];
                al[mi] = *(const uint4*)&Acur[off + 128];
            }
            uint32_t bh[4][2], bl[4][2];
            int kr2 = ki * 8;
            #pragma unroll
            for (int ni = 0; ni < 4; ni++) {
                int nb = wc * 32 + ni * 8 + g;
                bh[ni][0] = Bh[(kr2 + tg) * BSS + nb];
                bh[ni][1] = Bh[(kr2 + tg + 4) * BSS + nb];
                bl[ni][0] = Bl[(kr2 + tg) * BSS + nb];
                bl[ni][1] = Bl[(kr2 + tg + 4) * BSS + nb];
            }
            #pragma unroll
            for (int mi = 0; mi < 2; mi++)
                #pragma unroll
                for (int ni = 0; ni < 4; ni++) {
                    mma16(acc[mi][ni], (const uint32_t*)&ah[mi], bh[ni]);
                    mma16(acc[mi][ni], (const uint32_t*)&al[mi], bh[ni]);
                    mma16(acc[mi][ni], (const uint32_t*)&ah[mi], bl[ni]);
                }
        }

        int m0 = mt * 64;
        #pragma unroll
        for (int mi = 0; mi < 2; mi++) {
            int o = m0 + wr * 32 + mi * 16 + g;
            float b0 = g_bexp[o], b1 = g_bexp[o + 8];
            #pragma unroll
            for (int ni = 0; ni < 4; ni++) {
                int p = p0 + wc * 32 + ni * 8 + tg * 2;
                if (p < HWP) {
                    float2 r0 = make_float2(silu_f(acc[mi][ni][0] + b0),
                                            silu_f(acc[mi][ni][1] + b0));
                    *(float2*)&ob[(size_t)o * HWP + p] = r0;
                    float2 r1 = make_float2(silu_f(acc[mi][ni][2] + b1),
                                            silu_f(acc[mi][ni][3] + b1));
                    *(float2*)&ob[(size_t)(o + 8) * HWP + p] = r1;
                }
            }
        }
        __syncthreads();   // all reads of Acur done before refill
        if (mt == 0) {
            const uint4* src = ((const uint4*)g_WexpF) + 2 * (EXP_A_U32 / 4);
            #pragma unroll
            for (int j = 0; j < 6; j++)
                cpa16(smaddr(As0) + (tid + j * 256) * 16, src + tid + j * 256, true);
            cpa_commit();
        }
    }
}

// ---------------------------------------------------------------------------
// dwmerge v2: vectorized. Shifted planes stored at col offset OFF=5-ox so
// OFF+ox=5 for all groups -> all compute reads start at col 4q+4 (aligned).
// Quad-pixel compute, 2 channels, uint4 stores of packed bf16 hi/lo.
// ---------------------------------------------------------------------------
#define SROW 64
__global__ void __launch_bounds__(256) dwmerge_kernel() {
    __shared__ float sps[2][58 * SROW];
    __shared__ float sred[16];
    int bc = blockIdx.x;
    int b = bc / 96, k2 = bc - b * 96;
    int tid = threadIdx.x;

    int oyA[2], oxA[2];
    const float* planes[2];
    float w9[2][9], T[2];
    #pragma unroll
    for (int ch = 0; ch < 2; ch++) {
        int c = 2 * k2 + ch;
        int cpre = (c & 3) * 48 + (c >> 2);
        int gg = c & 3;
        oyA[ch] = (gg == 0) ? -1 : (gg == 2) ? 1 : 0;
        oxA[ch] = (gg == 1) ? -1 : (gg == 3) ? 1 : 0;
        planes[ch] = g_mid + ((size_t)b * MIDC + cpre) * HWP;
        #pragma unroll
        for (int k = 0; k < 9; k++) w9[ch][k] = g_W9[c * 9 + k];
        T[ch] = g_T[c];
    }

    // Pass 1: zero both planes (float4)
    {
        float4* z = (float4*)&sps[0][0];
        for (int i = tid; i < 2 * 58 * SROW / 4; i += 256)
            z[i] = make_float4(0.f, 0.f, 0.f, 0.f);
    }
    __syncthreads();

    // Pass 2: fill valid rows with LDG.128 row segments at col offset OFF=5-ox
    for (int t = tid; t < 1624; t += 256) {
        int ch = t >= 812;
        int u = t - ch * 812;
        int r = u / 14, qq = u - r * 14;
        int hp = r - 1, hs = hp + oyA[ch];
        if ((unsigned)hp < 56u && (unsigned)hs < 56u) {
            float4 v = *(const float4*)&planes[ch][hs * 56 + qq * 4];
            float* d = &sps[ch][r * SROW + qq * 4 + (5 - oxA[ch])];
            d[0] = v.x; d[1] = v.y; d[2] = v.z; d[3] = v.w;
        }
    }
    __syncthreads();

    // Pass 3: zero the conv-pad cell that the shifted copy filled (wp out of range)
    if (tid < 116) {
        int ch = tid >= 58;
        int r = tid - ch * 58;
        int ox = oxA[ch];
        if (ox == 1)  sps[ch][r * SROW + 4] = 0.f;   // wp=-1 cell
        if (ox == -1) sps[ch][r * SROW + 61] = 0.f;  // wp=56 cell
    }
    __syncthreads();

    uint32_t* oH = g_mergedH + ((size_t)b * 96 + k2) * HWP;
    uint32_t* oL = g_mergedL + ((size_t)b * 96 + k2) * HWP;
    float ls0 = 0.f, ls1 = 0.f;

    for (int t = tid; t < 784; t += 256) {
        int h = t / 14, q = t - h * 14;
        float a0[4] = {T[0], T[0], T[0], T[0]};
        float a1[4] = {T[1], T[1], T[1], T[1]};
        #pragma unroll
        for (int ch = 0; ch < 2; ch++) {
            float* accp = ch ? a1 : a0;
            #pragma unroll
            for (int dy = 0; dy < 3; dy++) {
                const float* row = &sps[ch][(h + dy) * SROW + q * 4 + 4];
                float4 A = *(const float4*)row;
                float2 Bv = *(const float2*)(row + 4);
                float wA = w9[ch][dy * 3], wB = w9[ch][dy * 3 + 1], wC = w9[ch][dy * 3 + 2];
                accp[0] += wA * A.x + wB * A.y + wC * A.z;
                accp[1] += wA * A.y + wB * A.z + wC * A.w;
                accp[2] += wA * A.z + wB * A.w + wC * Bv.x;
                accp[3] += wA * A.w + wB * Bv.x + wC * Bv.y;
            }
        }
        uint32_t Hw[4], Lw[4];
        #pragma unroll
        for (int i = 0; i < 4; i++) {
            float s0 = silu_f(a0[i]);
            float s1 = silu_f(a1[i]);
            float h0 = bf16hi(s0), h1 = bf16hi(s1);
            Hw[i] = packbf2(h0, h1);
            Lw[i] = packbf2(s0 - h0, s1 - h1);
            ls0 += s0;
            ls1 += s1;
        }
        int o = h * 56 + q * 4;
        *(uint4*)&oH[o] = make_uint4(Hw[0], Hw[1], Hw[2], Hw[3]);
        *(uint4*)&oL[o] = make_uint4(Lw[0], Lw[1], Lw[2], Lw[3]);
    }

    int wid = tid >> 5, lane = tid & 31;
    #pragma unroll
    for (int o = 16; o > 0; o >>= 1) {
        ls0 += __shfl_down_sync(0xffffffffu, ls0, o);
        ls1 += __shfl_down_sync(0xffffffffu, ls1, o);
    }
    if (lane == 0) { sred[wid] = ls0; sred[8 + wid] = ls1; }
    __syncthreads();
    if (tid < 16) {
        float v = sred[tid];
        #pragma unroll
        for (int o = 4; o > 0; o >>= 1) v += __shfl_down_sync(0xffffu, v, o);
        if (tid == 0) g_sums[b * 192 + 2 * k2] = v;
        if (tid == 8) g_sums[b * 192 + 2 * k2 + 1] = v;
    }
}

// ---------------------------------------------------------------------------
// SE gating + per-batch scaled/resplit proj weights. Block = (batch, chunk).
// ---------------------------------------------------------------------------
__global__ void __launch_bounds__(256) se_scale_kernel(const float* __restrict__ red_w,
                                                       const float* __restrict__ red_b,
                                                       const float* __restrict__ exp_w,
                                                       const float* __restrict__ exp_b) {
    __shared__ float smean[192];
    __shared__ float sredu[24];
    __shared__ float s_se[192];
    int b = blockIdx.x, cc = blockIdx.y;
    int tid = threadIdx.x;

    if (tid < 192) smean[tid] = g_sums[b * 192 + tid] * (1.f / 3136.f);
    __syncthreads();
    if (tid < 24) {
        int gq = tid >> 1;
        float a = red_b[tid];
        #pragma unroll
        for (int i = 0; i < 16; i++) a += red_w[tid * 16 + i] * smean[gq * 16 + i];
        sredu[tid] = fmaxf(a, 0.f);
    }
    __syncthreads();
    if (tid < 192) {
        int gq = tid >> 4;
        float v = exp_w[tid * 2] * sredu[gq * 2] + exp_w[tid * 2 + 1] * sredu[gq * 2 + 1]
                + exp_b[tid];
        s_se[tid] = 1.f / (1.f + __expf(-v));
    }
    __syncthreads();

    uint32_t* dstb = g_WprojSE + (size_t)b * 18432;
    const uint4* src = ((const uint4*)g_WprojF) + cc * (PROJ_A_U32 / 4);
    uint4* dst = ((uint4*)dstb) + cc * (PROJ_A_U32 / 4);
    for (int i = tid; i < 576; i += 256) {
        int grp = i >> 5, li = i & 31;
        int ki = (grp / 3) % 3;
        uint4 H = src[grp * 64 + li];
        uint4 L = src[grp * 64 + li + 32];
        int k2a = cc * 24 + ki * 8 + (li & 3);
        float se0 = s_se[2 * k2a], se1 = s_se[2 * k2a + 1];
        float se2 = s_se[2 * k2a + 8], se3 = s_se[2 * k2a + 9];
        uint32_t hu[4] = {H.x, H.y, H.z, H.w};
        uint32_t lu[4] = {L.x, L.y, L.z, L.w};
        uint32_t nh[4], nl[4];
        #pragma unroll
        for (int q = 0; q < 4; q++) {
            float sA = (q < 2) ? se0 : se2;
            float sB = (q < 2) ? se1 : se3;
            float2 hf = unpackbf2(hu[q]);
            float2 lf = unpackbf2(lu[q]);
            float v0 = (hf.x + lf.x) * sA;
            float v1 = (hf.y + lf.y) * sB;
            float h0 = bf16hi(v0), h1 = bf16hi(v1);
            nh[q] = packbf2(h0, h1);
            nl[q] = packbf2(v0 - h0, v1 - h1);
        }
        dst[grp * 64 + li]      = make_uint4(nh[0], nh[1], nh[2], nh[3]);
        dst[grp * 64 + li + 32] = make_uint4(nl[0], nl[1], nl[2], nl[3]);
    }
}

// ---------------------------------------------------------------------------
// Project 1x1 GEMM. M=96 x N=128; 4 k-chunks of 48; depth-2 cp.async
// pipeline (chunks 0+1 upfront, c+2 after compute c); residual x prefetched
// into freed smem during the last chunk's compute.
// ---------------------------------------------------------------------------
__global__ void __launch_bounds__(256, 2) proj_gemm(const float* __restrict__ x,
                                                    float* __restrict__ out) {
    extern __shared__ uint32_t smu[];
    uint32_t* As0 = smu;                        // PROJ_A_U32
    uint32_t* As1 = smu + PROJ_A_U32;
    uint32_t* Bst = smu + 2 * PROJ_A_U32;       // 2 stages x 2 planes x PROJ_B_U32

    int b = blockIdx.z;
    int p0 = blockIdx.x * 128;
    int tid = threadIdx.x;
    int lane = tid & 31, w = tid >> 5;
    int wr = w >> 2, wc = w & 3;
    int g = lane >> 2, tg = lane & 3;
    const uint32_t* mH = g_mergedH + (size_t)b * 96 * HWP;
    const uint32_t* mL = g_mergedL + (size_t)b * 96 * HWP;
    const uint4* Asrc = (const uint4*)(g_WprojSE + (size_t)b * 18432);
    const float* xb = x + (size_t)b * COUTC * HWP;

    auto cp_stage = [&](int c) {
        int stage = c & 1;
        uint32_t dstB = smaddr(Bst) + stage * 2 * PROJ_B_U32 * 4;
        const uint4* sH = (const uint4*)(mH + (size_t)(c * 24) * HWP);
        const uint4* sL = (const uint4*)(mL + (size_t)(c * 24) * HWP);
        #pragma unroll
        for (int j = 0; j < 3; j++) {
            int v = tid + j * 256;
            int r = v >> 5, c4 = (v & 31);
            int p = p0 + c4 * 4;
            bool ok = p < HWP;                  // zero-fill pad (intended)
            size_t so = (size_t)r * (HWP / 4) + (p0 >> 2) + c4;
            uint32_t d = dstB + (r * BSS + c4 * 4) * 4;
            cpa16(d, sH + (ok ? so : 0), ok);
            cpa16(d + PROJ_B_U32 * 4, sL + (ok ? so : 0), ok);
        }
        // A chunk: 1152 uint4 = 4*256 + 128 exact
        uint32_t dstA = smaddr(stage ? As1 : As0);
        const uint4* sA = Asrc + c * (PROJ_A_U32 / 4);
        #pragma unroll
        for (int j = 0; j < 4; j++) {
            int v = tid + j * 256;
            cpa16(dstA + v * 16, sA + v, true);
        }
        if (tid < 128) {
            int v = tid + 1024;
            cpa16(dstA + v * 16, sA + v, true);
        }
        cpa_commit();
    };
    cp_stage(0);
    cp_stage(1);

    float acc[3][4][4] = {};

    for (int c = 0; c < 4; c++) {
        uint32_t* Acur = (c & 1) ? As1 : As0;
        uint32_t* BhS = Bst + (c & 1) * 2 * PROJ_B_U32;
        uint32_t* BlS = BhS + PROJ_B_U32;
        cpa_wait<1>();        // chunk c complete (FIFO); c+1 may be in flight
        __syncthreads();

        #pragma unroll
        for (int ki = 0; ki < 3; ki++) {
            uint4 ah[3], al[3];
            #pragma unroll
            for (int mi = 0; mi < 3; mi++) {
                int off = ((wr * 3 + ki) * 3 + mi) * 256 + lane * 4;
                ah[mi] = *(const uint4*)&Acur[off];
                al[mi] = *(const uint4*)&Acur[off + 128];
            }
            uint32_t bh[4][2], bl[4][2];
            int kr2 = ki * 8;
            #pragma unroll
            for (int ni = 0; ni < 4; ni++) {
                int nb = wc * 32 + ni * 8 + g;
                bh[ni][0] = BhS[(kr2 + tg) * BSS + nb];
                bh[ni][1] = BhS[(kr2 + tg + 4) * BSS + nb];
                bl[ni][0] = BlS[(kr2 + tg) * BSS + nb];
                bl[ni][1] = BlS[(kr2 + tg + 4) * BSS + nb];
            }
            #pragma unroll
            for (int mi = 0; mi < 3; mi++)
                #pragma unroll
                for (int ni = 0; ni < 4; ni++) {
                    mma16(acc[mi][ni], (const uint32_t*)&ah[mi], bh[ni]);
                    mma16(acc[mi][ni], (const uint32_t*)&al[mi], bh[ni]);
                    mma16(acc[mi][ni], (const uint32_t*)&ah[mi], bl[ni]);
                }
        }
        __syncthreads();      // buffer (c&1) now free for refill

        if (c < 2) {
            cp_stage(c + 2);
        } else if (c == 2) {
            // Prefetch x rows 0..86 into As0 + Bst stage0 (44544 B = 2784 uint4)
            #pragma unroll
            for (int j = 0; j < 11; j++) {
                int t = tid + j * 256;
                if (t < 2784) {
                    int row = t >> 5, c4 = t & 31;
                    int p = p0 + c4 * 4;
                    int idx = row * 128 + c4 * 4;               // u32 index
                    uint32_t off = (idx < PROJ_A_U32) ? (uint32_t)idx
                                                      : (uint32_t)(idx + PROJ_A_U32);
                    cpa16(smaddr(smu) + off * 4,
                          xb + (size_t)row * HWP + p, p < HWP);
                }
            }
            cpa_commit();
        }
    }
    cpa_wait<0>();   // x prefetch complete
    __syncthreads();

    float* ob = out + (size_t)b * COUTC * HWP;
    #pragma unroll
    for (int mi = 0; mi < 3; mi++) {
        int o = wr * 48 + mi * 16 + g;
        float b0 = g_bproj[o], b1 = g_bproj[o + 8];
        #pragma unroll
        for (int ni = 0; ni < 4; ni++) {
            int pp = wc * 32 + ni * 8 + tg * 2;
            int p = p0 + pp;
            if (p < HWP) {
                float2 x0, x1;
                {
                    int idx = o * 128 + pp;
                    uint32_t off = (idx < PROJ_A_U32) ? (uint32_t)idx
                                                      : (uint32_t)(idx + PROJ_A_U32);
                    x0 = (o < 87) ? make_float2(__uint_as_float(smu[off]),
                                                __uint_as_float(smu[off + 1]))
                                  : *(const float2*)&xb[(size_t)o * HWP + p];
                }
                {
                    int o2 = o + 8;
                    int idx = o2 * 128 + pp;
                    uint32_t off = (idx < PROJ_A_U32) ? (uint32_t)idx
                                                      : (uint32_t)(idx + PROJ_A_U32);
                    x1 = (o2 < 87) ? make_float2(__uint_as_float(smu[off]),
                                                 __uint_as_float(smu[off + 1]))
                                   : *(const float2*)&xb[(size_t)(o + 8) * HWP + p];
                }
                float2 r0;
                r0.x = silu_f(acc[mi][ni][0] + b0 + x0.x);
                r0.y = silu_f(acc[mi][ni][1] + b0 + x0.y);
                *(float2*)&ob[(size_t)o * HWP + p] = r0;
                float2 r1;
                r1.x = silu_f(acc[mi][ni][2] + b1 + x1.x);
                r1.y = silu_f(acc[mi][ni][3] + b1 + x1.y);
                *(float2*)&ob[(size_t)(o + 8) * HWP + p] = r1;
            }
        }
    }
}

// ---------------------------------------------------------------------------
extern "C" void kernel_launch(void* const* d_in, const int* in_sizes, int n_in,
                              void* d_out, int out_size) {
    const float* x         = (const float*)d_in[0];
    const float* expand_w  = (const float*)d_in[1];
    const float* expand_bn = (const float*)d_in[2];
    const float* dw_w      = (const float*)d_in[3];
    const float* dw_bn     = (const float*)d_in[4];
    const float* id_w      = (const float*)d_in[5];
    const float* id_bn     = (const float*)d_in[6];
    const float* merge_bn  = (const float*)d_in[7];
    const float* se_red_w  = (const float*)d_in[8];
    const float* se_red_b  = (const float*)d_in[9];
    const float* se_exp_w  = (const float*)d_in[10];
    const float* se_exp_b  = (const float*)d_in[11];
    const float* proj_w    = (const float*)d_in[12];
    const float* proj_bn   = (const float*)d_in[13];
    float* out = (float*)d_out;

    cudaFuncSetAttribute(expand_gemm, cudaFuncAttributeMaxDynamicSharedMemorySize, EXP_SMEM);
    cudaFuncSetAttribute(proj_gemm,   cudaFuncAttributeMaxDynamicSharedMemorySize, PROJ_SMEM);

    prep_kernel<<<264, 256>>>(expand_w, expand_bn, dw_w, dw_bn, id_w, id_bn,
                              merge_bn, proj_w, proj_bn);
    expand_gemm<<<dim3(25, 1, BZ), 256, EXP_SMEM>>>(x);
    dwmerge_kernel<<<BZ * 96, 256>>>();
    se_scale_kernel<<<dim3(BZ, 4), 256>>>(se_red_w, se_red_b, se_exp_w, se_exp_b);
    proj_gemm<<<dim3(25, 1, BZ), 256, PROJ_SMEM>>>(x, out);
}

// round 12
// speedup vs baseline: 2.4013x; 1.0090x over previous
#include <cuda_runtime.h>
#include <cuda_bf16.h>
#include <cuda_fp16.h>
#include <math.h>
#include <stdint.h>

#define BZ    64
#define CINC  96
#define COUTC 96
#define MIDC  192
#define HWP   3136
#define EPSBN 1e-5f

#define BSS 136                    // pair-row stride (u32): bank = 8*tg+g, conflict-free
#define EXP_A_U32   6144           // per-mt A chunk  [wr2][ki6][mi2][hl2][lane32][q4]
#define PROJ_A_U32  4608           // per-kchunk A    [wr2][ki3][mi3][hl2][lane32][q4]
#define EXP_B_U32   (48 * BSS)     // one plane (hi or lo), 48 pair-rows
#define PROJ_B_U32  (24 * BSS)     // one plane per chunk, 24 pair-rows
#define EXP_SMEM  ((2 * EXP_A_U32 + 2 * EXP_B_U32) * 4)      // 101376 B
#define PROJ_SMEM ((2 * PROJ_A_U32 + 4 * PROJ_B_U32) * 4)    // 89088 B

// Scratch (device globals: allowed; no cudaMalloc anywhere)
__device__ __align__(16) __half   g_mid[(size_t)BZ * MIDC * HWP];    // fp16 mid
__device__ __align__(16) uint32_t g_mergedH[(size_t)BZ * 96 * HWP];  // packed bf16 (c,c+1) hi
__device__ __align__(16) uint32_t g_mergedL[(size_t)BZ * 96 * HWP];  // packed bf16 lo residual
__device__ float    g_sums[BZ * MIDC];
__device__ __align__(16) uint32_t g_WexpF[18432];   // [mt3][wr2][ki6][mi2][hl2][lane32][q4]
__device__ __align__(16) uint32_t g_WprojF[18432];  // [chunk4][wr2][ki3][mi3][hl2][lane32][q4]
__device__ __align__(16) uint32_t g_WprojSE[(size_t)BZ * 18432];  // per-batch SE-scaled resplit
__device__ float    g_bexp[MIDC];
__device__ float    g_W9[MIDC * 9];
__device__ float    g_T[MIDC];
__device__ float    g_bproj[COUTC];

__device__ __forceinline__ float silu_f(float v) { return v / (1.f + __expf(-v)); }

__device__ __forceinline__ uint32_t packbf2(float lo_elem, float hi_elem) {
    __nv_bfloat162 t = __floats2bfloat162_rn(lo_elem, hi_elem);  // .x = low 16 bits
    return *(uint32_t*)&t;
}
__device__ __forceinline__ float2 unpackbf2(uint32_t u) {
    __nv_bfloat162 t = *(__nv_bfloat162*)&u;
    return __bfloat1622float2(t);
}
__device__ __forceinline__ float bf16hi(float v) {
    return __bfloat162float(__float2bfloat16_rn(v));
}

__device__ __forceinline__ void mma16(float* c, const uint32_t* a, const uint32_t* b) {
    asm volatile(
        "mma.sync.aligned.m16n8k16.row.col.f32.bf16.bf16.f32 "
        "{%0,%1,%2,%3},{%4,%5,%6,%7},{%8,%9},{%0,%1,%2,%3};"
        : "+f"(c[0]), "+f"(c[1]), "+f"(c[2]), "+f"(c[3])
        : "r"(a[0]), "r"(a[1]), "r"(a[2]), "r"(a[3]), "r"(b[0]), "r"(b[1]));
}

__device__ __forceinline__ uint32_t smaddr(const void* p) {
    return (uint32_t)__cvta_generic_to_shared(p);
}
__device__ __forceinline__ void cpa16(uint32_t dst_s, const void* src, bool valid) {
    // NOTE: valid=false still WRITES 16 zero bytes to dst (zero-fill), use only
    // where zero-padding the destination is intended.
    int sz = valid ? 16 : 0;
    asm volatile("cp.async.cg.shared.global [%0], [%1], 16, %2;\n"
                 :: "r"(dst_s), "l"(src), "r"(sz));
}
__device__ __forceinline__ void cpa_commit() {
    asm volatile("cp.async.commit_group;\n");
}
template <int N>
__device__ __forceinline__ void cpa_wait() {
    asm volatile("cp.async.wait_group %0;\n" :: "n"(N));
}

// ---------------------------------------------------------------------------
// prep: fold BN; emit fragment-ordered packed-bf16 hi/lo weights.
// ---------------------------------------------------------------------------
__global__ void prep_kernel(const float* __restrict__ expand_w,
                            const float* __restrict__ expand_bn,
                            const float* __restrict__ dw_w,
                            const float* __restrict__ dw_bn,
                            const float* __restrict__ id_w,
                            const float* __restrict__ id_bn,
                            const float* __restrict__ merge_bn,
                            const float* __restrict__ proj_w,
                            const float* __restrict__ proj_bn) {
    int tid = blockIdx.x * blockDim.x + threadIdx.x;
    int nth = gridDim.x * blockDim.x;

    for (int idx = tid; idx < 18432; idx += nth) {
        int q = idx & 3, lane = (idx >> 2) & 31, hl = (idx >> 7) & 1;
        int t = idx >> 8;
        int mi = t & 1; t >>= 1;
        int ki = t % 6; t /= 6;
        int wr = t & 1; t >>= 1;
        int mt = t;
        int m = mt * 64 + wr * 32 + mi * 16 + (lane >> 2) + 8 * (q & 1);
        int k = ki * 16 + (lane & 3) * 2 + 8 * (q >> 1);
        float sc = expand_bn[m] * rsqrtf(expand_bn[3 * MIDC + m] + EPSBN);
        float w0 = expand_w[m * CINC + k] * sc;
        float w1 = expand_w[m * CINC + k + 1] * sc;
        float h0 = bf16hi(w0), h1 = bf16hi(w1);
        g_WexpF[idx] = hl ? packbf2(w0 - h0, w1 - h1) : packbf2(h0, h1);
    }
    for (int idx = tid; idx < 18432; idx += nth) {
        int q = idx & 3, lane = (idx >> 2) & 31, hl = (idx >> 7) & 1;
        int t = idx >> 8;
        int mi = t % 3; t /= 3;
        int ki = t % 3; t /= 3;
        int wr = t & 1; int chunk = t >> 1;
        int m = wr * 48 + mi * 16 + (lane >> 2) + 8 * (q & 1);
        int k = chunk * 48 + ki * 16 + (lane & 3) * 2 + 8 * (q >> 1);
        float sc = proj_bn[m] * rsqrtf(proj_bn[3 * COUTC + m] + EPSBN);
        float w0 = proj_w[m * MIDC + k] * sc;
        float w1 = proj_w[m * MIDC + k + 1] * sc;
        float h0 = bf16hi(w0), h1 = bf16hi(w1);
        g_WprojF[idx] = hl ? packbf2(w0 - h0, w1 - h1) : packbf2(h0, h1);
    }
    for (int o = tid; o < MIDC; o += nth) {
        float sc = expand_bn[o] * rsqrtf(expand_bn[3 * MIDC + o] + EPSBN);
        g_bexp[o] = expand_bn[MIDC + o] - expand_bn[2 * MIDC + o] * sc;
    }
    for (int c = tid; c < MIDC; c += nth) {
        float dsc = dw_bn[c] * rsqrtf(dw_bn[3 * MIDC + c] + EPSBN);
        float dsh = dw_bn[MIDC + c] - dw_bn[2 * MIDC + c] * dsc;
        float isc = id_bn[c] * rsqrtf(id_bn[3 * MIDC + c] + EPSBN);
        float ish = id_bn[MIDC + c] - id_bn[2 * MIDC + c] * isc;
        float msc = merge_bn[c] * rsqrtf(merge_bn[3 * MIDC + c] + EPSBN);
        float msh = merge_bn[MIDC + c] - merge_bn[2 * MIDC + c] * msc;
        #pragma unroll
        for (int k = 0; k < 9; k++) g_W9[c * 9 + k] = msc * dsc * dw_w[c * 9 + k];
        g_W9[c * 9 + 4] += msc * isc * id_w[c];
        g_T[c] = msc * (dsh + ish) + msh;
    }
    for (int o = tid; o < COUTC; o += nth) {
        float sc = proj_bn[o] * rsqrtf(proj_bn[3 * COUTC + o] + EPSBN);
        g_bproj[o] = proj_bn[COUTC + o] - proj_bn[2 * COUTC + o] * sc;
    }
}

// ---------------------------------------------------------------------------
// Expand 1x1 GEMM. 192(Mx3 passes) x 128(N); warp tile 32x32; bf16 k16.
// A depth-2 cp.async pipeline; B converted once at start. fp16 output.
// ---------------------------------------------------------------------------
__global__ void __launch_bounds__(256, 2) expand_gemm(const float* __restrict__ x) {
    extern __shared__ uint32_t smu[];
    uint32_t* As0 = smu;                    // EXP_A_U32
    uint32_t* As1 = smu + EXP_A_U32;
    uint32_t* Bh  = smu + 2 * EXP_A_U32;    // EXP_B_U32
    uint32_t* Bl  = Bh + EXP_B_U32;
    int b = blockIdx.z;
    int p0 = blockIdx.x * 128;
    int tid = threadIdx.x;
    int lane = tid & 31, w = tid >> 5;
    int wr = w >> 2, wc = w & 3;
    int g = lane >> 2, tg = lane & 3;
    const float* xb = x + (size_t)b * CINC * HWP;
    __half* ob = g_mid + (size_t)b * MIDC * HWP;

    // Prefetch A(0) and A(1) upfront (two commit groups)
    {
        const uint4* src = (const uint4*)g_WexpF;
        #pragma unroll
        for (int j = 0; j < 6; j++)
            cpa16(smaddr(As0) + (tid + j * 256) * 16, src + tid + j * 256, true);
        cpa_commit();
        src += EXP_A_U32 / 4;
        #pragma unroll
        for (int j = 0; j < 6; j++)
            cpa16(smaddr(As1) + (tid + j * 256) * 16, src + tid + j * 256, true);
        cpa_commit();
    }
    // Convert B (overlaps both A fetches)
    #pragma unroll
    for (int j = 0; j < 6; j++) {
        int v = tid + j * 256;
        int k2 = v >> 5, c4 = (v & 31) << 2;
        int p = p0 + c4;
        float4 r0 = make_float4(0.f, 0.f, 0.f, 0.f), r1 = r0;
        if (p < HWP) {
            r0 = *(const float4*)&xb[(size_t)(2 * k2) * HWP + p];
            r1 = *(const float4*)&xb[(size_t)(2 * k2 + 1) * HWP + p];
        }
        float e0[4] = {r0.x, r0.y, r0.z, r0.w};
        float e1[4] = {r1.x, r1.y, r1.z, r1.w};
        uint32_t hh[4], ll[4];
        #pragma unroll
        for (int i = 0; i < 4; i++) {
            float h0 = bf16hi(e0[i]), h1 = bf16hi(e1[i]);
            hh[i] = packbf2(h0, h1);
            ll[i] = packbf2(e0[i] - h0, e1[i] - h1);
        }
        *(uint4*)&Bh[k2 * BSS + c4] = make_uint4(hh[0], hh[1], hh[2], hh[3]);
        *(uint4*)&Bl[k2 * BSS + c4] = make_uint4(ll[0], ll[1], ll[2], ll[3]);
    }

    for (int mt = 0; mt < 3; mt++) {
        uint32_t* Acur = (mt & 1) ? As1 : As0;
        if (mt == 2) { cpa_wait<0>(); } else { cpa_wait<1>(); }
        __syncthreads();   // A(mt) visible; B visible (mt=0); prev buffer free

        float acc[2][4][4] = {};
        #pragma unroll
        for (int ki = 0; ki < 6; ki++) {
            uint4 ah[2], al[2];
            #pragma unroll
            for (int mi = 0; mi < 2; mi++) {
                int off = (((wr * 6 + ki) * 2 + mi) * 2) * 128 + lane * 4;
                ah[mi] = *(const uint4*)&Acur[off];
                al[mi] = *(const uint4*)&Acur[off + 128];
            }
            uint32_t bh[4][2], bl[4][2];
            int kr2 = ki * 8;
            #pragma unroll
            for (int ni = 0; ni < 4; ni++) {
                int nb = wc * 32 + ni * 8 + g;
                bh[ni][0] = Bh[(kr2 + tg) * BSS + nb];
                bh[ni][1] = Bh[(kr2 + tg + 4) * BSS + nb];
                bl[ni][0] = Bl[(kr2 + tg) * BSS + nb];
                bl[ni][1] = Bl[(kr2 + tg + 4) * BSS + nb];
            }
            #pragma unroll
            for (int mi = 0; mi < 2; mi++)
                #pragma unroll
                for (int ni = 0; ni < 4; ni++) {
                    mma16(acc[mi][ni], (const uint32_t*)&ah[mi], bh[ni]);
                    mma16(acc[mi][ni], (const uint32_t*)&al[mi], bh[ni]);
                    mma16(acc[mi][ni], (const uint32_t*)&ah[mi], bl[ni]);
                }
        }

        int m0 = mt * 64;
        #pragma unroll
        for (int mi = 0; mi < 2; mi++) {
            int o = m0 + wr * 32 + mi * 16 + g;
            float b0f = g_bexp[o], b1f = g_bexp[o + 8];
            #pragma unroll
            for (int ni = 0; ni < 4; ni++) {
                int p = p0 + wc * 32 + ni * 8 + tg * 2;
                if (p < HWP) {
                    *(__half2*)&ob[(size_t)o * HWP + p] =
                        __floats2half2_rn(silu_f(acc[mi][ni][0] + b0f),
                                          silu_f(acc[mi][ni][1] + b0f));
                    *(__half2*)&ob[(size_t)(o + 8) * HWP + p] =
                        __floats2half2_rn(silu_f(acc[mi][ni][2] + b1f),
                                          silu_f(acc[mi][ni][3] + b1f));
                }
            }
        }
        __syncthreads();   // all reads of Acur done before refill
        if (mt == 0) {
            const uint4* src = ((const uint4*)g_WexpF) + 2 * (EXP_A_U32 / 4);
            #pragma unroll
            for (int j = 0; j < 6; j++)
                cpa16(smaddr(As0) + (tid + j * 256) * 16, src + tid + j * 256, true);
            cpa_commit();
        }
    }
}

// ---------------------------------------------------------------------------
// dwmerge v2: vectorized; shifted planes at col offset OFF=5-ox. fp16 input.
// ---------------------------------------------------------------------------
#define SROW 64
__global__ void __launch_bounds__(256) dwmerge_kernel() {
    __shared__ float sps[2][58 * SROW];
    __shared__ float sred[16];
    int bc = blockIdx.x;
    int b = bc / 96, k2 = bc - b * 96;
    int tid = threadIdx.x;

    int oyA[2], oxA[2];
    const __half* planes[2];
    float w9[2][9], T[2];
    #pragma unroll
    for (int ch = 0; ch < 2; ch++) {
        int c = 2 * k2 + ch;
        int cpre = (c & 3) * 48 + (c >> 2);
        int gg = c & 3;
        oyA[ch] = (gg == 0) ? -1 : (gg == 2) ? 1 : 0;
        oxA[ch] = (gg == 1) ? -1 : (gg == 3) ? 1 : 0;
        planes[ch] = g_mid + ((size_t)b * MIDC + cpre) * HWP;
        #pragma unroll
        for (int k = 0; k < 9; k++) w9[ch][k] = g_W9[c * 9 + k];
        T[ch] = g_T[c];
    }

    // Pass 1: zero both planes (float4)
    {
        float4* z = (float4*)&sps[0][0];
        for (int i = tid; i < 2 * 58 * SROW / 4; i += 256)
            z[i] = make_float4(0.f, 0.f, 0.f, 0.f);
    }
    __syncthreads();

    // Pass 2: fill valid rows; fp16 loads (8B-aligned: row stride 112B, qq*8B)
    for (int t = tid; t < 1624; t += 256) {
        int ch = t >= 812;
        int u = t - ch * 812;
        int r = u / 14, qq = u - r * 14;
        int hp = r - 1, hs = hp + oyA[ch];
        if ((unsigned)hp < 56u && (unsigned)hs < 56u) {
            uint2 v = *(const uint2*)&planes[ch][hs * 56 + qq * 4];
            float2 f01 = __half22float2(*(__half2*)&v.x);
            float2 f23 = __half22float2(*(__half2*)&v.y);
            float* d = &sps[ch][r * SROW + qq * 4 + (5 - oxA[ch])];
            d[0] = f01.x; d[1] = f01.y; d[2] = f23.x; d[3] = f23.y;
        }
    }
    __syncthreads();

    // Pass 3: zero the conv-pad cell that the shifted copy filled
    if (tid < 116) {
        int ch = tid >= 58;
        int r = tid - ch * 58;
        int ox = oxA[ch];
        if (ox == 1)  sps[ch][r * SROW + 4] = 0.f;   // wp=-1 cell
        if (ox == -1) sps[ch][r * SROW + 61] = 0.f;  // wp=56 cell
    }
    __syncthreads();

    uint32_t* oH = g_mergedH + ((size_t)b * 96 + k2) * HWP;
    uint32_t* oL = g_mergedL + ((size_t)b * 96 + k2) * HWP;
    float ls0 = 0.f, ls1 = 0.f;

    for (int t = tid; t < 784; t += 256) {
        int h = t / 14, q = t - h * 14;
        float a0[4] = {T[0], T[0], T[0], T[0]};
        float a1[4] = {T[1], T[1], T[1], T[1]};
        #pragma unroll
        for (int ch = 0; ch < 2; ch++) {
            float* accp = ch ? a1 : a0;
            #pragma unroll
            for (int dy = 0; dy < 3; dy++) {
                const float* row = &sps[ch][(h + dy) * SROW + q * 4 + 4];
                float4 A = *(const float4*)row;
                float2 Bv = *(const float2*)(row + 4);
                float wA = w9[ch][dy * 3], wB = w9[ch][dy * 3 + 1], wC = w9[ch][dy * 3 + 2];
                accp[0] += wA * A.x + wB * A.y + wC * A.z;
                accp[1] += wA * A.y + wB * A.z + wC * A.w;
                accp[2] += wA * A.z + wB * A.w + wC * Bv.x;
                accp[3] += wA * A.w + wB * Bv.x + wC * Bv.y;
            }
        }
        uint32_t Hw[4], Lw[4];
        #pragma unroll
        for (int i = 0; i < 4; i++) {
            float s0 = silu_f(a0[i]);
            float s1 = silu_f(a1[i]);
            float h0 = bf16hi(s0), h1 = bf16hi(s1);
            Hw[i] = packbf2(h0, h1);
            Lw[i] = packbf2(s0 - h0, s1 - h1);
            ls0 += s0;
            ls1 += s1;
        }
        int o = h * 56 + q * 4;
        *(uint4*)&oH[o] = make_uint4(Hw[0], Hw[1], Hw[2], Hw[3]);
        *(uint4*)&oL[o] = make_uint4(Lw[0], Lw[1], Lw[2], Lw[3]);
    }

    int wid = tid >> 5, lane = tid & 31;
    #pragma unroll
    for (int o = 16; o > 0; o >>= 1) {
        ls0 += __shfl_down_sync(0xffffffffu, ls0, o);
        ls1 += __shfl_down_sync(0xffffffffu, ls1, o);
    }
    if (lane == 0) { sred[wid] = ls0; sred[8 + wid] = ls1; }
    __syncthreads();
    if (tid < 16) {
        float v = sred[tid];
        #pragma unroll
        for (int o = 4; o > 0; o >>= 1) v += __shfl_down_sync(0xffffu, v, o);
        if (tid == 0) g_sums[b * 192 + 2 * k2] = v;
        if (tid == 8) g_sums[b * 192 + 2 * k2 + 1] = v;
    }
}

// ---------------------------------------------------------------------------
// SE gating + per-batch scaled/resplit proj weights. Block = (batch, chunk).
// ---------------------------------------------------------------------------
__global__ void __launch_bounds__(256) se_scale_kernel(const float* __restrict__ red_w,
                                                       const float* __restrict__ red_b,
                                                       const float* __restrict__ exp_w,
                                                       const float* __restrict__ exp_b) {
    __shared__ float smean[192];
    __shared__ float sredu[24];
    __shared__ float s_se[192];
    int b = blockIdx.x, cc = blockIdx.y;
    int tid = threadIdx.x;

    if (tid < 192) smean[tid] = g_sums[b * 192 + tid] * (1.f / 3136.f);
    __syncthreads();
    if (tid < 24) {
        int gq = tid >> 1;
        float a = red_b[tid];
        #pragma unroll
        for (int i = 0; i < 16; i++) a += red_w[tid * 16 + i] * smean[gq * 16 + i];
        sredu[tid] = fmaxf(a, 0.f);
    }
    __syncthreads();
    if (tid < 192) {
        int gq = tid >> 4;
        float v = exp_w[tid * 2] * sredu[gq * 2] + exp_w[tid * 2 + 1] * sredu[gq * 2 + 1]
                + exp_b[tid];
        s_se[tid] = 1.f / (1.f + __expf(-v));
    }
    __syncthreads();

    uint32_t* dstb = g_WprojSE + (size_t)b * 18432;
    const uint4* src = ((const uint4*)g_WprojF) + cc * (PROJ_A_U32 / 4);
    uint4* dst = ((uint4*)dstb) + cc * (PROJ_A_U32 / 4);
    for (int i = tid; i < 576; i += 256) {
        int grp = i >> 5, li = i & 31;
        int ki = (grp / 3) % 3;
        uint4 H = src[grp * 64 + li];
        uint4 L = src[grp * 64 + li + 32];
        int k2a = cc * 24 + ki * 8 + (li & 3);
        float se0 = s_se[2 * k2a], se1 = s_se[2 * k2a + 1];
        float se2 = s_se[2 * k2a + 8], se3 = s_se[2 * k2a + 9];
        uint32_t hu[4] = {H.x, H.y, H.z, H.w};
        uint32_t lu[4] = {L.x, L.y, L.z, L.w};
        uint32_t nh[4], nl[4];
        #pragma unroll
        for (int q = 0; q < 4; q++) {
            float sA = (q < 2) ? se0 : se2;
            float sB = (q < 2) ? se1 : se3;
            float2 hf = unpackbf2(hu[q]);
            float2 lf = unpackbf2(lu[q]);
            float v0 = (hf.x + lf.x) * sA;
            float v1 = (hf.y + lf.y) * sB;
            float h0 = bf16hi(v0), h1 = bf16hi(v1);
            nh[q] = packbf2(h0, h1);
            nl[q] = packbf2(v0 - h0, v1 - h1);
        }
        dst[grp * 64 + li]      = make_uint4(nh[0], nh[1], nh[2], nh[3]);
        dst[grp * 64 + li + 32] = make_uint4(nl[0], nl[1], nl[2], nl[3]);
    }
}

// ---------------------------------------------------------------------------
// Project 1x1 GEMM. M=96 x N=128; 4 k-chunks of 48; depth-2 cp.async
// pipeline; residual x prefetched into freed smem during last chunk.
// ---------------------------------------------------------------------------
__global__ void __launch_bounds__(256, 2) proj_gemm(const float* __restrict__ x,
                                                    float* __restrict__ out) {
    extern __shared__ uint32_t smu[];
    uint32_t* As0 = smu;                        // PROJ_A_U32
    uint32_t* As1 = smu + PROJ_A_U32;
    uint32_t* Bst = smu + 2 * PROJ_A_U32;       // 2 stages x 2 planes x PROJ_B_U32

    int b = blockIdx.z;
    int p0 = blockIdx.x * 128;
    int tid = threadIdx.x;
    int lane = tid & 31, w = tid >> 5;
    int wr = w >> 2, wc = w & 3;
    int g = lane >> 2, tg = lane & 3;
    const uint32_t* mH = g_mergedH + (size_t)b * 96 * HWP;
    const uint32_t* mL = g_mergedL + (size_t)b * 96 * HWP;
    const uint4* Asrc = (const uint4*)(g_WprojSE + (size_t)b * 18432);
    const float* xb = x + (size_t)b * COUTC * HWP;

    auto cp_stage = [&](int c) {
        int stage = c & 1;
        uint32_t dstB = smaddr(Bst) + stage * 2 * PROJ_B_U32 * 4;
        const uint4* sH = (const uint4*)(mH + (size_t)(c * 24) * HWP);
        const uint4* sL = (const uint4*)(mL + (size_t)(c * 24) * HWP);
        #pragma unroll
        for (int j = 0; j < 3; j++) {
            int v = tid + j * 256;
            int r = v >> 5, c4 = (v & 31);
            int p = p0 + c4 * 4;
            bool ok = p < HWP;                  // zero-fill pad (intended)
            size_t so = (size_t)r * (HWP / 4) + (p0 >> 2) + c4;
            uint32_t d = dstB + (r * BSS + c4 * 4) * 4;
            cpa16(d, sH + (ok ? so : 0), ok);
            cpa16(d + PROJ_B_U32 * 4, sL + (ok ? so : 0), ok);
        }
        // A chunk: 1152 uint4 = 4*256 + 128 exact
        uint32_t dstA = smaddr(stage ? As1 : As0);
        const uint4* sA = Asrc + c * (PROJ_A_U32 / 4);
        #pragma unroll
        for (int j = 0; j < 4; j++) {
            int v = tid + j * 256;
            cpa16(dstA + v * 16, sA + v, true);
        }
        if (tid < 128) {
            int v = tid + 1024;
            cpa16(dstA + v * 16, sA + v, true);
        }
        cpa_commit();
    };
    cp_stage(0);
    cp_stage(1);

    float acc[3][4][4] = {};

    for (int c = 0; c < 4; c++) {
        uint32_t* Acur = (c & 1) ? As1 : As0;
        uint32_t* BhS = Bst + (c & 1) * 2 * PROJ_B_U32;
        uint32_t* BlS = BhS + PROJ_B_U32;
        cpa_wait<1>();        // chunk c complete (FIFO); c+1 may be in flight
        __syncthreads();

        #pragma unroll
        for (int ki = 0; ki < 3; ki++) {
            uint4 ah[3], al[3];
            #pragma unroll
            for (int mi = 0; mi < 3; mi++) {
                int off = ((wr * 3 + ki) * 3 + mi) * 256 + lane * 4;
                ah[mi] = *(const uint4*)&Acur[off];
                al[mi] = *(const uint4*)&Acur[off + 128];
            }
            uint32_t bh[4][2], bl[4][2];
            int kr2 = ki * 8;
            #pragma unroll
            for (int ni = 0; ni < 4; ni++) {
                int nb = wc * 32 + ni * 8 + g;
                bh[ni][0] = BhS[(kr2 + tg) * BSS + nb];
                bh[ni][1] = BhS[(kr2 + tg + 4) * BSS + nb];
                bl[ni][0] = BlS[(kr2 + tg) * BSS + nb];
                bl[ni][1] = BlS[(kr2 + tg + 4) * BSS + nb];
            }
            #pragma unroll
            for (int mi = 0; mi < 3; mi++)
                #pragma unroll
                for (int ni = 0; ni < 4; ni++) {
                    mma16(acc[mi][ni], (const uint32_t*)&ah[mi], bh[ni]);
                    mma16(acc[mi][ni], (const uint32_t*)&al[mi], bh[ni]);
                    mma16(acc[mi][ni], (const uint32_t*)&ah[mi], bl[ni]);
                }
        }
        __syncthreads();      // buffer (c&1) now free for refill

        if (c < 2) {
            cp_stage(c + 2);
        } else if (c == 2) {
            // Prefetch x rows 0..86 into As0 + Bst stage0 (44544 B = 2784 uint4)
            #pragma unroll
            for (int j = 0; j < 11; j++) {
                int t = tid + j * 256;
                if (t < 2784) {
                    int row = t >> 5, c4 = t & 31;
                    int p = p0 + c4 * 4;
                    int idx = row * 128 + c4 * 4;               // u32 index
                    uint32_t off = (idx < PROJ_A_U32) ? (uint32_t)idx
                                                      : (uint32_t)(idx + PROJ_A_U32);
                    cpa16(smaddr(smu) + off * 4,
                          xb + (size_t)row * HWP + p, p < HWP);
                }
            }
            cpa_commit();
        }
    }
    cpa_wait<0>();   // x prefetch complete
    __syncthreads();

    float* ob = out + (size_t)b * COUTC * HWP;
    #pragma unroll
    for (int mi = 0; mi < 3; mi++) {
        int o = wr * 48 + mi * 16 + g;
        float b0f = g_bproj[o], b1f = g_bproj[o + 8];
        #pragma unroll
        for (int ni = 0; ni < 4; ni++) {
            int pp = wc * 32 + ni * 8 + tg * 2;
            int p = p0 + pp;
            if (p < HWP) {
                float2 x0, x1;
                {
                    int idx = o * 128 + pp;
                    uint32_t off = (idx < PROJ_A_U32) ? (uint32_t)idx
                                                      : (uint32_t)(idx + PROJ_A_U32);
                    x0 = (o < 87) ? make_float2(__uint_as_float(smu[off]),
                                                __uint_as_float(smu[off + 1]))
                                  : *(const float2*)&xb[(size_t)o * HWP + p];
                }
                {
                    int o2 = o + 8;
                    int idx = o2 * 128 + pp;
                    uint32_t off = (idx < PROJ_A_U32) ? (uint32_t)idx
                                                      : (uint32_t)(idx + PROJ_A_U32);
                    x1 = (o2 < 87) ? make_float2(__uint_as_float(smu[off]),
                                                 __uint_as_float(smu[off + 1]))
                                   : *(const float2*)&xb[(size_t)(o + 8) * HWP + p];
                }
                float2 r0;
                r0.x = silu_f(acc[mi][ni][0] + b0f + x0.x);
                r0.y = silu_f(acc[mi][ni][1] + b0f + x0.y);
                *(float2*)&ob[(size_t)o * HWP + p] = r0;
                float2 r1;
                r1.x = silu_f(acc[mi][ni][2] + b1f + x1.x);
                r1.y = silu_f(acc[mi][ni][3] + b1f + x1.y);
                *(float2*)&ob[(size_t)(o + 8) * HWP + p] = r1;
            }
        }
    }
}

// ---------------------------------------------------------------------------
extern "C" void kernel_launch(void* const* d_in, const int* in_sizes, int n_in,
                              void* d_out, int out_size) {
    const float* x         = (const float*)d_in[0];
    const float* expand_w  = (const float*)d_in[1];
    const float* expand_bn = (const float*)d_in[2];
    const float* dw_w      = (const float*)d_in[3];
    const float* dw_bn     = (const float*)d_in[4];
    const float* id_w      = (const float*)d_in[5];
    const float* id_bn     = (const float*)d_in[6];
    const float* merge_bn  = (const float*)d_in[7];
    const float* se_red_w  = (const float*)d_in[8];
    const float* se_red_b  = (const float*)d_in[9];
    const float* se_exp_w  = (const float*)d_in[10];
    const float* se_exp_b  = (const float*)d_in[11];
    const float* proj_w    = (const float*)d_in[12];
    const float* proj_bn   = (const float*)d_in[13];
    float* out = (float*)d_out;

    cudaFuncSetAttribute(expand_gemm, cudaFuncAttributeMaxDynamicSharedMemorySize, EXP_SMEM);
    cudaFuncSetAttribute(proj_gemm,   cudaFuncAttributeMaxDynamicSharedMemorySize, PROJ_SMEM);

    prep_kernel<<<264, 256>>>(expand_w, expand_bn, dw_w, dw_bn, id_w, id_bn,
                              merge_bn, proj_w, proj_bn);
    expand_gemm<<<dim3(25, 1, BZ), 256, EXP_SMEM>>>(x);
    dwmerge_kernel<<<BZ * 96, 256>>>();
    se_scale_kernel<<<dim3(BZ, 4), 256>>>(se_red_w, se_red_b, se_exp_w, se_exp_b);
    proj_gemm<<<dim3(25, 1, BZ), 256, PROJ_SMEM>>>(x, out);
}